// round 11
// baseline (speedup 1.0000x reference)
#include <cuda_runtime.h>
#include <cuda_fp16.h>
#include <cuda_bf16.h>
#include <cstdint>

#define NN 100000
#define NE 1600000
#define NTOT (NE + NN)

// ---------------- scratch (device globals: allocation-free) ----------------
__device__ float  g_bufA[NN * 160];
__device__ float  g_bufB[NN * 160];
__device__ __align__(16) __half g_bufH[NN * 80];
__device__ __align__(16) __half g_ah[NN * 160];    // GEMM A operand (fp16)
__device__ __align__(16) __half g_ah2[NN * 160];   // dg3 fp16 output
__device__ __align__(16) __half g_wth[32000];      // transposed weights [n*K+k] fp16
__device__ int    g_cnt[NN];
__device__ float  g_dis[NN];
__device__ int    g_rowptr[NN + 1];
__device__ int    g_fill[NN];
__device__ int2   g_entries[NTOT];
__device__ int    g_bsums[128];

static inline int cdiv(int a, int b) { return (a + b - 1) / b; }

#define WOFF_EG2 0
#define WOFF_EG3 12800
#define WOFF_DG2 16000
#define WOFF_DG3 19200

// ---------------- CSR build ----------------
__global__ void k_init_cnt() {
    int i = blockIdx.x * blockDim.x + threadIdx.x;
    if (i < NN) g_cnt[i] = 1;
}
__global__ void k_count(const int* __restrict__ dst) {
    int e = blockIdx.x * blockDim.x + threadIdx.x;
    if (e < NE) atomicAdd(&g_cnt[dst[e]], 1);
}
__global__ void k_scan1() {
    __shared__ int s[1024];
    int i = blockIdx.x * 1024 + threadIdx.x;
    int v = (i < NN) ? g_cnt[i] : 0;
    if (i < NN) g_dis[i] = rsqrtf((float)v);
    s[threadIdx.x] = v;
    __syncthreads();
    for (int d = 1; d < 1024; d <<= 1) {
        int t = (threadIdx.x >= d) ? s[threadIdx.x - d] : 0;
        __syncthreads();
        s[threadIdx.x] += t;
        __syncthreads();
    }
    if (i < NN) g_rowptr[i + 1] = s[threadIdx.x];
    if (threadIdx.x == 1023) g_bsums[blockIdx.x] = s[1023];
}
__global__ void k_scan2(int nb) {
    __shared__ int s[128];
    int v = (threadIdx.x < nb) ? g_bsums[threadIdx.x] : 0;
    s[threadIdx.x] = v;
    __syncthreads();
    for (int d = 1; d < 128; d <<= 1) {
        int t = (threadIdx.x >= d) ? s[threadIdx.x - d] : 0;
        __syncthreads();
        s[threadIdx.x] += t;
        __syncthreads();
    }
    if (threadIdx.x < nb) g_bsums[threadIdx.x] = s[threadIdx.x] - v;
}
__global__ void k_scan3() {
    int i = blockIdx.x * 1024 + threadIdx.x;
    if (i < NN) g_rowptr[i + 1] += g_bsums[blockIdx.x];
    if (i == 0) g_rowptr[0] = 0;
}
__global__ void k_self() {
    int i = blockIdx.x * blockDim.x + threadIdx.x;
    if (i < NN) {
        int p = g_rowptr[i];
        float d = g_dis[i];
        g_entries[p] = make_int2(i, __float_as_int(d * d));
        g_fill[i] = p + 1;
    }
}
__global__ void k_edges(const int* __restrict__ src, const int* __restrict__ dst) {
    int e = blockIdx.x * blockDim.x + threadIdx.x;
    if (e < NE) {
        int s = src[e], d = dst[e];
        int p = atomicAdd(&g_fill[d], 1);
        g_entries[p] = make_int2(s, __float_as_int(g_dis[s] * g_dis[d]));
    }
}

// ---------------- all-weights convert+transpose (single launch) ----------------
__global__ void k_wconv_all(const float* __restrict__ W1, const float* __restrict__ W2,
                            const float* __restrict__ W9, const float* __restrict__ W10) {
    int idx = blockIdx.x * blockDim.x + threadIdx.x;
    if (idx >= 32000) return;
    const float* W; int K, Nc, off, li;
    if (idx < 12800)      { W = W1;  K = 160; Nc = 80;  off = WOFF_EG2; li = idx; }
    else if (idx < 16000) { W = W2;  K = 80;  Nc = 40;  off = WOFF_EG3; li = idx - 12800; }
    else if (idx < 19200) { W = W9;  K = 40;  Nc = 80;  off = WOFF_DG2; li = idx - 16000; }
    else                  { W = W10; K = 80;  Nc = 160; off = WOFF_DG3; li = idx - 19200; }
    int k = li / Nc, n = li - k * Nc;
    g_wth[off + n * K + k] = __float2half_rn(W[li]);
}

// ---------------- scalar aggregation (C=3) ----------------
template <int ACT, bool BIAS, typename TIN>
__global__ void k_agg3(const TIN* __restrict__ in, const float* __restrict__ bias,
                       float* __restrict__ out) {
    int gwarp = (blockIdx.x * blockDim.x + threadIdx.x) >> 5;
    int lane = threadIdx.x & 31;
    int node = gwarp * 8 + lane / 4;
    int cl = lane & 3;
    if (node >= NN) return;
    int p0 = g_rowptr[node], p1 = g_rowptr[node + 1];
    float acc = 0.f;
    bool act3 = (cl < 3);
    int p = p0;
    for (; p + 4 <= p1; p += 4) {
        int2 e0 = __ldg(&g_entries[p]);
        int2 e1 = __ldg(&g_entries[p + 1]);
        int2 e2 = __ldg(&g_entries[p + 2]);
        int2 e3 = __ldg(&g_entries[p + 3]);
        if (act3) {
            float v0 = (float)__ldg(in + (long)e0.x * 3 + cl);
            float v1 = (float)__ldg(in + (long)e1.x * 3 + cl);
            float v2 = (float)__ldg(in + (long)e2.x * 3 + cl);
            float v3 = (float)__ldg(in + (long)e3.x * 3 + cl);
            acc = fmaf(__int_as_float(e0.y), v0, acc);
            acc = fmaf(__int_as_float(e1.y), v1, acc);
            acc = fmaf(__int_as_float(e2.y), v2, acc);
            acc = fmaf(__int_as_float(e3.y), v3, acc);
        }
    }
    for (; p < p1; p++) {
        int2 e = __ldg(&g_entries[p]);
        if (act3) {
            float v = (float)__ldg(in + (long)e.x * 3 + cl);
            acc = fmaf(__int_as_float(e.y), v, acc);
        }
    }
    if (act3) {
        float v = acc;
        if (BIAS) v += bias[cl];
        if (ACT == 1) v = fmaxf(v, 0.f);
        if (ACT == 2) v = tanhf(v);
        out[(long)node * 3 + cl] = v;
    }
}

// ---------------- fp32 vectorized aggregation, unroll-8 ----------------
template <int C, int SUB, int ACT, bool BIAS>
__global__ void k_aggv(const float* __restrict__ in, const float* __restrict__ bias,
                       float* __restrict__ out) {
    constexpr int NV = C / 4;
    static_assert(NV <= SUB, "SUB too small");
    constexpr int NPW = 32 / SUB;
    int gwarp = (blockIdx.x * blockDim.x + threadIdx.x) >> 5;
    int lane = threadIdx.x & 31;
    int sg = lane / SUB;
    if (sg >= NPW) return;
    int node = gwarp * NPW + sg;
    int vl = lane % SUB;
    if (node >= NN) return;
    int p0 = g_rowptr[node], p1 = g_rowptr[node + 1];
    float4 acc = make_float4(0.f, 0.f, 0.f, 0.f);
    bool active = (vl < NV);
    int p = p0;
    for (; p + 8 <= p1; p += 8) {
        int2 e[8];
#pragma unroll
        for (int u = 0; u < 8; u++) e[u] = __ldg(&g_entries[p + u]);
        if (active) {
            float4 v[8];
#pragma unroll
            for (int u = 0; u < 8; u++)
                v[u] = __ldg((const float4*)(in + (long)e[u].x * C) + vl);
#pragma unroll
            for (int u = 0; u < 8; u++) {
                float w = __int_as_float(e[u].y);
                acc.x = fmaf(w, v[u].x, acc.x); acc.y = fmaf(w, v[u].y, acc.y);
                acc.z = fmaf(w, v[u].z, acc.z); acc.w = fmaf(w, v[u].w, acc.w);
            }
        }
    }
    for (; p + 4 <= p1; p += 4) {
        int2 e[4];
#pragma unroll
        for (int u = 0; u < 4; u++) e[u] = __ldg(&g_entries[p + u]);
        if (active) {
            float4 v[4];
#pragma unroll
            for (int u = 0; u < 4; u++)
                v[u] = __ldg((const float4*)(in + (long)e[u].x * C) + vl);
#pragma unroll
            for (int u = 0; u < 4; u++) {
                float w = __int_as_float(e[u].y);
                acc.x = fmaf(w, v[u].x, acc.x); acc.y = fmaf(w, v[u].y, acc.y);
                acc.z = fmaf(w, v[u].z, acc.z); acc.w = fmaf(w, v[u].w, acc.w);
            }
        }
    }
    for (; p < p1; p++) {
        int2 e = __ldg(&g_entries[p]);
        if (active) {
            float w = __int_as_float(e.y);
            float4 v = __ldg((const float4*)(in + (long)e.x * C) + vl);
            acc.x = fmaf(w, v.x, acc.x); acc.y = fmaf(w, v.y, acc.y);
            acc.z = fmaf(w, v.z, acc.z); acc.w = fmaf(w, v.w, acc.w);
        }
    }
    if (active) {
        if (BIAS) {
            float4 bv = __ldg((const float4*)bias + vl);
            acc.x += bv.x; acc.y += bv.y; acc.z += bv.z; acc.w += bv.w;
        }
        if (ACT == 1) {
            acc.x = fmaxf(acc.x, 0.f); acc.y = fmaxf(acc.y, 0.f);
            acc.z = fmaxf(acc.z, 0.f); acc.w = fmaxf(acc.w, 0.f);
        }
        *((float4*)(out + (long)node * C) + vl) = acc;
    }
}

// ---------------- fp16-input aggregation, unroll-8; OM: 0=f32 out, 1=fp16 out ----------------
__device__ __forceinline__ void accum8h(float* acc, int4 h, float w) {
    const __half2* hp = (const __half2*)&h;
#pragma unroll
    for (int i = 0; i < 4; i++) {
        float2 f = __half22float2(hp[i]);
        acc[2 * i]     = fmaf(w, f.x, acc[2 * i]);
        acc[2 * i + 1] = fmaf(w, f.y, acc[2 * i + 1]);
    }
}

template <int C, int SUB, int ACT, bool BIAS, int OM>
__global__ void k_aggvh(const __half* __restrict__ in, const float* __restrict__ bias,
                        float* __restrict__ out, __half* __restrict__ oh) {
    constexpr int NV = C / 8;
    static_assert(NV <= SUB, "SUB too small");
    constexpr int NPW = 32 / SUB;
    int gwarp = (blockIdx.x * blockDim.x + threadIdx.x) >> 5;
    int lane = threadIdx.x & 31;
    int sg = lane / SUB;
    if (sg >= NPW) return;
    int node = gwarp * NPW + sg;
    int vl = lane % SUB;
    if (node >= NN) return;
    int p0 = g_rowptr[node], p1 = g_rowptr[node + 1];
    float acc[8] = {};
    bool active = (vl < NV);
    int p = p0;
    for (; p + 8 <= p1; p += 8) {
        int2 e[8];
#pragma unroll
        for (int u = 0; u < 8; u++) e[u] = __ldg(&g_entries[p + u]);
        if (active) {
            int4 h[8];
#pragma unroll
            for (int u = 0; u < 8; u++)
                h[u] = __ldg((const int4*)(in + (long)e[u].x * C) + vl);
#pragma unroll
            for (int u = 0; u < 8; u++)
                accum8h(acc, h[u], __int_as_float(e[u].y));
        }
    }
    for (; p + 4 <= p1; p += 4) {
        int2 e[4];
#pragma unroll
        for (int u = 0; u < 4; u++) e[u] = __ldg(&g_entries[p + u]);
        if (active) {
            int4 h[4];
#pragma unroll
            for (int u = 0; u < 4; u++)
                h[u] = __ldg((const int4*)(in + (long)e[u].x * C) + vl);
#pragma unroll
            for (int u = 0; u < 4; u++)
                accum8h(acc, h[u], __int_as_float(e[u].y));
        }
    }
    for (; p < p1; p++) {
        int2 e = __ldg(&g_entries[p]);
        if (active) {
            int4 h = __ldg((const int4*)(in + (long)e.x * C) + vl);
            accum8h(acc, h, __int_as_float(e.y));
        }
    }
    if (active) {
        if (BIAS) {
            const float4* bp = (const float4*)bias + vl * 2;
            float4 b0 = __ldg(bp), b1 = __ldg(bp + 1);
            acc[0] += b0.x; acc[1] += b0.y; acc[2] += b0.z; acc[3] += b0.w;
            acc[4] += b1.x; acc[5] += b1.y; acc[6] += b1.z; acc[7] += b1.w;
        }
        if (ACT == 1) {
#pragma unroll
            for (int i = 0; i < 8; i++) acc[i] = fmaxf(acc[i], 0.f);
        }
        if (OM == 0) {
            float4* op = (float4*)(out + (long)node * C) + vl * 2;
            op[0] = make_float4(acc[0], acc[1], acc[2], acc[3]);
            op[1] = make_float4(acc[4], acc[5], acc[6], acc[7]);
        } else {
            __half hh[8];
#pragma unroll
            for (int i = 0; i < 8; i++) hh[i] = __float2half_rn(acc[i]);
            *((int4*)(oh + (long)node * C) + vl) = *(const int4*)hh;
        }
    }
}

// ---------------- fused eg1 -> fp16 for eg2 GEMM ----------------
__global__ void __launch_bounds__(256)
k_eg1(const float* __restrict__ x, const float* __restrict__ W,
      const float* __restrict__ Bb, __half* __restrict__ oh) {
    __shared__ float sW[480];
    __shared__ float sB[160];
    for (int i = threadIdx.x; i < 480; i += 256) sW[i] = W[i];
    for (int i = threadIdx.x; i < 160; i += 256) sB[i] = Bb[i];
    __syncthreads();
    int gwarp = (blockIdx.x * blockDim.x + threadIdx.x) >> 5;
    int lane = threadIdx.x & 31;
    int nodeBase = gwarp * 8;
    int node = nodeBase + lane / 4;
    int cl = lane & 3;
    float acc = 0.f;
    if (node < NN) {
        int p0 = g_rowptr[node], p1 = g_rowptr[node + 1];
        bool act3 = (cl < 3);
        int p = p0;
        for (; p + 4 <= p1; p += 4) {
            int2 e0 = __ldg(&g_entries[p]);
            int2 e1 = __ldg(&g_entries[p + 1]);
            int2 e2 = __ldg(&g_entries[p + 2]);
            int2 e3 = __ldg(&g_entries[p + 3]);
            if (act3) {
                float v0 = __ldg(x + (long)e0.x * 3 + cl);
                float v1 = __ldg(x + (long)e1.x * 3 + cl);
                float v2 = __ldg(x + (long)e2.x * 3 + cl);
                float v3 = __ldg(x + (long)e3.x * 3 + cl);
                acc = fmaf(__int_as_float(e0.y), v0, acc);
                acc = fmaf(__int_as_float(e1.y), v1, acc);
                acc = fmaf(__int_as_float(e2.y), v2, acc);
                acc = fmaf(__int_as_float(e3.y), v3, acc);
            }
        }
        for (; p < p1; p++) {
            int2 e = __ldg(&g_entries[p]);
            if (act3) {
                float v = __ldg(x + (long)e.x * 3 + cl);
                acc = fmaf(__int_as_float(e.y), v, acc);
            }
        }
    }
#pragma unroll
    for (int j = 0; j < 8; j++) {
        int n2 = nodeBase + j;
        float a0 = __shfl_sync(0xffffffffu, acc, j * 4 + 0);
        float a1 = __shfl_sync(0xffffffffu, acc, j * 4 + 1);
        float a2 = __shfl_sync(0xffffffffu, acc, j * 4 + 2);
        if (n2 >= NN) break;
#pragma unroll
        for (int c0 = 0; c0 < 160; c0 += 32) {
            int c = c0 + lane;
            float v = sB[c];
            v = fmaf(a0, sW[c], v);
            v = fmaf(a1, sW[160 + c], v);
            v = fmaf(a2, sW[320 + c], v);
            v = fmaxf(v, 0.f);
            oh[(long)n2 * 160 + c] = __float2half_rn(v);
        }
    }
}

// ---------------- thread-per-node dense (fp32 input) ----------------
template <int K, int NC, int ACT, bool BIAS, bool OUTH>
__global__ void __launch_bounds__(256)
k_dense(const float* __restrict__ in, const float* __restrict__ W,
        const float* __restrict__ bias, void* __restrict__ outv) {
    __shared__ float sW[K * NC];
    __shared__ float sB[NC];
    for (int i = threadIdx.x; i < K * NC; i += 256) sW[i] = W[i];
    if (BIAS) for (int i = threadIdx.x; i < NC; i += 256) sB[i] = bias[i];
    __syncthreads();
    int n = blockIdx.x * blockDim.x + threadIdx.x;
    if (n >= NN) return;
    float acc[NC];
#pragma unroll
    for (int c = 0; c < NC; c++) acc[c] = BIAS ? sB[c] : 0.f;
    const float4* ip = (const float4*)(in + (long)n * K);
#pragma unroll
    for (int k4 = 0; k4 < K / 4; k4++) {
        float4 v = __ldg(ip + k4);
#pragma unroll
        for (int c = 0; c < NC; c++) {
            acc[c] = fmaf(v.x, sW[(k4 * 4 + 0) * NC + c], acc[c]);
            acc[c] = fmaf(v.y, sW[(k4 * 4 + 1) * NC + c], acc[c]);
            acc[c] = fmaf(v.z, sW[(k4 * 4 + 2) * NC + c], acc[c]);
            acc[c] = fmaf(v.w, sW[(k4 * 4 + 3) * NC + c], acc[c]);
        }
    }
#pragma unroll
    for (int c = 0; c < NC; c++) {
        float v = acc[c];
        if (ACT == 1) v = fmaxf(v, 0.f);
        if (OUTH) ((__half*)outv)[(long)n * NC + c] = __float2half_rn(v);
        else ((float*)outv)[(long)n * NC + c] = v;
    }
}

// ---------------- thread-per-node dense (fp16 input) ----------------
template <int K, int NC, int ACT, bool BIAS>
__global__ void __launch_bounds__(256)
k_dense_h(const __half* __restrict__ in, const float* __restrict__ W,
          const float* __restrict__ bias, float* __restrict__ out) {
    __shared__ float sW[K * NC];
    __shared__ float sB[NC];
    for (int i = threadIdx.x; i < K * NC; i += 256) sW[i] = W[i];
    if (BIAS) for (int i = threadIdx.x; i < NC; i += 256) sB[i] = bias[i];
    __syncthreads();
    int n = blockIdx.x * blockDim.x + threadIdx.x;
    if (n >= NN) return;
    float acc[NC];
#pragma unroll
    for (int c = 0; c < NC; c++) acc[c] = BIAS ? sB[c] : 0.f;
    const int4* ip = (const int4*)(in + (long)n * K);
#pragma unroll
    for (int k8 = 0; k8 < K / 8; k8++) {
        int4 hv = __ldg(ip + k8);
        const __half2* hp = (const __half2*)&hv;
#pragma unroll
        for (int q = 0; q < 4; q++) {
            float2 f = __half22float2(hp[q]);
            int kk = k8 * 8 + q * 2;
#pragma unroll
            for (int c = 0; c < NC; c++) {
                acc[c] = fmaf(f.x, sW[kk * NC + c], acc[c]);
                acc[c] = fmaf(f.y, sW[(kk + 1) * NC + c], acc[c]);
            }
        }
    }
#pragma unroll
    for (int c = 0; c < NC; c++) {
        float v = acc[c];
        if (ACT == 1) v = fmaxf(v, 0.f);
        out[(long)n * NC + c] = v;
    }
}

// ---------------- pure fp16 tensor GEMM ----------------
__device__ __forceinline__ void mma_f16(float* c, uint32_t a0, uint32_t a1,
                                        uint32_t a2, uint32_t a3,
                                        uint32_t b0, uint32_t b1) {
    asm volatile(
        "mma.sync.aligned.m16n8k16.row.col.f32.f16.f16.f32 "
        "{%0,%1,%2,%3}, {%4,%5,%6,%7}, {%8,%9}, {%0,%1,%2,%3};\n"
        : "+f"(c[0]), "+f"(c[1]), "+f"(c[2]), "+f"(c[3])
        : "r"(a0), "r"(a1), "r"(a2), "r"(a3), "r"(b0), "r"(b1));
}

#define HBM_T 128
#define HBN_T 80
#define HBK_T 32
#define HSA 40
#define HSB 40

template <int ACT, bool BIAS, int OUTM>
__global__ void __launch_bounds__(256, 2)
k_gemm_h(const __half* __restrict__ Ah, const __half* __restrict__ Bth,
         const float* __restrict__ bias, void* __restrict__ outv,
         int M, int K, int Nc) {
    __shared__ __half sAh[HBM_T * HSA];
    __shared__ __half sBh[HBN_T * HSB];

    int tid = threadIdx.x;
    int wid = tid >> 5;
    int lane = tid & 31;
    int g = lane >> 2;
    int t = lane & 3;
    int wm = wid & 3;
    int wn = wid >> 2;
    int row0 = blockIdx.y * HBM_T;
    int col0 = blockIdx.x * HBN_T;

    float acc[2][5][4];
#pragma unroll
    for (int i = 0; i < 2; i++)
#pragma unroll
        for (int j = 0; j < 5; j++)
#pragma unroll
            for (int q = 0; q < 4; q++) acc[i][j][q] = 0.f;

    const int4 z4 = make_int4(0, 0, 0, 0);
    for (int k0 = 0; k0 < K; k0 += HBK_T) {
#pragma unroll
        for (int it = 0; it < 2; it++) {
            int idx = tid + it * 256;
            int m = idx >> 2, kq = idx & 3;
            int gm = row0 + m;
            int gk = k0 + kq * 8;
            bool ok = (gm < M) && (gk < K);
            *(int4*)&sAh[m * HSA + kq * 8] = ok ? *(const int4*)&Ah[(long)gm * K + gk] : z4;
        }
        {
            int idx = tid;
            if (idx < 320) {
                int n = idx >> 2, kq = idx & 3;
                int gk = k0 + kq * 8;
                bool ok = (gk < K);
                *(int4*)&sBh[n * HSB + kq * 8] = ok ? *(const int4*)&Bth[(long)(col0 + n) * K + gk] : z4;
            }
            idx = tid + 256;
            if (idx < 320) {
                int n = idx >> 2, kq = idx & 3;
                int gk = k0 + kq * 8;
                bool ok = (gk < K);
                *(int4*)&sBh[n * HSB + kq * 8] = ok ? *(const int4*)&Bth[(long)(col0 + n) * K + gk] : z4;
            }
        }
        __syncthreads();

#pragma unroll
        for (int ks = 0; ks < HBK_T; ks += 16) {
            uint32_t ah[2][4];
#pragma unroll
            for (int i = 0; i < 2; i++) {
                int r0 = wm * 32 + i * 16 + g;
                ah[i][0] = *(const uint32_t*)&sAh[r0 * HSA + ks + 2 * t];
                ah[i][1] = *(const uint32_t*)&sAh[(r0 + 8) * HSA + ks + 2 * t];
                ah[i][2] = *(const uint32_t*)&sAh[r0 * HSA + ks + 2 * t + 8];
                ah[i][3] = *(const uint32_t*)&sAh[(r0 + 8) * HSA + ks + 2 * t + 8];
            }
#pragma unroll
            for (int j = 0; j < 5; j++) {
                int c = wn * 40 + j * 8 + g;
                uint32_t bh0 = *(const uint32_t*)&sBh[c * HSB + ks + 2 * t];
                uint32_t bh1 = *(const uint32_t*)&sBh[c * HSB + ks + 2 * t + 8];
#pragma unroll
                for (int i = 0; i < 2; i++)
                    mma_f16(acc[i][j], ah[i][0], ah[i][1], ah[i][2], ah[i][3], bh0, bh1);
            }
        }
        __syncthreads();
    }

#pragma unroll
    for (int i = 0; i < 2; i++) {
        int rbase = row0 + wm * 32 + i * 16 + g;
#pragma unroll
        for (int j = 0; j < 5; j++) {
            int cbase = col0 + wn * 40 + j * 8 + t * 2;
#pragma unroll
            for (int q = 0; q < 4; q++) {
                int gm = rbase + ((q >= 2) ? 8 : 0);
                int gn = cbase + (q & 1);
                if (gm < M && gn < Nc) {
                    float v = acc[i][j][q];
                    if (BIAS) v += bias[gn];
                    if (ACT == 1) v = fmaxf(v, 0.f);
                    if (OUTM == 1) ((__half*)outv)[(long)gm * Nc + gn] = __float2half_rn(v);
                    else ((float*)outv)[(long)gm * Nc + gn] = v;
                }
            }
        }
    }
}

// ---------------- fused dense chain ----------------
__global__ void __launch_bounds__(256)
k_chain(const float* __restrict__ in, float* __restrict__ out,
        const float* __restrict__ w1, const float* __restrict__ b1,
        const float* __restrict__ w2, const float* __restrict__ b2,
        const float* __restrict__ w3, const float* __restrict__ b3,
        const float* __restrict__ w4, const float* __restrict__ b4) {
    __shared__ float sw1[200], sb1[10], sw2[30], sb2[3], sw3[30], sb3[10], sw4[200], sb4[20];
    int tid = threadIdx.x;
    for (int i = tid; i < 200; i += 256) sw1[i] = w1[i];
    for (int i = tid; i < 10; i += 256) sb1[i] = b1[i];
    for (int i = tid; i < 30; i += 256) sw2[i] = w2[i];
    for (int i = tid; i < 3; i += 256) sb2[i] = b2[i];
    for (int i = tid; i < 30; i += 256) sw3[i] = w3[i];
    for (int i = tid; i < 10; i += 256) sb3[i] = b3[i];
    for (int i = tid; i < 200; i += 256) sw4[i] = w4[i];
    for (int i = tid; i < 20; i += 256) sb4[i] = b4[i];
    __syncthreads();

    int n = blockIdx.x * blockDim.x + tid;
    if (n >= NN) return;
    float h0[20];
    const float4* ip = (const float4*)(in + (long)n * 20);
#pragma unroll
    for (int i = 0; i < 5; i++) {
        float4 v = __ldg(ip + i);
        h0[i * 4 + 0] = v.x; h0[i * 4 + 1] = v.y; h0[i * 4 + 2] = v.z; h0[i * 4 + 3] = v.w;
    }
    float h1[10];
#pragma unroll
    for (int j = 0; j < 10; j++) {
        float s = sb1[j];
#pragma unroll
        for (int i = 0; i < 20; i++) s = fmaf(h0[i], sw1[i * 10 + j], s);
        h1[j] = fmaxf(s, 0.f);
    }
    float z[3];
#pragma unroll
    for (int j = 0; j < 3; j++) {
        float s = sb2[j];
#pragma unroll
        for (int i = 0; i < 10; i++) s = fmaf(h1[i], sw2[i * 3 + j], s);
        z[j] = s;
    }
    float h2[10];
#pragma unroll
    for (int j = 0; j < 10; j++) {
        float s = sb3[j];
#pragma unroll
        for (int i = 0; i < 3; i++) s = fmaf(z[i], sw3[i * 10 + j], s);
        h2[j] = fmaxf(s, 0.f);
    }
    float* op = out + (long)n * 20;
#pragma unroll
    for (int j = 0; j < 20; j++) {
        float s = sb4[j];
#pragma unroll
        for (int i = 0; i < 10; i++) s = fmaf(h2[i], sw4[i * 20 + j], s);
        op[j] = fmaxf(s, 0.f);
    }
}

// ---------------- driver ----------------
template <int ACT, bool BIAS, int OUTM>
static void gemm_h(const __half* Ah, const __half* Bth, const float* b, void* o,
                   int K, int Nc) {
    dim3 g(cdiv(Nc, HBN_T), cdiv(NN, HBM_T));
    k_gemm_h<ACT, BIAS, OUTM><<<g, 256>>>(Ah, Bth, b, o, NN, K, Nc);
}

extern "C" void kernel_launch(void* const* d_in, const int* in_sizes, int n_in,
                              void* d_out, int out_size) {
    const float* x = (const float*)d_in[0];
    const int* ei = (const int*)d_in[1];
    const int* src = ei;
    const int* dst = ei + NE;
    const float* W[12];
    const float* B[12];
    for (int i = 0; i < 12; i++) {
        W[i] = (const float*)d_in[2 + 2 * i];
        B[i] = (const float*)d_in[3 + 2 * i];
    }
    float* bufA; cudaGetSymbolAddress((void**)&bufA, g_bufA);
    float* bufB; cudaGetSymbolAddress((void**)&bufB, g_bufB);
    __half* bufH; cudaGetSymbolAddress((void**)&bufH, g_bufH);
    __half* ah; cudaGetSymbolAddress((void**)&ah, g_ah);
    __half* ah2; cudaGetSymbolAddress((void**)&ah2, g_ah2);
    __half* wth; cudaGetSymbolAddress((void**)&wth, g_wth);
    float* outp = (float*)d_out;

    const int NB = cdiv(NN, 1024);
    k_wconv_all<<<cdiv(32000, 256), 256>>>(W[1], W[2], W[9], W[10]);
    // CSR build
    k_init_cnt<<<cdiv(NN, 256), 256>>>();
    k_count<<<cdiv(NE, 256), 256>>>(dst);
    k_scan1<<<NB, 1024>>>();
    k_scan2<<<1, 128>>>(NB);
    k_scan3<<<NB, 1024>>>();
    k_self<<<cdiv(NN, 256), 256>>>();
    k_edges<<<cdiv(NE, 256), 256>>>(src, dst);

    const int TPB = 256;
    int blocks80 = cdiv(cdiv(NN, 3) * 32, TPB);   // SUB=10, 3 nodes/warp
    int blocks40 = cdiv(cdiv(NN, 6) * 32, TPB);   // SUB=5, 6 nodes/warp
    int blocks4  = cdiv(cdiv(NN, 8) * 32, TPB);   // C=3, 8 nodes/warp
    int blocksN  = cdiv(NN, TPB);

    // encoder
    k_eg1<<<blocks4, TPB>>>(x, W[0], B[0], ah);                                     // agg+eg1 -> fp16
    gemm_h<0, false, 1>(ah, wth + WOFF_EG2, nullptr, bufH, 160, 80);                // eg2 matmul
    k_aggvh<80, 10, 1, true, 1><<<blocks80, TPB>>>(bufH, B[1], nullptr, ah);        // eg2 agg -> fp16
    gemm_h<0, false, 1>(ah, wth + WOFF_EG3, nullptr, bufH, 80, 40);                 // eg3 matmul
    k_aggvh<40, 5, 1, true, 0><<<blocks40, TPB>>>(bufH, B[2], bufB, nullptr);       // eg3 agg
    k_dense<40, 20, 0, false, false><<<blocksN, TPB>>>(bufB, W[3], nullptr, bufA);  // eg4 matmul
    k_aggv<20, 5, 1, true><<<blocks40, TPB>>>(bufA, B[3], bufB);                    // eg4 agg
    // latent dense chain
    k_chain<<<blocksN, TPB>>>(bufB, bufA, W[4], B[4], W[5], B[5], W[6], B[6], W[7], B[7]);
    // decoder
    k_aggv<20, 5, 0, false><<<blocks40, TPB>>>(bufA, nullptr, bufB);                // dg1 agg
    k_dense<20, 40, 1, true, true><<<blocksN, TPB>>>(bufB, W[8], B[8], bufH);       // dg1 -> fp16
    k_aggvh<40, 5, 0, false, 1><<<blocks40, TPB>>>(bufH, nullptr, nullptr, ah);     // dg2 agg -> fp16
    gemm_h<1, true, 1>(ah, wth + WOFF_DG2, B[9], bufH, 40, 80);                     // dg2
    k_aggvh<80, 10, 0, false, 1><<<blocks80, TPB>>>(bufH, nullptr, nullptr, ah);    // dg3 agg -> fp16
    gemm_h<1, true, 1>(ah, wth + WOFF_DG3, B[10], ah2, 80, 160);                    // dg3 -> fp16
    k_dense_h<160, 3, 0, false><<<blocksN, TPB>>>(ah2, W[11], nullptr, bufB);       // dg4 matmul
    k_agg3<2, true, float><<<blocks4, TPB>>>(bufB, B[11], outp);                    // dg4 agg+tanh
}

// round 12
// speedup vs baseline: 1.0187x; 1.0187x over previous
#include <cuda_runtime.h>
#include <cuda_fp16.h>
#include <cuda_bf16.h>
#include <cstdint>

#define NN 100000
#define NE 1600000
#define NTOT (NE + NN)

// ---------------- scratch (device globals: allocation-free) ----------------
__device__ float  g_bufA[NN * 160];
__device__ float  g_bufB[NN * 160];
__device__ __align__(16) __half g_bufH[NN * 80];
__device__ __align__(16) __half g_ah[NN * 160];    // GEMM A operand (fp16)
__device__ __align__(16) __half g_ah2[NN * 160];   // dg3 fp16 output
__device__ __align__(16) __half g_wth[32000];      // transposed weights [n*K+k] fp16
__device__ int    g_cnt[NN];
__device__ float  g_dis[NN];
__device__ int    g_rowptr[NN + 1];
__device__ int    g_fill[NN];
__device__ int2   g_entries[NTOT];
__device__ int    g_bsums[128];

static inline int cdiv(int a, int b) { return (a + b - 1) / b; }

#define WOFF_EG2 0
#define WOFF_EG3 12800
#define WOFF_DG2 16000
#define WOFF_DG3 19200

// ---------------- fused: weight convert+transpose AND cnt init ----------------
__global__ void k_wconv_init(const float* __restrict__ W1, const float* __restrict__ W2,
                             const float* __restrict__ W9, const float* __restrict__ W10) {
    int idx = blockIdx.x * blockDim.x + threadIdx.x;
    if (idx < NN) g_cnt[idx] = 1;   // self-loop count
    if (idx >= 32000) return;
    const float* W; int K, Nc, off, li;
    if (idx < 12800)      { W = W1;  K = 160; Nc = 80;  off = WOFF_EG2; li = idx; }
    else if (idx < 16000) { W = W2;  K = 80;  Nc = 40;  off = WOFF_EG3; li = idx - 12800; }
    else if (idx < 19200) { W = W9;  K = 40;  Nc = 80;  off = WOFF_DG2; li = idx - 16000; }
    else                  { W = W10; K = 80;  Nc = 160; off = WOFF_DG3; li = idx - 19200; }
    int k = li / Nc, n = li - k * Nc;
    g_wth[off + n * K + k] = __float2half_rn(W[li]);
}

// ---------------- CSR build ----------------
__global__ void k_count(const int* __restrict__ dst) {
    int e = blockIdx.x * blockDim.x + threadIdx.x;
    if (e < NE) atomicAdd(&g_cnt[dst[e]], 1);
}
__global__ void k_scan1() {
    __shared__ int s[1024];
    int i = blockIdx.x * 1024 + threadIdx.x;
    int v = (i < NN) ? g_cnt[i] : 0;
    if (i < NN) g_dis[i] = rsqrtf((float)v);
    s[threadIdx.x] = v;
    __syncthreads();
    for (int d = 1; d < 1024; d <<= 1) {
        int t = (threadIdx.x >= d) ? s[threadIdx.x - d] : 0;
        __syncthreads();
        s[threadIdx.x] += t;
        __syncthreads();
    }
    if (i < NN) g_rowptr[i + 1] = s[threadIdx.x];
    if (threadIdx.x == 1023) g_bsums[blockIdx.x] = s[1023];
}
__global__ void k_scan2(int nb) {
    __shared__ int s[128];
    int v = (threadIdx.x < nb) ? g_bsums[threadIdx.x] : 0;
    s[threadIdx.x] = v;
    __syncthreads();
    for (int d = 1; d < 128; d <<= 1) {
        int t = (threadIdx.x >= d) ? s[threadIdx.x - d] : 0;
        __syncthreads();
        s[threadIdx.x] += t;
        __syncthreads();
    }
    if (threadIdx.x < nb) g_bsums[threadIdx.x] = s[threadIdx.x] - v;
}
// scan3 fused with self-loop placement + fill-cursor init
__global__ void k_scan3_self() {
    int i = blockIdx.x * 1024 + threadIdx.x;
    if (i >= NN) return;
    int rp1 = g_rowptr[i + 1] + g_bsums[blockIdx.x];
    g_rowptr[i + 1] = rp1;
    if (i == 0) g_rowptr[0] = 0;
    int p = rp1 - g_cnt[i];          // final rowptr[i]
    float d = g_dis[i];
    g_entries[p] = make_int2(i, __float_as_int(d * d));
    g_fill[i] = p + 1;
}
__global__ void k_edges(const int* __restrict__ src, const int* __restrict__ dst) {
    int e = blockIdx.x * blockDim.x + threadIdx.x;
    if (e < NE) {
        int s = src[e], d = dst[e];
        int p = atomicAdd(&g_fill[d], 1);
        g_entries[p] = make_int2(s, __float_as_int(g_dis[s] * g_dis[d]));
    }
}

// ---------------- scalar aggregation (C=3) ----------------
template <int ACT, bool BIAS, typename TIN>
__global__ void k_agg3(const TIN* __restrict__ in, const float* __restrict__ bias,
                       float* __restrict__ out) {
    int gwarp = (blockIdx.x * blockDim.x + threadIdx.x) >> 5;
    int lane = threadIdx.x & 31;
    int node = gwarp * 8 + lane / 4;
    int cl = lane & 3;
    if (node >= NN) return;
    int p0 = g_rowptr[node], p1 = g_rowptr[node + 1];
    float acc = 0.f;
    bool act3 = (cl < 3);
    int p = p0;
    for (; p + 4 <= p1; p += 4) {
        int2 e0 = __ldg(&g_entries[p]);
        int2 e1 = __ldg(&g_entries[p + 1]);
        int2 e2 = __ldg(&g_entries[p + 2]);
        int2 e3 = __ldg(&g_entries[p + 3]);
        if (act3) {
            float v0 = (float)__ldg(in + (long)e0.x * 3 + cl);
            float v1 = (float)__ldg(in + (long)e1.x * 3 + cl);
            float v2 = (float)__ldg(in + (long)e2.x * 3 + cl);
            float v3 = (float)__ldg(in + (long)e3.x * 3 + cl);
            acc = fmaf(__int_as_float(e0.y), v0, acc);
            acc = fmaf(__int_as_float(e1.y), v1, acc);
            acc = fmaf(__int_as_float(e2.y), v2, acc);
            acc = fmaf(__int_as_float(e3.y), v3, acc);
        }
    }
    for (; p < p1; p++) {
        int2 e = __ldg(&g_entries[p]);
        if (act3) {
            float v = (float)__ldg(in + (long)e.x * 3 + cl);
            acc = fmaf(__int_as_float(e.y), v, acc);
        }
    }
    if (act3) {
        float v = acc;
        if (BIAS) v += bias[cl];
        if (ACT == 1) v = fmaxf(v, 0.f);
        if (ACT == 2) v = tanhf(v);
        out[(long)node * 3 + cl] = v;
    }
}

// ---------------- fp32 vectorized aggregation, unroll-4 ----------------
template <int C, int SUB, int ACT, bool BIAS>
__global__ void k_aggv(const float* __restrict__ in, const float* __restrict__ bias,
                       float* __restrict__ out) {
    constexpr int NV = C / 4;
    static_assert(NV <= SUB, "SUB too small");
    constexpr int NPW = 32 / SUB;
    int gwarp = (blockIdx.x * blockDim.x + threadIdx.x) >> 5;
    int lane = threadIdx.x & 31;
    int sg = lane / SUB;
    if (sg >= NPW) return;
    int node = gwarp * NPW + sg;
    int vl = lane % SUB;
    if (node >= NN) return;
    int p0 = g_rowptr[node], p1 = g_rowptr[node + 1];
    float4 acc = make_float4(0.f, 0.f, 0.f, 0.f);
    bool active = (vl < NV);
    int p = p0;
    for (; p + 4 <= p1; p += 4) {
        int2 e0 = __ldg(&g_entries[p]);
        int2 e1 = __ldg(&g_entries[p + 1]);
        int2 e2 = __ldg(&g_entries[p + 2]);
        int2 e3 = __ldg(&g_entries[p + 3]);
        if (active) {
            float4 v0 = __ldg((const float4*)(in + (long)e0.x * C) + vl);
            float4 v1 = __ldg((const float4*)(in + (long)e1.x * C) + vl);
            float4 v2 = __ldg((const float4*)(in + (long)e2.x * C) + vl);
            float4 v3 = __ldg((const float4*)(in + (long)e3.x * C) + vl);
            float w0 = __int_as_float(e0.y), w1 = __int_as_float(e1.y);
            float w2 = __int_as_float(e2.y), w3 = __int_as_float(e3.y);
            acc.x = fmaf(w0, v0.x, acc.x); acc.y = fmaf(w0, v0.y, acc.y);
            acc.z = fmaf(w0, v0.z, acc.z); acc.w = fmaf(w0, v0.w, acc.w);
            acc.x = fmaf(w1, v1.x, acc.x); acc.y = fmaf(w1, v1.y, acc.y);
            acc.z = fmaf(w1, v1.z, acc.z); acc.w = fmaf(w1, v1.w, acc.w);
            acc.x = fmaf(w2, v2.x, acc.x); acc.y = fmaf(w2, v2.y, acc.y);
            acc.z = fmaf(w2, v2.z, acc.z); acc.w = fmaf(w2, v2.w, acc.w);
            acc.x = fmaf(w3, v3.x, acc.x); acc.y = fmaf(w3, v3.y, acc.y);
            acc.z = fmaf(w3, v3.z, acc.z); acc.w = fmaf(w3, v3.w, acc.w);
        }
    }
    for (; p < p1; p++) {
        int2 e = __ldg(&g_entries[p]);
        if (active) {
            float w = __int_as_float(e.y);
            float4 v = __ldg((const float4*)(in + (long)e.x * C) + vl);
            acc.x = fmaf(w, v.x, acc.x); acc.y = fmaf(w, v.y, acc.y);
            acc.z = fmaf(w, v.z, acc.z); acc.w = fmaf(w, v.w, acc.w);
        }
    }
    if (active) {
        if (BIAS) {
            float4 bv = __ldg((const float4*)bias + vl);
            acc.x += bv.x; acc.y += bv.y; acc.z += bv.z; acc.w += bv.w;
        }
        if (ACT == 1) {
            acc.x = fmaxf(acc.x, 0.f); acc.y = fmaxf(acc.y, 0.f);
            acc.z = fmaxf(acc.z, 0.f); acc.w = fmaxf(acc.w, 0.f);
        }
        *((float4*)(out + (long)node * C) + vl) = acc;
    }
}

// ---------------- fp16-input aggregation, unroll-4; OM: 0=f32 out, 1=fp16 out ----------------
__device__ __forceinline__ void accum8h(float* acc, int4 h, float w) {
    const __half2* hp = (const __half2*)&h;
#pragma unroll
    for (int i = 0; i < 4; i++) {
        float2 f = __half22float2(hp[i]);
        acc[2 * i]     = fmaf(w, f.x, acc[2 * i]);
        acc[2 * i + 1] = fmaf(w, f.y, acc[2 * i + 1]);
    }
}

template <int C, int SUB, int ACT, bool BIAS, int OM>
__global__ void k_aggvh(const __half* __restrict__ in, const float* __restrict__ bias,
                        float* __restrict__ out, __half* __restrict__ oh) {
    constexpr int NV = C / 8;
    static_assert(NV <= SUB, "SUB too small");
    constexpr int NPW = 32 / SUB;
    int gwarp = (blockIdx.x * blockDim.x + threadIdx.x) >> 5;
    int lane = threadIdx.x & 31;
    int sg = lane / SUB;
    if (sg >= NPW) return;
    int node = gwarp * NPW + sg;
    int vl = lane % SUB;
    if (node >= NN) return;
    int p0 = g_rowptr[node], p1 = g_rowptr[node + 1];
    float acc[8] = {};
    bool active = (vl < NV);
    int p = p0;
    for (; p + 4 <= p1; p += 4) {
        int2 e0 = __ldg(&g_entries[p]);
        int2 e1 = __ldg(&g_entries[p + 1]);
        int2 e2 = __ldg(&g_entries[p + 2]);
        int2 e3 = __ldg(&g_entries[p + 3]);
        if (active) {
            int4 h0 = __ldg((const int4*)(in + (long)e0.x * C) + vl);
            int4 h1 = __ldg((const int4*)(in + (long)e1.x * C) + vl);
            int4 h2 = __ldg((const int4*)(in + (long)e2.x * C) + vl);
            int4 h3 = __ldg((const int4*)(in + (long)e3.x * C) + vl);
            accum8h(acc, h0, __int_as_float(e0.y));
            accum8h(acc, h1, __int_as_float(e1.y));
            accum8h(acc, h2, __int_as_float(e2.y));
            accum8h(acc, h3, __int_as_float(e3.y));
        }
    }
    for (; p < p1; p++) {
        int2 e = __ldg(&g_entries[p]);
        if (active) {
            int4 h = __ldg((const int4*)(in + (long)e.x * C) + vl);
            accum8h(acc, h, __int_as_float(e.y));
        }
    }
    if (active) {
        if (BIAS) {
            const float4* bp = (const float4*)bias + vl * 2;
            float4 b0 = __ldg(bp), b1 = __ldg(bp + 1);
            acc[0] += b0.x; acc[1] += b0.y; acc[2] += b0.z; acc[3] += b0.w;
            acc[4] += b1.x; acc[5] += b1.y; acc[6] += b1.z; acc[7] += b1.w;
        }
        if (ACT == 1) {
#pragma unroll
            for (int i = 0; i < 8; i++) acc[i] = fmaxf(acc[i], 0.f);
        }
        if (OM == 0) {
            float4* op = (float4*)(out + (long)node * C) + vl * 2;
            op[0] = make_float4(acc[0], acc[1], acc[2], acc[3]);
            op[1] = make_float4(acc[4], acc[5], acc[6], acc[7]);
        } else {
            __half hh[8];
#pragma unroll
            for (int i = 0; i < 8; i++) hh[i] = __float2half_rn(acc[i]);
            *((int4*)(oh + (long)node * C) + vl) = *(const int4*)hh;
        }
    }
}

// ---------------- fused eg1 -> fp16 for eg2 GEMM ----------------
__global__ void __launch_bounds__(256)
k_eg1(const float* __restrict__ x, const float* __restrict__ W,
      const float* __restrict__ Bb, __half* __restrict__ oh) {
    __shared__ float sW[480];
    __shared__ float sB[160];
    for (int i = threadIdx.x; i < 480; i += 256) sW[i] = W[i];
    for (int i = threadIdx.x; i < 160; i += 256) sB[i] = Bb[i];
    __syncthreads();
    int gwarp = (blockIdx.x * blockDim.x + threadIdx.x) >> 5;
    int lane = threadIdx.x & 31;
    int nodeBase = gwarp * 8;
    int node = nodeBase + lane / 4;
    int cl = lane & 3;
    float acc = 0.f;
    if (node < NN) {
        int p0 = g_rowptr[node], p1 = g_rowptr[node + 1];
        bool act3 = (cl < 3);
        int p = p0;
        for (; p + 4 <= p1; p += 4) {
            int2 e0 = __ldg(&g_entries[p]);
            int2 e1 = __ldg(&g_entries[p + 1]);
            int2 e2 = __ldg(&g_entries[p + 2]);
            int2 e3 = __ldg(&g_entries[p + 3]);
            if (act3) {
                float v0 = __ldg(x + (long)e0.x * 3 + cl);
                float v1 = __ldg(x + (long)e1.x * 3 + cl);
                float v2 = __ldg(x + (long)e2.x * 3 + cl);
                float v3 = __ldg(x + (long)e3.x * 3 + cl);
                acc = fmaf(__int_as_float(e0.y), v0, acc);
                acc = fmaf(__int_as_float(e1.y), v1, acc);
                acc = fmaf(__int_as_float(e2.y), v2, acc);
                acc = fmaf(__int_as_float(e3.y), v3, acc);
            }
        }
        for (; p < p1; p++) {
            int2 e = __ldg(&g_entries[p]);
            if (act3) {
                float v = __ldg(x + (long)e.x * 3 + cl);
                acc = fmaf(__int_as_float(e.y), v, acc);
            }
        }
    }
#pragma unroll
    for (int j = 0; j < 8; j++) {
        int n2 = nodeBase + j;
        float a0 = __shfl_sync(0xffffffffu, acc, j * 4 + 0);
        float a1 = __shfl_sync(0xffffffffu, acc, j * 4 + 1);
        float a2 = __shfl_sync(0xffffffffu, acc, j * 4 + 2);
        if (n2 >= NN) break;
#pragma unroll
        for (int c0 = 0; c0 < 160; c0 += 32) {
            int c = c0 + lane;
            float v = sB[c];
            v = fmaf(a0, sW[c], v);
            v = fmaf(a1, sW[160 + c], v);
            v = fmaf(a2, sW[320 + c], v);
            v = fmaxf(v, 0.f);
            oh[(long)n2 * 160 + c] = __float2half_rn(v);
        }
    }
}

// ---------------- thread-per-node dense (fp32 input) ----------------
template <int K, int NC, int ACT, bool BIAS, bool OUTH>
__global__ void __launch_bounds__(256)
k_dense(const float* __restrict__ in, const float* __restrict__ W,
        const float* __restrict__ bias, void* __restrict__ outv) {
    __shared__ float sW[K * NC];
    __shared__ float sB[NC];
    for (int i = threadIdx.x; i < K * NC; i += 256) sW[i] = W[i];
    if (BIAS) for (int i = threadIdx.x; i < NC; i += 256) sB[i] = bias[i];
    __syncthreads();
    int n = blockIdx.x * blockDim.x + threadIdx.x;
    if (n >= NN) return;
    float acc[NC];
#pragma unroll
    for (int c = 0; c < NC; c++) acc[c] = BIAS ? sB[c] : 0.f;
    const float4* ip = (const float4*)(in + (long)n * K);
#pragma unroll
    for (int k4 = 0; k4 < K / 4; k4++) {
        float4 v = __ldg(ip + k4);
#pragma unroll
        for (int c = 0; c < NC; c++) {
            acc[c] = fmaf(v.x, sW[(k4 * 4 + 0) * NC + c], acc[c]);
            acc[c] = fmaf(v.y, sW[(k4 * 4 + 1) * NC + c], acc[c]);
            acc[c] = fmaf(v.z, sW[(k4 * 4 + 2) * NC + c], acc[c]);
            acc[c] = fmaf(v.w, sW[(k4 * 4 + 3) * NC + c], acc[c]);
        }
    }
#pragma unroll
    for (int c = 0; c < NC; c++) {
        float v = acc[c];
        if (ACT == 1) v = fmaxf(v, 0.f);
        if (OUTH) ((__half*)outv)[(long)n * NC + c] = __float2half_rn(v);
        else ((float*)outv)[(long)n * NC + c] = v;
    }
}

// ---------------- thread-per-node dense (fp16 input) ----------------
template <int K, int NC, int ACT, bool BIAS>
__global__ void __launch_bounds__(256)
k_dense_h(const __half* __restrict__ in, const float* __restrict__ W,
          const float* __restrict__ bias, float* __restrict__ out) {
    __shared__ float sW[K * NC];
    __shared__ float sB[NC];
    for (int i = threadIdx.x; i < K * NC; i += 256) sW[i] = W[i];
    if (BIAS) for (int i = threadIdx.x; i < NC; i += 256) sB[i] = bias[i];
    __syncthreads();
    int n = blockIdx.x * blockDim.x + threadIdx.x;
    if (n >= NN) return;
    float acc[NC];
#pragma unroll
    for (int c = 0; c < NC; c++) acc[c] = BIAS ? sB[c] : 0.f;
    const int4* ip = (const int4*)(in + (long)n * K);
#pragma unroll
    for (int k8 = 0; k8 < K / 8; k8++) {
        int4 hv = __ldg(ip + k8);
        const __half2* hp = (const __half2*)&hv;
#pragma unroll
        for (int q = 0; q < 4; q++) {
            float2 f = __half22float2(hp[q]);
            int kk = k8 * 8 + q * 2;
#pragma unroll
            for (int c = 0; c < NC; c++) {
                acc[c] = fmaf(f.x, sW[kk * NC + c], acc[c]);
                acc[c] = fmaf(f.y, sW[(kk + 1) * NC + c], acc[c]);
            }
        }
    }
#pragma unroll
    for (int c = 0; c < NC; c++) {
        float v = acc[c];
        if (ACT == 1) v = fmaxf(v, 0.f);
        out[(long)n * NC + c] = v;
    }
}

// ---------------- pure fp16 tensor GEMM ----------------
__device__ __forceinline__ void mma_f16(float* c, uint32_t a0, uint32_t a1,
                                        uint32_t a2, uint32_t a3,
                                        uint32_t b0, uint32_t b1) {
    asm volatile(
        "mma.sync.aligned.m16n8k16.row.col.f32.f16.f16.f32 "
        "{%0,%1,%2,%3}, {%4,%5,%6,%7}, {%8,%9}, {%0,%1,%2,%3};\n"
        : "+f"(c[0]), "+f"(c[1]), "+f"(c[2]), "+f"(c[3])
        : "r"(a0), "r"(a1), "r"(a2), "r"(a3), "r"(b0), "r"(b1));
}

#define HBM_T 128
#define HBN_T 80
#define HBK_T 32
#define HSA 40
#define HSB 40

template <int ACT, bool BIAS, int OUTM>
__global__ void __launch_bounds__(256, 2)
k_gemm_h(const __half* __restrict__ Ah, const __half* __restrict__ Bth,
         const float* __restrict__ bias, void* __restrict__ outv,
         int M, int K, int Nc) {
    __shared__ __half sAh[HBM_T * HSA];
    __shared__ __half sBh[HBN_T * HSB];

    int tid = threadIdx.x;
    int wid = tid >> 5;
    int lane = tid & 31;
    int g = lane >> 2;
    int t = lane & 3;
    int wm = wid & 3;
    int wn = wid >> 2;
    int row0 = blockIdx.y * HBM_T;
    int col0 = blockIdx.x * HBN_T;

    float acc[2][5][4];
#pragma unroll
    for (int i = 0; i < 2; i++)
#pragma unroll
        for (int j = 0; j < 5; j++)
#pragma unroll
            for (int q = 0; q < 4; q++) acc[i][j][q] = 0.f;

    const int4 z4 = make_int4(0, 0, 0, 0);
    for (int k0 = 0; k0 < K; k0 += HBK_T) {
#pragma unroll
        for (int it = 0; it < 2; it++) {
            int idx = tid + it * 256;
            int m = idx >> 2, kq = idx & 3;
            int gm = row0 + m;
            int gk = k0 + kq * 8;
            bool ok = (gm < M) && (gk < K);
            *(int4*)&sAh[m * HSA + kq * 8] = ok ? *(const int4*)&Ah[(long)gm * K + gk] : z4;
        }
        {
            int idx = tid;
            if (idx < 320) {
                int n = idx >> 2, kq = idx & 3;
                int gk = k0 + kq * 8;
                bool ok = (gk < K);
                *(int4*)&sBh[n * HSB + kq * 8] = ok ? *(const int4*)&Bth[(long)(col0 + n) * K + gk] : z4;
            }
            idx = tid + 256;
            if (idx < 320) {
                int n = idx >> 2, kq = idx & 3;
                int gk = k0 + kq * 8;
                bool ok = (gk < K);
                *(int4*)&sBh[n * HSB + kq * 8] = ok ? *(const int4*)&Bth[(long)(col0 + n) * K + gk] : z4;
            }
        }
        __syncthreads();

#pragma unroll
        for (int ks = 0; ks < HBK_T; ks += 16) {
            uint32_t ah[2][4];
#pragma unroll
            for (int i = 0; i < 2; i++) {
                int r0 = wm * 32 + i * 16 + g;
                ah[i][0] = *(const uint32_t*)&sAh[r0 * HSA + ks + 2 * t];
                ah[i][1] = *(const uint32_t*)&sAh[(r0 + 8) * HSA + ks + 2 * t];
                ah[i][2] = *(const uint32_t*)&sAh[r0 * HSA + ks + 2 * t + 8];
                ah[i][3] = *(const uint32_t*)&sAh[(r0 + 8) * HSA + ks + 2 * t + 8];
            }
#pragma unroll
            for (int j = 0; j < 5; j++) {
                int c = wn * 40 + j * 8 + g;
                uint32_t bh0 = *(const uint32_t*)&sBh[c * HSB + ks + 2 * t];
                uint32_t bh1 = *(const uint32_t*)&sBh[c * HSB + ks + 2 * t + 8];
#pragma unroll
                for (int i = 0; i < 2; i++)
                    mma_f16(acc[i][j], ah[i][0], ah[i][1], ah[i][2], ah[i][3], bh0, bh1);
            }
        }
        __syncthreads();
    }

#pragma unroll
    for (int i = 0; i < 2; i++) {
        int rbase = row0 + wm * 32 + i * 16 + g;
#pragma unroll
        for (int j = 0; j < 5; j++) {
            int cbase = col0 + wn * 40 + j * 8 + t * 2;
#pragma unroll
            for (int q = 0; q < 4; q++) {
                int gm = rbase + ((q >= 2) ? 8 : 0);
                int gn = cbase + (q & 1);
                if (gm < M && gn < Nc) {
                    float v = acc[i][j][q];
                    if (BIAS) v += bias[gn];
                    if (ACT == 1) v = fmaxf(v, 0.f);
                    if (OUTM == 1) ((__half*)outv)[(long)gm * Nc + gn] = __float2half_rn(v);
                    else ((float*)outv)[(long)gm * Nc + gn] = v;
                }
            }
        }
    }
}

// ---------------- fused dense chain ----------------
__global__ void __launch_bounds__(256)
k_chain(const float* __restrict__ in, float* __restrict__ out,
        const float* __restrict__ w1, const float* __restrict__ b1,
        const float* __restrict__ w2, const float* __restrict__ b2,
        const float* __restrict__ w3, const float* __restrict__ b3,
        const float* __restrict__ w4, const float* __restrict__ b4) {
    __shared__ float sw1[200], sb1[10], sw2[30], sb2[3], sw3[30], sb3[10], sw4[200], sb4[20];
    int tid = threadIdx.x;
    for (int i = tid; i < 200; i += 256) sw1[i] = w1[i];
    for (int i = tid; i < 10; i += 256) sb1[i] = b1[i];
    for (int i = tid; i < 30; i += 256) sw2[i] = w2[i];
    for (int i = tid; i < 3; i += 256) sb2[i] = b2[i];
    for (int i = tid; i < 30; i += 256) sw3[i] = w3[i];
    for (int i = tid; i < 10; i += 256) sb3[i] = b3[i];
    for (int i = tid; i < 200; i += 256) sw4[i] = w4[i];
    for (int i = tid; i < 20; i += 256) sb4[i] = b4[i];
    __syncthreads();

    int n = blockIdx.x * blockDim.x + tid;
    if (n >= NN) return;
    float h0[20];
    const float4* ip = (const float4*)(in + (long)n * 20);
#pragma unroll
    for (int i = 0; i < 5; i++) {
        float4 v = __ldg(ip + i);
        h0[i * 4 + 0] = v.x; h0[i * 4 + 1] = v.y; h0[i * 4 + 2] = v.z; h0[i * 4 + 3] = v.w;
    }
    float h1[10];
#pragma unroll
    for (int j = 0; j < 10; j++) {
        float s = sb1[j];
#pragma unroll
        for (int i = 0; i < 20; i++) s = fmaf(h0[i], sw1[i * 10 + j], s);
        h1[j] = fmaxf(s, 0.f);
    }
    float z[3];
#pragma unroll
    for (int j = 0; j < 3; j++) {
        float s = sb2[j];
#pragma unroll
        for (int i = 0; i < 10; i++) s = fmaf(h1[i], sw2[i * 3 + j], s);
        z[j] = s;
    }
    float h2[10];
#pragma unroll
    for (int j = 0; j < 10; j++) {
        float s = sb3[j];
#pragma unroll
        for (int i = 0; i < 3; i++) s = fmaf(z[i], sw3[i * 10 + j], s);
        h2[j] = fmaxf(s, 0.f);
    }
    float* op = out + (long)n * 20;
#pragma unroll
    for (int j = 0; j < 20; j++) {
        float s = sb4[j];
#pragma unroll
        for (int i = 0; i < 10; i++) s = fmaf(h2[i], sw4[i * 20 + j], s);
        op[j] = fmaxf(s, 0.f);
    }
}

// ---------------- driver ----------------
template <int ACT, bool BIAS, int OUTM>
static void gemm_h(const __half* Ah, const __half* Bth, const float* b, void* o,
                   int K, int Nc) {
    dim3 g(cdiv(Nc, HBN_T), cdiv(NN, HBM_T));
    k_gemm_h<ACT, BIAS, OUTM><<<g, 256>>>(Ah, Bth, b, o, NN, K, Nc);
}

extern "C" void kernel_launch(void* const* d_in, const int* in_sizes, int n_in,
                              void* d_out, int out_size) {
    const float* x = (const float*)d_in[0];
    const int* ei = (const int*)d_in[1];
    const int* src = ei;
    const int* dst = ei + NE;
    const float* W[12];
    const float* B[12];
    for (int i = 0; i < 12; i++) {
        W[i] = (const float*)d_in[2 + 2 * i];
        B[i] = (const float*)d_in[3 + 2 * i];
    }
    float* bufA; cudaGetSymbolAddress((void**)&bufA, g_bufA);
    float* bufB; cudaGetSymbolAddress((void**)&bufB, g_bufB);
    __half* bufH; cudaGetSymbolAddress((void**)&bufH, g_bufH);
    __half* ah; cudaGetSymbolAddress((void**)&ah, g_ah);
    __half* ah2; cudaGetSymbolAddress((void**)&ah2, g_ah2);
    __half* wth; cudaGetSymbolAddress((void**)&wth, g_wth);
    float* outp = (float*)d_out;

    const int NB = cdiv(NN, 1024);
    // fused weight conversion + cnt init, then CSR build (6 launches)
    k_wconv_init<<<cdiv(NN, 256), 256>>>(W[1], W[2], W[9], W[10]);
    k_count<<<cdiv(NE, 256), 256>>>(dst);
    k_scan1<<<NB, 1024>>>();
    k_scan2<<<1, 128>>>(NB);
    k_scan3_self<<<NB, 1024>>>();
    k_edges<<<cdiv(NE, 256), 256>>>(src, dst);

    const int TPB = 256;
    int blocks80 = cdiv(cdiv(NN, 3) * 32, TPB);   // SUB=10, 3 nodes/warp
    int blocks40 = cdiv(cdiv(NN, 6) * 32, TPB);   // SUB=5, 6 nodes/warp
    int blocks4  = cdiv(cdiv(NN, 8) * 32, TPB);   // C=3, 8 nodes/warp
    int blocksN  = cdiv(NN, TPB);

    // encoder
    k_eg1<<<blocks4, TPB>>>(x, W[0], B[0], ah);                                     // agg+eg1 -> fp16
    gemm_h<0, false, 1>(ah, wth + WOFF_EG2, nullptr, bufH, 160, 80);                // eg2 matmul
    k_aggvh<80, 10, 1, true, 1><<<blocks80, TPB>>>(bufH, B[1], nullptr, ah);        // eg2 agg -> fp16
    gemm_h<0, false, 1>(ah, wth + WOFF_EG3, nullptr, bufH, 80, 40);                 // eg3 matmul
    k_aggvh<40, 5, 1, true, 0><<<blocks40, TPB>>>(bufH, B[2], bufB, nullptr);       // eg3 agg
    k_dense<40, 20, 0, false, false><<<blocksN, TPB>>>(bufB, W[3], nullptr, bufA);  // eg4 matmul
    k_aggv<20, 5, 1, true><<<blocks40, TPB>>>(bufA, B[3], bufB);                    // eg4 agg
    // latent dense chain
    k_chain<<<blocksN, TPB>>>(bufB, bufA, W[4], B[4], W[5], B[5], W[6], B[6], W[7], B[7]);
    // decoder
    k_aggv<20, 5, 0, false><<<blocks40, TPB>>>(bufA, nullptr, bufB);                // dg1 agg
    k_dense<20, 40, 1, true, true><<<blocksN, TPB>>>(bufB, W[8], B[8], bufH);       // dg1 -> fp16
    k_aggvh<40, 5, 0, false, 1><<<blocks40, TPB>>>(bufH, nullptr, nullptr, ah);     // dg2 agg -> fp16
    gemm_h<1, true, 1>(ah, wth + WOFF_DG2, B[9], bufH, 40, 80);                     // dg2
    k_aggvh<80, 10, 0, false, 1><<<blocks80, TPB>>>(bufH, nullptr, nullptr, ah);    // dg3 agg -> fp16
    gemm_h<1, true, 1>(ah, wth + WOFF_DG3, B[10], ah2, 80, 160);                    // dg3 -> fp16
    k_dense_h<160, 3, 0, false><<<blocksN, TPB>>>(ah2, W[11], nullptr, bufB);       // dg4 matmul
    k_agg3<2, true, float><<<blocks4, TPB>>>(bufB, B[11], outp);                    // dg4 agg+tanh
}

// round 13
// speedup vs baseline: 1.0283x; 1.0095x over previous
#include <cuda_runtime.h>
#include <cuda_fp16.h>
#include <cuda_bf16.h>
#include <cstdint>

#define NN 100000
#define NE 1600000
#define NTOT (NE + NN)

// ---------------- scratch (device globals: allocation-free) ----------------
__device__ float  g_bufA[NN * 160];
__device__ float  g_bufB[NN * 160];
__device__ __align__(16) __half g_bufH[NN * 80];
__device__ __align__(16) __half g_ah[NN * 160];    // GEMM A operand (fp16)
__device__ __align__(16) __half g_ah2[NN * 160];   // dg3 fp16 output
__device__ __align__(16) __half g_wth[32000];      // transposed weights [n*K+k] fp16
__device__ int    g_cnt[NN];
__device__ float  g_dis[NN];
__device__ int    g_rowptr[NN + 1];
__device__ int    g_fill[NN];
__device__ int2   g_entries[NTOT];
__device__ int    g_bsums[128];

static inline int cdiv(int a, int b) { return (a + b - 1) / b; }

#define WOFF_EG2 0
#define WOFF_EG3 12800
#define WOFF_DG2 16000
#define WOFF_DG3 19200

#define CP_ASYNC16(saddr, gptr) \
    asm volatile("cp.async.cg.shared.global [%0], [%1], 16;\n" :: "r"(saddr), "l"(gptr))
#define CP_COMMIT() asm volatile("cp.async.commit_group;\n" ::: "memory")
#define CP_WAIT(n)  asm volatile("cp.async.wait_group %0;\n" :: "n"(n) : "memory")

// ---------------- fused: weight convert+transpose AND cnt init ----------------
__global__ void k_wconv_init(const float* __restrict__ W1, const float* __restrict__ W2,
                             const float* __restrict__ W9, const float* __restrict__ W10) {
    int idx = blockIdx.x * blockDim.x + threadIdx.x;
    if (idx < NN) g_cnt[idx] = 1;   // self-loop count
    if (idx >= 32000) return;
    const float* W; int K, Nc, off, li;
    if (idx < 12800)      { W = W1;  K = 160; Nc = 80;  off = WOFF_EG2; li = idx; }
    else if (idx < 16000) { W = W2;  K = 80;  Nc = 40;  off = WOFF_EG3; li = idx - 12800; }
    else if (idx < 19200) { W = W9;  K = 40;  Nc = 80;  off = WOFF_DG2; li = idx - 16000; }
    else                  { W = W10; K = 80;  Nc = 160; off = WOFF_DG3; li = idx - 19200; }
    int k = li / Nc, n = li - k * Nc;
    g_wth[off + n * K + k] = __float2half_rn(W[li]);
}

// ---------------- CSR build ----------------
__global__ void k_count(const int* __restrict__ dst) {
    int e = blockIdx.x * blockDim.x + threadIdx.x;
    if (e < NE) atomicAdd(&g_cnt[dst[e]], 1);
}
__global__ void k_scan1() {
    __shared__ int s[1024];
    int i = blockIdx.x * 1024 + threadIdx.x;
    int v = (i < NN) ? g_cnt[i] : 0;
    if (i < NN) g_dis[i] = rsqrtf((float)v);
    s[threadIdx.x] = v;
    __syncthreads();
    for (int d = 1; d < 1024; d <<= 1) {
        int t = (threadIdx.x >= d) ? s[threadIdx.x - d] : 0;
        __syncthreads();
        s[threadIdx.x] += t;
        __syncthreads();
    }
    if (i < NN) g_rowptr[i + 1] = s[threadIdx.x];
    if (threadIdx.x == 1023) g_bsums[blockIdx.x] = s[1023];
}
// scan3 fused with: own bsums-prefix reduction, self-loop placement, fill init
__global__ void k_scan3_self() {
    __shared__ int swarp[32];
    int t = threadIdx.x;
    // exclusive prefix of block sums for this block: sum of g_bsums[j], j < blockIdx.x
    int v = (t < blockIdx.x) ? g_bsums[t] : 0;   // blockIdx.x <= 97 < 1024
#pragma unroll
    for (int o = 16; o > 0; o >>= 1) v += __shfl_down_sync(0xffffffffu, v, o);
    if ((t & 31) == 0) swarp[t >> 5] = v;
    __syncthreads();
    if (t < 32) {
        int w = swarp[t];
#pragma unroll
        for (int o = 16; o > 0; o >>= 1) w += __shfl_down_sync(0xffffffffu, w, o);
        if (t == 0) swarp[0] = w;
    }
    __syncthreads();
    int offset = swarp[0];

    int i = blockIdx.x * 1024 + t;
    if (i >= NN) return;
    int rp1 = g_rowptr[i + 1] + offset;
    g_rowptr[i + 1] = rp1;
    if (i == 0) g_rowptr[0] = 0;
    int p = rp1 - g_cnt[i];          // final rowptr[i]
    float d = g_dis[i];
    g_entries[p] = make_int2(i, __float_as_int(d * d));
    g_fill[i] = p + 1;
}
__global__ void k_edges(const int* __restrict__ src, const int* __restrict__ dst) {
    int e = blockIdx.x * blockDim.x + threadIdx.x;
    if (e < NE) {
        int s = src[e], d = dst[e];
        int p = atomicAdd(&g_fill[d], 1);
        g_entries[p] = make_int2(s, __float_as_int(g_dis[s] * g_dis[d]));
    }
}

// ---------------- scalar aggregation (C=3) ----------------
template <int ACT, bool BIAS, typename TIN>
__global__ void k_agg3(const TIN* __restrict__ in, const float* __restrict__ bias,
                       float* __restrict__ out) {
    int gwarp = (blockIdx.x * blockDim.x + threadIdx.x) >> 5;
    int lane = threadIdx.x & 31;
    int node = gwarp * 8 + lane / 4;
    int cl = lane & 3;
    if (node >= NN) return;
    int p0 = g_rowptr[node], p1 = g_rowptr[node + 1];
    float acc = 0.f;
    bool act3 = (cl < 3);
    int p = p0;
    for (; p + 4 <= p1; p += 4) {
        int2 e0 = __ldg(&g_entries[p]);
        int2 e1 = __ldg(&g_entries[p + 1]);
        int2 e2 = __ldg(&g_entries[p + 2]);
        int2 e3 = __ldg(&g_entries[p + 3]);
        if (act3) {
            float v0 = (float)__ldg(in + (long)e0.x * 3 + cl);
            float v1 = (float)__ldg(in + (long)e1.x * 3 + cl);
            float v2 = (float)__ldg(in + (long)e2.x * 3 + cl);
            float v3 = (float)__ldg(in + (long)e3.x * 3 + cl);
            acc = fmaf(__int_as_float(e0.y), v0, acc);
            acc = fmaf(__int_as_float(e1.y), v1, acc);
            acc = fmaf(__int_as_float(e2.y), v2, acc);
            acc = fmaf(__int_as_float(e3.y), v3, acc);
        }
    }
    for (; p < p1; p++) {
        int2 e = __ldg(&g_entries[p]);
        if (act3) {
            float v = (float)__ldg(in + (long)e.x * 3 + cl);
            acc = fmaf(__int_as_float(e.y), v, acc);
        }
    }
    if (act3) {
        float v = acc;
        if (BIAS) v += bias[cl];
        if (ACT == 1) v = fmaxf(v, 0.f);
        if (ACT == 2) v = tanhf(v);
        out[(long)node * 3 + cl] = v;
    }
}

// ---------------- fp32 vectorized aggregation, unroll-4 ----------------
template <int C, int SUB, int ACT, bool BIAS>
__global__ void k_aggv(const float* __restrict__ in, const float* __restrict__ bias,
                       float* __restrict__ out) {
    constexpr int NV = C / 4;
    static_assert(NV <= SUB, "SUB too small");
    constexpr int NPW = 32 / SUB;
    int gwarp = (blockIdx.x * blockDim.x + threadIdx.x) >> 5;
    int lane = threadIdx.x & 31;
    int sg = lane / SUB;
    if (sg >= NPW) return;
    int node = gwarp * NPW + sg;
    int vl = lane % SUB;
    if (node >= NN) return;
    int p0 = g_rowptr[node], p1 = g_rowptr[node + 1];
    float4 acc = make_float4(0.f, 0.f, 0.f, 0.f);
    bool active = (vl < NV);
    int p = p0;
    for (; p + 4 <= p1; p += 4) {
        int2 e0 = __ldg(&g_entries[p]);
        int2 e1 = __ldg(&g_entries[p + 1]);
        int2 e2 = __ldg(&g_entries[p + 2]);
        int2 e3 = __ldg(&g_entries[p + 3]);
        if (active) {
            float4 v0 = __ldg((const float4*)(in + (long)e0.x * C) + vl);
            float4 v1 = __ldg((const float4*)(in + (long)e1.x * C) + vl);
            float4 v2 = __ldg((const float4*)(in + (long)e2.x * C) + vl);
            float4 v3 = __ldg((const float4*)(in + (long)e3.x * C) + vl);
            float w0 = __int_as_float(e0.y), w1 = __int_as_float(e1.y);
            float w2 = __int_as_float(e2.y), w3 = __int_as_float(e3.y);
            acc.x = fmaf(w0, v0.x, acc.x); acc.y = fmaf(w0, v0.y, acc.y);
            acc.z = fmaf(w0, v0.z, acc.z); acc.w = fmaf(w0, v0.w, acc.w);
            acc.x = fmaf(w1, v1.x, acc.x); acc.y = fmaf(w1, v1.y, acc.y);
            acc.z = fmaf(w1, v1.z, acc.z); acc.w = fmaf(w1, v1.w, acc.w);
            acc.x = fmaf(w2, v2.x, acc.x); acc.y = fmaf(w2, v2.y, acc.y);
            acc.z = fmaf(w2, v2.z, acc.z); acc.w = fmaf(w2, v2.w, acc.w);
            acc.x = fmaf(w3, v3.x, acc.x); acc.y = fmaf(w3, v3.y, acc.y);
            acc.z = fmaf(w3, v3.z, acc.z); acc.w = fmaf(w3, v3.w, acc.w);
        }
    }
    for (; p < p1; p++) {
        int2 e = __ldg(&g_entries[p]);
        if (active) {
            float w = __int_as_float(e.y);
            float4 v = __ldg((const float4*)(in + (long)e.x * C) + vl);
            acc.x = fmaf(w, v.x, acc.x); acc.y = fmaf(w, v.y, acc.y);
            acc.z = fmaf(w, v.z, acc.z); acc.w = fmaf(w, v.w, acc.w);
        }
    }
    if (active) {
        if (BIAS) {
            float4 bv = __ldg((const float4*)bias + vl);
            acc.x += bv.x; acc.y += bv.y; acc.z += bv.z; acc.w += bv.w;
        }
        if (ACT == 1) {
            acc.x = fmaxf(acc.x, 0.f); acc.y = fmaxf(acc.y, 0.f);
            acc.z = fmaxf(acc.z, 0.f); acc.w = fmaxf(acc.w, 0.f);
        }
        *((float4*)(out + (long)node * C) + vl) = acc;
    }
}

// ---------------- fp16-input aggregation, unroll-4; OM: 0=f32 out, 1=fp16 out ----------------
__device__ __forceinline__ void accum8h(float* acc, int4 h, float w) {
    const __half2* hp = (const __half2*)&h;
#pragma unroll
    for (int i = 0; i < 4; i++) {
        float2 f = __half22float2(hp[i]);
        acc[2 * i]     = fmaf(w, f.x, acc[2 * i]);
        acc[2 * i + 1] = fmaf(w, f.y, acc[2 * i + 1]);
    }
}

template <int C, int SUB, int ACT, bool BIAS, int OM>
__global__ void k_aggvh(const __half* __restrict__ in, const float* __restrict__ bias,
                        float* __restrict__ out, __half* __restrict__ oh) {
    constexpr int NV = C / 8;
    static_assert(NV <= SUB, "SUB too small");
    constexpr int NPW = 32 / SUB;
    int gwarp = (blockIdx.x * blockDim.x + threadIdx.x) >> 5;
    int lane = threadIdx.x & 31;
    int sg = lane / SUB;
    if (sg >= NPW) return;
    int node = gwarp * NPW + sg;
    int vl = lane % SUB;
    if (node >= NN) return;
    int p0 = g_rowptr[node], p1 = g_rowptr[node + 1];
    float acc[8] = {};
    bool active = (vl < NV);
    int p = p0;
    for (; p + 4 <= p1; p += 4) {
        int2 e0 = __ldg(&g_entries[p]);
        int2 e1 = __ldg(&g_entries[p + 1]);
        int2 e2 = __ldg(&g_entries[p + 2]);
        int2 e3 = __ldg(&g_entries[p + 3]);
        if (active) {
            int4 h0 = __ldg((const int4*)(in + (long)e0.x * C) + vl);
            int4 h1 = __ldg((const int4*)(in + (long)e1.x * C) + vl);
            int4 h2 = __ldg((const int4*)(in + (long)e2.x * C) + vl);
            int4 h3 = __ldg((const int4*)(in + (long)e3.x * C) + vl);
            accum8h(acc, h0, __int_as_float(e0.y));
            accum8h(acc, h1, __int_as_float(e1.y));
            accum8h(acc, h2, __int_as_float(e2.y));
            accum8h(acc, h3, __int_as_float(e3.y));
        }
    }
    for (; p < p1; p++) {
        int2 e = __ldg(&g_entries[p]);
        if (active) {
            int4 h = __ldg((const int4*)(in + (long)e.x * C) + vl);
            accum8h(acc, h, __int_as_float(e.y));
        }
    }
    if (active) {
        if (BIAS) {
            const float4* bp = (const float4*)bias + vl * 2;
            float4 b0 = __ldg(bp), b1 = __ldg(bp + 1);
            acc[0] += b0.x; acc[1] += b0.y; acc[2] += b0.z; acc[3] += b0.w;
            acc[4] += b1.x; acc[5] += b1.y; acc[6] += b1.z; acc[7] += b1.w;
        }
        if (ACT == 1) {
#pragma unroll
            for (int i = 0; i < 8; i++) acc[i] = fmaxf(acc[i], 0.f);
        }
        if (OM == 0) {
            float4* op = (float4*)(out + (long)node * C) + vl * 2;
            op[0] = make_float4(acc[0], acc[1], acc[2], acc[3]);
            op[1] = make_float4(acc[4], acc[5], acc[6], acc[7]);
        } else {
            __half hh[8];
#pragma unroll
            for (int i = 0; i < 8; i++) hh[i] = __float2half_rn(acc[i]);
            *((int4*)(oh + (long)node * C) + vl) = *(const int4*)hh;
        }
    }
}

// ---------------- fused eg1 -> fp16 for eg2 GEMM ----------------
__global__ void __launch_bounds__(256)
k_eg1(const float* __restrict__ x, const float* __restrict__ W,
      const float* __restrict__ Bb, __half* __restrict__ oh) {
    __shared__ float sW[480];
    __shared__ float sB[160];
    for (int i = threadIdx.x; i < 480; i += 256) sW[i] = W[i];
    for (int i = threadIdx.x; i < 160; i += 256) sB[i] = Bb[i];
    __syncthreads();
    int gwarp = (blockIdx.x * blockDim.x + threadIdx.x) >> 5;
    int lane = threadIdx.x & 31;
    int nodeBase = gwarp * 8;
    int node = nodeBase + lane / 4;
    int cl = lane & 3;
    float acc = 0.f;
    if (node < NN) {
        int p0 = g_rowptr[node], p1 = g_rowptr[node + 1];
        bool act3 = (cl < 3);
        int p = p0;
        for (; p + 4 <= p1; p += 4) {
            int2 e0 = __ldg(&g_entries[p]);
            int2 e1 = __ldg(&g_entries[p + 1]);
            int2 e2 = __ldg(&g_entries[p + 2]);
            int2 e3 = __ldg(&g_entries[p + 3]);
            if (act3) {
                float v0 = __ldg(x + (long)e0.x * 3 + cl);
                float v1 = __ldg(x + (long)e1.x * 3 + cl);
                float v2 = __ldg(x + (long)e2.x * 3 + cl);
                float v3 = __ldg(x + (long)e3.x * 3 + cl);
                acc = fmaf(__int_as_float(e0.y), v0, acc);
                acc = fmaf(__int_as_float(e1.y), v1, acc);
                acc = fmaf(__int_as_float(e2.y), v2, acc);
                acc = fmaf(__int_as_float(e3.y), v3, acc);
            }
        }
        for (; p < p1; p++) {
            int2 e = __ldg(&g_entries[p]);
            if (act3) {
                float v = __ldg(x + (long)e.x * 3 + cl);
                acc = fmaf(__int_as_float(e.y), v, acc);
            }
        }
    }
#pragma unroll
    for (int j = 0; j < 8; j++) {
        int n2 = nodeBase + j;
        float a0 = __shfl_sync(0xffffffffu, acc, j * 4 + 0);
        float a1 = __shfl_sync(0xffffffffu, acc, j * 4 + 1);
        float a2 = __shfl_sync(0xffffffffu, acc, j * 4 + 2);
        if (n2 >= NN) break;
#pragma unroll
        for (int c0 = 0; c0 < 160; c0 += 32) {
            int c = c0 + lane;
            float v = sB[c];
            v = fmaf(a0, sW[c], v);
            v = fmaf(a1, sW[160 + c], v);
            v = fmaf(a2, sW[320 + c], v);
            v = fmaxf(v, 0.f);
            oh[(long)n2 * 160 + c] = __float2half_rn(v);
        }
    }
}

// ---------------- thread-per-node dense (fp32 input) ----------------
template <int K, int NC, int ACT, bool BIAS, bool OUTH>
__global__ void __launch_bounds__(256)
k_dense(const float* __restrict__ in, const float* __restrict__ W,
        const float* __restrict__ bias, void* __restrict__ outv) {
    __shared__ float sW[K * NC];
    __shared__ float sB[NC];
    for (int i = threadIdx.x; i < K * NC; i += 256) sW[i] = W[i];
    if (BIAS) for (int i = threadIdx.x; i < NC; i += 256) sB[i] = bias[i];
    __syncthreads();
    int n = blockIdx.x * blockDim.x + threadIdx.x;
    if (n >= NN) return;
    float acc[NC];
#pragma unroll
    for (int c = 0; c < NC; c++) acc[c] = BIAS ? sB[c] : 0.f;
    const float4* ip = (const float4*)(in + (long)n * K);
#pragma unroll
    for (int k4 = 0; k4 < K / 4; k4++) {
        float4 v = __ldg(ip + k4);
#pragma unroll
        for (int c = 0; c < NC; c++) {
            acc[c] = fmaf(v.x, sW[(k4 * 4 + 0) * NC + c], acc[c]);
            acc[c] = fmaf(v.y, sW[(k4 * 4 + 1) * NC + c], acc[c]);
            acc[c] = fmaf(v.z, sW[(k4 * 4 + 2) * NC + c], acc[c]);
            acc[c] = fmaf(v.w, sW[(k4 * 4 + 3) * NC + c], acc[c]);
        }
    }
#pragma unroll
    for (int c = 0; c < NC; c++) {
        float v = acc[c];
        if (ACT == 1) v = fmaxf(v, 0.f);
        if (OUTH) ((__half*)outv)[(long)n * NC + c] = __float2half_rn(v);
        else ((float*)outv)[(long)n * NC + c] = v;
    }
}

// ---------------- thread-per-node dense (fp16 input) ----------------
template <int K, int NC, int ACT, bool BIAS>
__global__ void __launch_bounds__(256)
k_dense_h(const __half* __restrict__ in, const float* __restrict__ W,
          const float* __restrict__ bias, float* __restrict__ out) {
    __shared__ float sW[K * NC];
    __shared__ float sB[NC];
    for (int i = threadIdx.x; i < K * NC; i += 256) sW[i] = W[i];
    if (BIAS) for (int i = threadIdx.x; i < NC; i += 256) sB[i] = bias[i];
    __syncthreads();
    int n = blockIdx.x * blockDim.x + threadIdx.x;
    if (n >= NN) return;
    float acc[NC];
#pragma unroll
    for (int c = 0; c < NC; c++) acc[c] = BIAS ? sB[c] : 0.f;
    const int4* ip = (const int4*)(in + (long)n * K);
#pragma unroll
    for (int k8 = 0; k8 < K / 8; k8++) {
        int4 hv = __ldg(ip + k8);
        const __half2* hp = (const __half2*)&hv;
#pragma unroll
        for (int q = 0; q < 4; q++) {
            float2 f = __half22float2(hp[q]);
            int kk = k8 * 8 + q * 2;
#pragma unroll
            for (int c = 0; c < NC; c++) {
                acc[c] = fmaf(f.x, sW[kk * NC + c], acc[c]);
                acc[c] = fmaf(f.y, sW[(kk + 1) * NC + c], acc[c]);
            }
        }
    }
#pragma unroll
    for (int c = 0; c < NC; c++) {
        float v = acc[c];
        if (ACT == 1) v = fmaxf(v, 0.f);
        out[(long)n * NC + c] = v;
    }
}

// ---------------- pure fp16 tensor GEMM, cp.async double-buffered ----------------
__device__ __forceinline__ void mma_f16(float* c, uint32_t a0, uint32_t a1,
                                        uint32_t a2, uint32_t a3,
                                        uint32_t b0, uint32_t b1) {
    asm volatile(
        "mma.sync.aligned.m16n8k16.row.col.f32.f16.f16.f32 "
        "{%0,%1,%2,%3}, {%4,%5,%6,%7}, {%8,%9}, {%0,%1,%2,%3};\n"
        : "+f"(c[0]), "+f"(c[1]), "+f"(c[2]), "+f"(c[3])
        : "r"(a0), "r"(a1), "r"(a2), "r"(a3), "r"(b0), "r"(b1));
}

#define HBM_T 128
#define HBN_T 80
#define HBK_T 32
#define HSA 40
#define HSB 40

template <int ACT, bool BIAS, int OUTM>
__global__ void __launch_bounds__(256, 2)
k_gemm_h(const __half* __restrict__ Ah, const __half* __restrict__ Bth,
         const float* __restrict__ bias, void* __restrict__ outv,
         int M, int K, int Nc) {
    __shared__ __half sAh[2][HBM_T * HSA];
    __shared__ __half sBh[2][HBN_T * HSB];

    int tid = threadIdx.x;
    int wid = tid >> 5;
    int lane = tid & 31;
    int g = lane >> 2;
    int t = lane & 3;
    int wm = wid & 3;
    int wn = wid >> 2;
    int row0 = blockIdx.y * HBM_T;
    int col0 = blockIdx.x * HBN_T;

    float acc[2][5][4];
#pragma unroll
    for (int i = 0; i < 2; i++)
#pragma unroll
        for (int j = 0; j < 5; j++)
#pragma unroll
            for (int q = 0; q < 4; q++) acc[i][j][q] = 0.f;

    const int4 z4 = make_int4(0, 0, 0, 0);

    // tile loader: cp.async for valid 16B groups, zero-store otherwise
    auto load_tile = [&](int buf, int k0) {
#pragma unroll
        for (int it = 0; it < 2; it++) {
            int idx = tid + it * 256;
            int m = idx >> 2, kq = idx & 3;
            int gm = row0 + m;
            int gk = k0 + kq * 8;
            __half* sp = &sAh[buf][m * HSA + kq * 8];
            if ((gm < M) && (gk < K)) {
                uint32_t sa = (uint32_t)__cvta_generic_to_shared(sp);
                CP_ASYNC16(sa, &Ah[(long)gm * K + gk]);
            } else {
                *(int4*)sp = z4;
            }
        }
#pragma unroll
        for (int it = 0; it < 2; it++) {
            int idx = tid + it * 256;
            if (idx < 320) {
                int n = idx >> 2, kq = idx & 3;
                int gk = k0 + kq * 8;
                __half* sp = &sBh[buf][n * HSB + kq * 8];
                if (gk < K) {
                    uint32_t sa = (uint32_t)__cvta_generic_to_shared(sp);
                    CP_ASYNC16(sa, &Bth[(long)(col0 + n) * K + gk]);
                } else {
                    *(int4*)sp = z4;
                }
            }
        }
    };

    int nk = (K + HBK_T - 1) / HBK_T;
    load_tile(0, 0);
    CP_COMMIT();

    for (int kt = 0; kt < nk; kt++) {
        int buf = kt & 1;
        if (kt + 1 < nk) {
            load_tile(buf ^ 1, (kt + 1) * HBK_T);
            CP_COMMIT();
            CP_WAIT(1);     // current tile complete; prefetch may be in flight
        } else {
            CP_WAIT(0);
        }
        __syncthreads();

#pragma unroll
        for (int ks = 0; ks < HBK_T; ks += 16) {
            uint32_t ah[2][4];
#pragma unroll
            for (int i = 0; i < 2; i++) {
                int r0 = wm * 32 + i * 16 + g;
                ah[i][0] = *(const uint32_t*)&sAh[buf][r0 * HSA + ks + 2 * t];
                ah[i][1] = *(const uint32_t*)&sAh[buf][(r0 + 8) * HSA + ks + 2 * t];
                ah[i][2] = *(const uint32_t*)&sAh[buf][r0 * HSA + ks + 2 * t + 8];
                ah[i][3] = *(const uint32_t*)&sAh[buf][(r0 + 8) * HSA + ks + 2 * t + 8];
            }
#pragma unroll
            for (int j = 0; j < 5; j++) {
                int c = wn * 40 + j * 8 + g;
                uint32_t bh0 = *(const uint32_t*)&sBh[buf][c * HSB + ks + 2 * t];
                uint32_t bh1 = *(const uint32_t*)&sBh[buf][c * HSB + ks + 2 * t + 8];
#pragma unroll
                for (int i = 0; i < 2; i++)
                    mma_f16(acc[i][j], ah[i][0], ah[i][1], ah[i][2], ah[i][3], bh0, bh1);
            }
        }
        __syncthreads();
    }

#pragma unroll
    for (int i = 0; i < 2; i++) {
        int rbase = row0 + wm * 32 + i * 16 + g;
#pragma unroll
        for (int j = 0; j < 5; j++) {
            int cbase = col0 + wn * 40 + j * 8 + t * 2;
#pragma unroll
            for (int q = 0; q < 4; q++) {
                int gm = rbase + ((q >= 2) ? 8 : 0);
                int gn = cbase + (q & 1);
                if (gm < M && gn < Nc) {
                    float v = acc[i][j][q];
                    if (BIAS) v += bias[gn];
                    if (ACT == 1) v = fmaxf(v, 0.f);
                    if (OUTM == 1) ((__half*)outv)[(long)gm * Nc + gn] = __float2half_rn(v);
                    else ((float*)outv)[(long)gm * Nc + gn] = v;
                }
            }
        }
    }
}

// ---------------- fused dense chain ----------------
__global__ void __launch_bounds__(256)
k_chain(const float* __restrict__ in, float* __restrict__ out,
        const float* __restrict__ w1, const float* __restrict__ b1,
        const float* __restrict__ w2, const float* __restrict__ b2,
        const float* __restrict__ w3, const float* __restrict__ b3,
        const float* __restrict__ w4, const float* __restrict__ b4) {
    __shared__ float sw1[200], sb1[10], sw2[30], sb2[3], sw3[30], sb3[10], sw4[200], sb4[20];
    int tid = threadIdx.x;
    for (int i = tid; i < 200; i += 256) sw1[i] = w1[i];
    for (int i = tid; i < 10; i += 256) sb1[i] = b1[i];
    for (int i = tid; i < 30; i += 256) sw2[i] = w2[i];
    for (int i = tid; i < 3; i += 256) sb2[i] = b2[i];
    for (int i = tid; i < 30; i += 256) sw3[i] = w3[i];
    for (int i = tid; i < 10; i += 256) sb3[i] = b3[i];
    for (int i = tid; i < 200; i += 256) sw4[i] = w4[i];
    for (int i = tid; i < 20; i += 256) sb4[i] = b4[i];
    __syncthreads();

    int n = blockIdx.x * blockDim.x + tid;
    if (n >= NN) return;
    float h0[20];
    const float4* ip = (const float4*)(in + (long)n * 20);
#pragma unroll
    for (int i = 0; i < 5; i++) {
        float4 v = __ldg(ip + i);
        h0[i * 4 + 0] = v.x; h0[i * 4 + 1] = v.y; h0[i * 4 + 2] = v.z; h0[i * 4 + 3] = v.w;
    }
    float h1[10];
#pragma unroll
    for (int j = 0; j < 10; j++) {
        float s = sb1[j];
#pragma unroll
        for (int i = 0; i < 20; i++) s = fmaf(h0[i], sw1[i * 10 + j], s);
        h1[j] = fmaxf(s, 0.f);
    }
    float z[3];
#pragma unroll
    for (int j = 0; j < 3; j++) {
        float s = sb2[j];
#pragma unroll
        for (int i = 0; i < 10; i++) s = fmaf(h1[i], sw2[i * 3 + j], s);
        z[j] = s;
    }
    float h2[10];
#pragma unroll
    for (int j = 0; j < 10; j++) {
        float s = sb3[j];
#pragma unroll
        for (int i = 0; i < 3; i++) s = fmaf(z[i], sw3[i * 10 + j], s);
        h2[j] = fmaxf(s, 0.f);
    }
    float* op = out + (long)n * 20;
#pragma unroll
    for (int j = 0; j < 20; j++) {
        float s = sb4[j];
#pragma unroll
        for (int i = 0; i < 10; i++) s = fmaf(h2[i], sw4[i * 20 + j], s);
        op[j] = fmaxf(s, 0.f);
    }
}

// ---------------- driver ----------------
template <int ACT, bool BIAS, int OUTM>
static void gemm_h(const __half* Ah, const __half* Bth, const float* b, void* o,
                   int K, int Nc) {
    dim3 g(cdiv(Nc, HBN_T), cdiv(NN, HBM_T));
    k_gemm_h<ACT, BIAS, OUTM><<<g, 256>>>(Ah, Bth, b, o, NN, K, Nc);
}

extern "C" void kernel_launch(void* const* d_in, const int* in_sizes, int n_in,
                              void* d_out, int out_size) {
    const float* x = (const float*)d_in[0];
    const int* ei = (const int*)d_in[1];
    const int* src = ei;
    const int* dst = ei + NE;
    const float* W[12];
    const float* B[12];
    for (int i = 0; i < 12; i++) {
        W[i] = (const float*)d_in[2 + 2 * i];
        B[i] = (const float*)d_in[3 + 2 * i];
    }
    float* bufA; cudaGetSymbolAddress((void**)&bufA, g_bufA);
    float* bufB; cudaGetSymbolAddress((void**)&bufB, g_bufB);
    __half* bufH; cudaGetSymbolAddress((void**)&bufH, g_bufH);
    __half* ah; cudaGetSymbolAddress((void**)&ah, g_ah);
    __half* ah2; cudaGetSymbolAddress((void**)&ah2, g_ah2);
    __half* wth; cudaGetSymbolAddress((void**)&wth, g_wth);
    float* outp = (float*)d_out;

    const int NB = cdiv(NN, 1024);
    // fused weight conversion + cnt init, then CSR build (5 launches)
    k_wconv_init<<<cdiv(NN, 256), 256>>>(W[1], W[2], W[9], W[10]);
    k_count<<<cdiv(NE, 256), 256>>>(dst);
    k_scan1<<<NB, 1024>>>();
    k_scan3_self<<<NB, 1024>>>();
    k_edges<<<cdiv(NE, 256), 256>>>(src, dst);

    const int TPB = 256;
    int blocks80 = cdiv(cdiv(NN, 3) * 32, TPB);   // SUB=10, 3 nodes/warp
    int blocks40 = cdiv(cdiv(NN, 6) * 32, TPB);   // SUB=5, 6 nodes/warp
    int blocks4  = cdiv(cdiv(NN, 8) * 32, TPB);   // C=3, 8 nodes/warp
    int blocksN  = cdiv(NN, TPB);

    // encoder
    k_eg1<<<blocks4, TPB>>>(x, W[0], B[0], ah);                                     // agg+eg1 -> fp16
    gemm_h<0, false, 1>(ah, wth + WOFF_EG2, nullptr, bufH, 160, 80);                // eg2 matmul
    k_aggvh<80, 10, 1, true, 1><<<blocks80, TPB>>>(bufH, B[1], nullptr, ah);        // eg2 agg -> fp16
    gemm_h<0, false, 1>(ah, wth + WOFF_EG3, nullptr, bufH, 80, 40);                 // eg3 matmul
    k_aggvh<40, 5, 1, true, 0><<<blocks40, TPB>>>(bufH, B[2], bufB, nullptr);       // eg3 agg
    k_dense<40, 20, 0, false, false><<<blocksN, TPB>>>(bufB, W[3], nullptr, bufA);  // eg4 matmul
    k_aggv<20, 5, 1, true><<<blocks40, TPB>>>(bufA, B[3], bufB);                    // eg4 agg
    // latent dense chain
    k_chain<<<blocksN, TPB>>>(bufB, bufA, W[4], B[4], W[5], B[5], W[6], B[6], W[7], B[7]);
    // decoder
    k_aggv<20, 5, 0, false><<<blocks40, TPB>>>(bufA, nullptr, bufB);                // dg1 agg
    k_dense<20, 40, 1, true, true><<<blocksN, TPB>>>(bufB, W[8], B[8], bufH);       // dg1 -> fp16
    k_aggvh<40, 5, 0, false, 1><<<blocks40, TPB>>>(bufH, nullptr, nullptr, ah);     // dg2 agg -> fp16
    gemm_h<1, true, 1>(ah, wth + WOFF_DG2, B[9], bufH, 40, 80);                     // dg2
    k_aggvh<80, 10, 0, false, 1><<<blocks80, TPB>>>(bufH, nullptr, nullptr, ah);    // dg3 agg -> fp16
    gemm_h<1, true, 1>(ah, wth + WOFF_DG3, B[10], ah2, 80, 160);                    // dg3 -> fp16
    k_dense_h<160, 3, 0, false><<<blocksN, TPB>>>(ah2, W[11], nullptr, bufB);       // dg4 matmul
    k_agg3<2, true, float><<<blocks4, TPB>>>(bufB, B[11], outp);                    // dg4 agg+tanh
}

// round 14
// speedup vs baseline: 1.1005x; 1.0702x over previous
#include <cuda_runtime.h>
#include <cuda_fp16.h>
#include <cuda_bf16.h>
#include <cstdint>

#define NN 100000
#define NE 1600000
#define NTOT (NE + NN)

// ---------------- scratch (device globals: allocation-free) ----------------
__device__ float  g_bufA[NN * 160];
__device__ float  g_bufB[NN * 160];
__device__ __align__(16) __half g_bufH[NN * 80];
__device__ __align__(16) __half g_ah[NN * 160];    // GEMM A operand (fp16)
__device__ __align__(16) __half g_ah2[NN * 160];   // dg3 fp16 output
__device__ __align__(16) __half g_wth[32000];      // transposed weights [n*K+k] fp16
__device__ int    g_cnt[NN];
__device__ float  g_dis[NN];
__device__ int    g_rowptr[NN + 1];
__device__ int    g_fill[NN];
__device__ int2   g_entries[NTOT];
__device__ int    g_bsums[128];

static inline int cdiv(int a, int b) { return (a + b - 1) / b; }

#define WOFF_EG2 0
#define WOFF_EG3 12800
#define WOFF_DG2 16000
#define WOFF_DG3 19200

#define CP_ASYNC16(saddr, gptr) \
    asm volatile("cp.async.cg.shared.global [%0], [%1], 16;\n" :: "r"(saddr), "l"(gptr))
#define CP_COMMIT() asm volatile("cp.async.commit_group;\n" ::: "memory")
#define CP_WAIT(n)  asm volatile("cp.async.wait_group %0;\n" :: "n"(n) : "memory")

// ---------------- fused: weight convert+transpose AND cnt init ----------------
__global__ void k_wconv_init(const float* __restrict__ W1, const float* __restrict__ W2,
                             const float* __restrict__ W9, const float* __restrict__ W10) {
    int idx = blockIdx.x * blockDim.x + threadIdx.x;
    if (idx < NN) g_cnt[idx] = 1;   // self-loop count
    if (idx >= 32000) return;
    const float* W; int K, Nc, off, li;
    if (idx < 12800)      { W = W1;  K = 160; Nc = 80;  off = WOFF_EG2; li = idx; }
    else if (idx < 16000) { W = W2;  K = 80;  Nc = 40;  off = WOFF_EG3; li = idx - 12800; }
    else if (idx < 19200) { W = W9;  K = 40;  Nc = 80;  off = WOFF_DG2; li = idx - 16000; }
    else                  { W = W10; K = 80;  Nc = 160; off = WOFF_DG3; li = idx - 19200; }
    int k = li / Nc, n = li - k * Nc;
    g_wth[off + n * K + k] = __float2half_rn(W[li]);
}

// ---------------- CSR build ----------------
__global__ void k_count(const int* __restrict__ dst) {
    int e = blockIdx.x * blockDim.x + threadIdx.x;
    if (e < NE) atomicAdd(&g_cnt[dst[e]], 1);
}
__global__ void k_scan1() {
    __shared__ int s[1024];
    int i = blockIdx.x * 1024 + threadIdx.x;
    int v = (i < NN) ? g_cnt[i] : 0;
    if (i < NN) g_dis[i] = rsqrtf((float)v);
    s[threadIdx.x] = v;
    __syncthreads();
    for (int d = 1; d < 1024; d <<= 1) {
        int t = (threadIdx.x >= d) ? s[threadIdx.x - d] : 0;
        __syncthreads();
        s[threadIdx.x] += t;
        __syncthreads();
    }
    if (i < NN) g_rowptr[i + 1] = s[threadIdx.x];
    if (threadIdx.x == 1023) g_bsums[blockIdx.x] = s[1023];
}
// scan3 fused with: own bsums-prefix reduction, self-loop placement, fill init
__global__ void k_scan3_self() {
    __shared__ int swarp[32];
    int t = threadIdx.x;
    int v = (t < blockIdx.x) ? g_bsums[t] : 0;
#pragma unroll
    for (int o = 16; o > 0; o >>= 1) v += __shfl_down_sync(0xffffffffu, v, o);
    if ((t & 31) == 0) swarp[t >> 5] = v;
    __syncthreads();
    if (t < 32) {
        int w = swarp[t];
#pragma unroll
        for (int o = 16; o > 0; o >>= 1) w += __shfl_down_sync(0xffffffffu, w, o);
        if (t == 0) swarp[0] = w;
    }
    __syncthreads();
    int offset = swarp[0];

    int i = blockIdx.x * 1024 + t;
    if (i >= NN) return;
    int rp1 = g_rowptr[i + 1] + offset;
    g_rowptr[i + 1] = rp1;
    if (i == 0) g_rowptr[0] = 0;
    int p = rp1 - g_cnt[i];
    float d = g_dis[i];
    g_entries[p] = make_int2(i, __float_as_int(d * d));
    g_fill[i] = p + 1;
}
__global__ void k_edges(const int* __restrict__ src, const int* __restrict__ dst) {
    int e = blockIdx.x * blockDim.x + threadIdx.x;
    if (e < NE) {
        int s = src[e], d = dst[e];
        int p = atomicAdd(&g_fill[d], 1);
        g_entries[p] = make_int2(s, __float_as_int(g_dis[s] * g_dis[d]));
    }
}

// ---------------- scalar aggregation (C=3) ----------------
template <int ACT, bool BIAS, typename TIN>
__global__ void k_agg3(const TIN* __restrict__ in, const float* __restrict__ bias,
                       float* __restrict__ out) {
    int gwarp = (blockIdx.x * blockDim.x + threadIdx.x) >> 5;
    int lane = threadIdx.x & 31;
    int node = gwarp * 8 + lane / 4;
    int cl = lane & 3;
    if (node >= NN) return;
    int p0 = g_rowptr[node], p1 = g_rowptr[node + 1];
    float acc = 0.f;
    bool act3 = (cl < 3);
    int p = p0;
    for (; p + 4 <= p1; p += 4) {
        int2 e0 = __ldg(&g_entries[p]);
        int2 e1 = __ldg(&g_entries[p + 1]);
        int2 e2 = __ldg(&g_entries[p + 2]);
        int2 e3 = __ldg(&g_entries[p + 3]);
        if (act3) {
            float v0 = (float)__ldg(in + (long)e0.x * 3 + cl);
            float v1 = (float)__ldg(in + (long)e1.x * 3 + cl);
            float v2 = (float)__ldg(in + (long)e2.x * 3 + cl);
            float v3 = (float)__ldg(in + (long)e3.x * 3 + cl);
            acc = fmaf(__int_as_float(e0.y), v0, acc);
            acc = fmaf(__int_as_float(e1.y), v1, acc);
            acc = fmaf(__int_as_float(e2.y), v2, acc);
            acc = fmaf(__int_as_float(e3.y), v3, acc);
        }
    }
    for (; p < p1; p++) {
        int2 e = __ldg(&g_entries[p]);
        if (act3) {
            float v = (float)__ldg(in + (long)e.x * 3 + cl);
            acc = fmaf(__int_as_float(e.y), v, acc);
        }
    }
    if (act3) {
        float v = acc;
        if (BIAS) v += bias[cl];
        if (ACT == 1) v = fmaxf(v, 0.f);
        if (ACT == 2) v = tanhf(v);
        out[(long)node * 3 + cl] = v;
    }
}

// ---------------- fp32 vectorized aggregation, unroll-4 ----------------
template <int C, int SUB, int ACT, bool BIAS>
__global__ void k_aggv(const float* __restrict__ in, const float* __restrict__ bias,
                       float* __restrict__ out) {
    constexpr int NV = C / 4;
    static_assert(NV <= SUB, "SUB too small");
    constexpr int NPW = 32 / SUB;
    int gwarp = (blockIdx.x * blockDim.x + threadIdx.x) >> 5;
    int lane = threadIdx.x & 31;
    int sg = lane / SUB;
    if (sg >= NPW) return;
    int node = gwarp * NPW + sg;
    int vl = lane % SUB;
    if (node >= NN) return;
    int p0 = g_rowptr[node], p1 = g_rowptr[node + 1];
    float4 acc = make_float4(0.f, 0.f, 0.f, 0.f);
    bool active = (vl < NV);
    int p = p0;
    for (; p + 4 <= p1; p += 4) {
        int2 e0 = __ldg(&g_entries[p]);
        int2 e1 = __ldg(&g_entries[p + 1]);
        int2 e2 = __ldg(&g_entries[p + 2]);
        int2 e3 = __ldg(&g_entries[p + 3]);
        if (active) {
            float4 v0 = __ldg((const float4*)(in + (long)e0.x * C) + vl);
            float4 v1 = __ldg((const float4*)(in + (long)e1.x * C) + vl);
            float4 v2 = __ldg((const float4*)(in + (long)e2.x * C) + vl);
            float4 v3 = __ldg((const float4*)(in + (long)e3.x * C) + vl);
            float w0 = __int_as_float(e0.y), w1 = __int_as_float(e1.y);
            float w2 = __int_as_float(e2.y), w3 = __int_as_float(e3.y);
            acc.x = fmaf(w0, v0.x, acc.x); acc.y = fmaf(w0, v0.y, acc.y);
            acc.z = fmaf(w0, v0.z, acc.z); acc.w = fmaf(w0, v0.w, acc.w);
            acc.x = fmaf(w1, v1.x, acc.x); acc.y = fmaf(w1, v1.y, acc.y);
            acc.z = fmaf(w1, v1.z, acc.z); acc.w = fmaf(w1, v1.w, acc.w);
            acc.x = fmaf(w2, v2.x, acc.x); acc.y = fmaf(w2, v2.y, acc.y);
            acc.z = fmaf(w2, v2.z, acc.z); acc.w = fmaf(w2, v2.w, acc.w);
            acc.x = fmaf(w3, v3.x, acc.x); acc.y = fmaf(w3, v3.y, acc.y);
            acc.z = fmaf(w3, v3.z, acc.z); acc.w = fmaf(w3, v3.w, acc.w);
        }
    }
    for (; p < p1; p++) {
        int2 e = __ldg(&g_entries[p]);
        if (active) {
            float w = __int_as_float(e.y);
            float4 v = __ldg((const float4*)(in + (long)e.x * C) + vl);
            acc.x = fmaf(w, v.x, acc.x); acc.y = fmaf(w, v.y, acc.y);
            acc.z = fmaf(w, v.z, acc.z); acc.w = fmaf(w, v.w, acc.w);
        }
    }
    if (active) {
        if (BIAS) {
            float4 bv = __ldg((const float4*)bias + vl);
            acc.x += bv.x; acc.y += bv.y; acc.z += bv.z; acc.w += bv.w;
        }
        if (ACT == 1) {
            acc.x = fmaxf(acc.x, 0.f); acc.y = fmaxf(acc.y, 0.f);
            acc.z = fmaxf(acc.z, 0.f); acc.w = fmaxf(acc.w, 0.f);
        }
        *((float4*)(out + (long)node * C) + vl) = acc;
    }
}

// ---------------- fp16-input aggregation, unroll-4; OM: 0=f32 out, 1=fp16 out ----------------
__device__ __forceinline__ void accum8h(float* acc, int4 h, float w) {
    const __half2* hp = (const __half2*)&h;
#pragma unroll
    for (int i = 0; i < 4; i++) {
        float2 f = __half22float2(hp[i]);
        acc[2 * i]     = fmaf(w, f.x, acc[2 * i]);
        acc[2 * i + 1] = fmaf(w, f.y, acc[2 * i + 1]);
    }
}

template <int C, int SUB, int ACT, bool BIAS, int OM>
__global__ void k_aggvh(const __half* __restrict__ in, const float* __restrict__ bias,
                        float* __restrict__ out, __half* __restrict__ oh) {
    constexpr int NV = C / 8;
    static_assert(NV <= SUB, "SUB too small");
    constexpr int NPW = 32 / SUB;
    int gwarp = (blockIdx.x * blockDim.x + threadIdx.x) >> 5;
    int lane = threadIdx.x & 31;
    int sg = lane / SUB;
    if (sg >= NPW) return;
    int node = gwarp * NPW + sg;
    int vl = lane % SUB;
    if (node >= NN) return;
    int p0 = g_rowptr[node], p1 = g_rowptr[node + 1];
    float acc[8] = {};
    bool active = (vl < NV);
    int p = p0;
    for (; p + 4 <= p1; p += 4) {
        int2 e0 = __ldg(&g_entries[p]);
        int2 e1 = __ldg(&g_entries[p + 1]);
        int2 e2 = __ldg(&g_entries[p + 2]);
        int2 e3 = __ldg(&g_entries[p + 3]);
        if (active) {
            int4 h0 = __ldg((const int4*)(in + (long)e0.x * C) + vl);
            int4 h1 = __ldg((const int4*)(in + (long)e1.x * C) + vl);
            int4 h2 = __ldg((const int4*)(in + (long)e2.x * C) + vl);
            int4 h3 = __ldg((const int4*)(in + (long)e3.x * C) + vl);
            accum8h(acc, h0, __int_as_float(e0.y));
            accum8h(acc, h1, __int_as_float(e1.y));
            accum8h(acc, h2, __int_as_float(e2.y));
            accum8h(acc, h3, __int_as_float(e3.y));
        }
    }
    for (; p < p1; p++) {
        int2 e = __ldg(&g_entries[p]);
        if (active) {
            int4 h = __ldg((const int4*)(in + (long)e.x * C) + vl);
            accum8h(acc, h, __int_as_float(e.y));
        }
    }
    if (active) {
        if (BIAS) {
            const float4* bp = (const float4*)bias + vl * 2;
            float4 b0 = __ldg(bp), b1 = __ldg(bp + 1);
            acc[0] += b0.x; acc[1] += b0.y; acc[2] += b0.z; acc[3] += b0.w;
            acc[4] += b1.x; acc[5] += b1.y; acc[6] += b1.z; acc[7] += b1.w;
        }
        if (ACT == 1) {
#pragma unroll
            for (int i = 0; i < 8; i++) acc[i] = fmaxf(acc[i], 0.f);
        }
        if (OM == 0) {
            float4* op = (float4*)(out + (long)node * C) + vl * 2;
            op[0] = make_float4(acc[0], acc[1], acc[2], acc[3]);
            op[1] = make_float4(acc[4], acc[5], acc[6], acc[7]);
        } else {
            __half hh[8];
#pragma unroll
            for (int i = 0; i < 8; i++) hh[i] = __float2half_rn(acc[i]);
            *((int4*)(oh + (long)node * C) + vl) = *(const int4*)hh;
        }
    }
}

// ---- FUSED: eg3 agg (C=40 fp16-in, bias+relu) + eg4 matmul 40->20 (f32 out) ----
__global__ void __launch_bounds__(256)
k_eg3mm(const __half* __restrict__ in, const float* __restrict__ bias,
        const float* __restrict__ W3, float* __restrict__ out) {
    __shared__ float sW[800];   // W3: 40x20
    __shared__ float sB[40];
    for (int i = threadIdx.x; i < 800; i += 256) sW[i] = W3[i];
    for (int i = threadIdx.x; i < 40; i += 256) sB[i] = bias[i];
    __syncthreads();

    constexpr int C = 40, SUB = 5, NPW = 6;
    int gwarp = (blockIdx.x * blockDim.x + threadIdx.x) >> 5;
    int lane = threadIdx.x & 31;
    int sg = lane / SUB;
    if (sg >= NPW) return;            // lanes 30,31
    int node = gwarp * NPW + sg;
    int vl = lane % SUB;
    bool valid = (node < NN);
    int p0 = 0, p1 = 0;
    if (valid) { p0 = g_rowptr[node]; p1 = g_rowptr[node + 1]; }
    float acc[8] = {};
    int p = p0;
    for (; p + 4 <= p1; p += 4) {
        int2 e0 = __ldg(&g_entries[p]);
        int2 e1 = __ldg(&g_entries[p + 1]);
        int2 e2 = __ldg(&g_entries[p + 2]);
        int2 e3 = __ldg(&g_entries[p + 3]);
        int4 h0 = __ldg((const int4*)(in + (long)e0.x * C) + vl);
        int4 h1 = __ldg((const int4*)(in + (long)e1.x * C) + vl);
        int4 h2 = __ldg((const int4*)(in + (long)e2.x * C) + vl);
        int4 h3 = __ldg((const int4*)(in + (long)e3.x * C) + vl);
        accum8h(acc, h0, __int_as_float(e0.y));
        accum8h(acc, h1, __int_as_float(e1.y));
        accum8h(acc, h2, __int_as_float(e2.y));
        accum8h(acc, h3, __int_as_float(e3.y));
    }
    for (; p < p1; p++) {
        int2 e = __ldg(&g_entries[p]);
        int4 h = __ldg((const int4*)(in + (long)e.x * C) + vl);
        accum8h(acc, h, __int_as_float(e.y));
    }
    // bias + relu (eg3 epilogue)
#pragma unroll
    for (int i = 0; i < 8; i++) acc[i] = fmaxf(acc[i] + sB[vl * 8 + i], 0.f);

    // matmul 40->20: each lane computes cols vl*4..vl*4+3
    float o[4] = {0.f, 0.f, 0.f, 0.f};
    int base = sg * SUB;
#pragma unroll
    for (int k = 0; k < 40; k++) {
        float val = __shfl_sync(0x3fffffffu, acc[k & 7], base + (k >> 3));
#pragma unroll
        for (int j = 0; j < 4; j++)
            o[j] = fmaf(val, sW[k * 20 + vl * 4 + j], o[j]);
    }
    if (valid)
        *(float4*)(out + (long)node * 20 + vl * 4) = make_float4(o[0], o[1], o[2], o[3]);
}

// ---- FUSED: dg1 agg (C=20 f32-in) + dg1 dense 20->40 (+bias, relu, fp16 out) ----
__global__ void __launch_bounds__(256)
k_dg1mm(const float* __restrict__ in, const float* __restrict__ W8,
        const float* __restrict__ B8, __half* __restrict__ out) {
    __shared__ float sW[800];   // W8: 20x40
    __shared__ float sB[40];
    for (int i = threadIdx.x; i < 800; i += 256) sW[i] = W8[i];
    for (int i = threadIdx.x; i < 40; i += 256) sB[i] = B8[i];
    __syncthreads();

    constexpr int C = 20, SUB = 5, NPW = 6;
    int gwarp = (blockIdx.x * blockDim.x + threadIdx.x) >> 5;
    int lane = threadIdx.x & 31;
    int sg = lane / SUB;
    if (sg >= NPW) return;
    int node = gwarp * NPW + sg;
    int vl = lane % SUB;
    bool valid = (node < NN);
    int p0 = 0, p1 = 0;
    if (valid) { p0 = g_rowptr[node]; p1 = g_rowptr[node + 1]; }
    float4 acc = make_float4(0.f, 0.f, 0.f, 0.f);
    int p = p0;
    for (; p + 4 <= p1; p += 4) {
        int2 e0 = __ldg(&g_entries[p]);
        int2 e1 = __ldg(&g_entries[p + 1]);
        int2 e2 = __ldg(&g_entries[p + 2]);
        int2 e3 = __ldg(&g_entries[p + 3]);
        float4 v0 = __ldg((const float4*)(in + (long)e0.x * C) + vl);
        float4 v1 = __ldg((const float4*)(in + (long)e1.x * C) + vl);
        float4 v2 = __ldg((const float4*)(in + (long)e2.x * C) + vl);
        float4 v3 = __ldg((const float4*)(in + (long)e3.x * C) + vl);
        float w0 = __int_as_float(e0.y), w1 = __int_as_float(e1.y);
        float w2 = __int_as_float(e2.y), w3 = __int_as_float(e3.y);
        acc.x = fmaf(w0, v0.x, acc.x); acc.y = fmaf(w0, v0.y, acc.y);
        acc.z = fmaf(w0, v0.z, acc.z); acc.w = fmaf(w0, v0.w, acc.w);
        acc.x = fmaf(w1, v1.x, acc.x); acc.y = fmaf(w1, v1.y, acc.y);
        acc.z = fmaf(w1, v1.z, acc.z); acc.w = fmaf(w1, v1.w, acc.w);
        acc.x = fmaf(w2, v2.x, acc.x); acc.y = fmaf(w2, v2.y, acc.y);
        acc.z = fmaf(w2, v2.z, acc.z); acc.w = fmaf(w2, v2.w, acc.w);
        acc.x = fmaf(w3, v3.x, acc.x); acc.y = fmaf(w3, v3.y, acc.y);
        acc.z = fmaf(w3, v3.z, acc.z); acc.w = fmaf(w3, v3.w, acc.w);
    }
    for (; p < p1; p++) {
        int2 e = __ldg(&g_entries[p]);
        float w = __int_as_float(e.y);
        float4 v = __ldg((const float4*)(in + (long)e.x * C) + vl);
        acc.x = fmaf(w, v.x, acc.x); acc.y = fmaf(w, v.y, acc.y);
        acc.z = fmaf(w, v.z, acc.z); acc.w = fmaf(w, v.w, acc.w);
    }
    float ar[4] = {acc.x, acc.y, acc.z, acc.w};

    // dense 20->40: each lane computes cols vl*8..vl*8+7
    float o[8];
#pragma unroll
    for (int j = 0; j < 8; j++) o[j] = sB[vl * 8 + j];
    int base = sg * SUB;
#pragma unroll
    for (int k = 0; k < 20; k++) {
        float val = __shfl_sync(0x3fffffffu, ar[k & 3], base + (k >> 2));
#pragma unroll
        for (int j = 0; j < 8; j++)
            o[j] = fmaf(val, sW[k * 40 + vl * 8 + j], o[j]);
    }
    if (valid) {
        __half hh[8];
#pragma unroll
        for (int j = 0; j < 8; j++) hh[j] = __float2half_rn(fmaxf(o[j], 0.f));
        *(int4*)(out + (long)node * 40 + vl * 8) = *(const int4*)hh;
    }
}

// ---------------- fused eg1 -> fp16 for eg2 GEMM ----------------
__global__ void __launch_bounds__(256)
k_eg1(const float* __restrict__ x, const float* __restrict__ W,
      const float* __restrict__ Bb, __half* __restrict__ oh) {
    __shared__ float sW[480];
    __shared__ float sB[160];
    for (int i = threadIdx.x; i < 480; i += 256) sW[i] = W[i];
    for (int i = threadIdx.x; i < 160; i += 256) sB[i] = Bb[i];
    __syncthreads();
    int gwarp = (blockIdx.x * blockDim.x + threadIdx.x) >> 5;
    int lane = threadIdx.x & 31;
    int nodeBase = gwarp * 8;
    int node = nodeBase + lane / 4;
    int cl = lane & 3;
    float acc = 0.f;
    if (node < NN) {
        int p0 = g_rowptr[node], p1 = g_rowptr[node + 1];
        bool act3 = (cl < 3);
        int p = p0;
        for (; p + 4 <= p1; p += 4) {
            int2 e0 = __ldg(&g_entries[p]);
            int2 e1 = __ldg(&g_entries[p + 1]);
            int2 e2 = __ldg(&g_entries[p + 2]);
            int2 e3 = __ldg(&g_entries[p + 3]);
            if (act3) {
                float v0 = __ldg(x + (long)e0.x * 3 + cl);
                float v1 = __ldg(x + (long)e1.x * 3 + cl);
                float v2 = __ldg(x + (long)e2.x * 3 + cl);
                float v3 = __ldg(x + (long)e3.x * 3 + cl);
                acc = fmaf(__int_as_float(e0.y), v0, acc);
                acc = fmaf(__int_as_float(e1.y), v1, acc);
                acc = fmaf(__int_as_float(e2.y), v2, acc);
                acc = fmaf(__int_as_float(e3.y), v3, acc);
            }
        }
        for (; p < p1; p++) {
            int2 e = __ldg(&g_entries[p]);
            if (act3) {
                float v = __ldg(x + (long)e.x * 3 + cl);
                acc = fmaf(__int_as_float(e.y), v, acc);
            }
        }
    }
#pragma unroll
    for (int j = 0; j < 8; j++) {
        int n2 = nodeBase + j;
        float a0 = __shfl_sync(0xffffffffu, acc, j * 4 + 0);
        float a1 = __shfl_sync(0xffffffffu, acc, j * 4 + 1);
        float a2 = __shfl_sync(0xffffffffu, acc, j * 4 + 2);
        if (n2 >= NN) break;
#pragma unroll
        for (int c0 = 0; c0 < 160; c0 += 32) {
            int c = c0 + lane;
            float v = sB[c];
            v = fmaf(a0, sW[c], v);
            v = fmaf(a1, sW[160 + c], v);
            v = fmaf(a2, sW[320 + c], v);
            v = fmaxf(v, 0.f);
            oh[(long)n2 * 160 + c] = __float2half_rn(v);
        }
    }
}

// ---------------- thread-per-node dense (fp16 input) ----------------
template <int K, int NC, int ACT, bool BIAS>
__global__ void __launch_bounds__(256)
k_dense_h(const __half* __restrict__ in, const float* __restrict__ W,
          const float* __restrict__ bias, float* __restrict__ out) {
    __shared__ float sW[K * NC];
    __shared__ float sB[NC];
    for (int i = threadIdx.x; i < K * NC; i += 256) sW[i] = W[i];
    if (BIAS) for (int i = threadIdx.x; i < NC; i += 256) sB[i] = bias[i];
    __syncthreads();
    int n = blockIdx.x * blockDim.x + threadIdx.x;
    if (n >= NN) return;
    float acc[NC];
#pragma unroll
    for (int c = 0; c < NC; c++) acc[c] = BIAS ? sB[c] : 0.f;
    const int4* ip = (const int4*)(in + (long)n * K);
#pragma unroll
    for (int k8 = 0; k8 < K / 8; k8++) {
        int4 hv = __ldg(ip + k8);
        const __half2* hp = (const __half2*)&hv;
#pragma unroll
        for (int q = 0; q < 4; q++) {
            float2 f = __half22float2(hp[q]);
            int kk = k8 * 8 + q * 2;
#pragma unroll
            for (int c = 0; c < NC; c++) {
                acc[c] = fmaf(f.x, sW[kk * NC + c], acc[c]);
                acc[c] = fmaf(f.y, sW[(kk + 1) * NC + c], acc[c]);
            }
        }
    }
#pragma unroll
    for (int c = 0; c < NC; c++) {
        float v = acc[c];
        if (ACT == 1) v = fmaxf(v, 0.f);
        out[(long)n * NC + c] = v;
    }
}

// ---------------- pure fp16 tensor GEMM, cp.async double-buffered ----------------
__device__ __forceinline__ void mma_f16(float* c, uint32_t a0, uint32_t a1,
                                        uint32_t a2, uint32_t a3,
                                        uint32_t b0, uint32_t b1) {
    asm volatile(
        "mma.sync.aligned.m16n8k16.row.col.f32.f16.f16.f32 "
        "{%0,%1,%2,%3}, {%4,%5,%6,%7}, {%8,%9}, {%0,%1,%2,%3};\n"
        : "+f"(c[0]), "+f"(c[1]), "+f"(c[2]), "+f"(c[3])
        : "r"(a0), "r"(a1), "r"(a2), "r"(a3), "r"(b0), "r"(b1));
}

#define HBM_T 128
#define HBN_T 80
#define HBK_T 32
#define HSA 40
#define HSB 40

template <int ACT, bool BIAS, int OUTM>
__global__ void __launch_bounds__(256, 2)
k_gemm_h(const __half* __restrict__ Ah, const __half* __restrict__ Bth,
         const float* __restrict__ bias, void* __restrict__ outv,
         int M, int K, int Nc) {
    __shared__ __half sAh[2][HBM_T * HSA];
    __shared__ __half sBh[2][HBN_T * HSB];

    int tid = threadIdx.x;
    int wid = tid >> 5;
    int lane = tid & 31;
    int g = lane >> 2;
    int t = lane & 3;
    int wm = wid & 3;
    int wn = wid >> 2;
    int row0 = blockIdx.y * HBM_T;
    int col0 = blockIdx.x * HBN_T;

    float acc[2][5][4];
#pragma unroll
    for (int i = 0; i < 2; i++)
#pragma unroll
        for (int j = 0; j < 5; j++)
#pragma unroll
            for (int q = 0; q < 4; q++) acc[i][j][q] = 0.f;

    const int4 z4 = make_int4(0, 0, 0, 0);

    auto load_tile = [&](int buf, int k0) {
#pragma unroll
        for (int it = 0; it < 2; it++) {
            int idx = tid + it * 256;
            int m = idx >> 2, kq = idx & 3;
            int gm = row0 + m;
            int gk = k0 + kq * 8;
            __half* sp = &sAh[buf][m * HSA + kq * 8];
            if ((gm < M) && (gk < K)) {
                uint32_t sa = (uint32_t)__cvta_generic_to_shared(sp);
                CP_ASYNC16(sa, &Ah[(long)gm * K + gk]);
            } else {
                *(int4*)sp = z4;
            }
        }
#pragma unroll
        for (int it = 0; it < 2; it++) {
            int idx = tid + it * 256;
            if (idx < 320) {
                int n = idx >> 2, kq = idx & 3;
                int gk = k0 + kq * 8;
                __half* sp = &sBh[buf][n * HSB + kq * 8];
                if (gk < K) {
                    uint32_t sa = (uint32_t)__cvta_generic_to_shared(sp);
                    CP_ASYNC16(sa, &Bth[(long)(col0 + n) * K + gk]);
                } else {
                    *(int4*)sp = z4;
                }
            }
        }
    };

    int nk = (K + HBK_T - 1) / HBK_T;
    load_tile(0, 0);
    CP_COMMIT();

    for (int kt = 0; kt < nk; kt++) {
        int buf = kt & 1;
        if (kt + 1 < nk) {
            load_tile(buf ^ 1, (kt + 1) * HBK_T);
            CP_COMMIT();
            CP_WAIT(1);
        } else {
            CP_WAIT(0);
        }
        __syncthreads();

#pragma unroll
        for (int ks = 0; ks < HBK_T; ks += 16) {
            uint32_t ah[2][4];
#pragma unroll
            for (int i = 0; i < 2; i++) {
                int r0 = wm * 32 + i * 16 + g;
                ah[i][0] = *(const uint32_t*)&sAh[buf][r0 * HSA + ks + 2 * t];
                ah[i][1] = *(const uint32_t*)&sAh[buf][(r0 + 8) * HSA + ks + 2 * t];
                ah[i][2] = *(const uint32_t*)&sAh[buf][r0 * HSA + ks + 2 * t + 8];
                ah[i][3] = *(const uint32_t*)&sAh[buf][(r0 + 8) * HSA + ks + 2 * t + 8];
            }
#pragma unroll
            for (int j = 0; j < 5; j++) {
                int c = wn * 40 + j * 8 + g;
                uint32_t bh0 = *(const uint32_t*)&sBh[buf][c * HSB + ks + 2 * t];
                uint32_t bh1 = *(const uint32_t*)&sBh[buf][c * HSB + ks + 2 * t + 8];
#pragma unroll
                for (int i = 0; i < 2; i++)
                    mma_f16(acc[i][j], ah[i][0], ah[i][1], ah[i][2], ah[i][3], bh0, bh1);
            }
        }
        __syncthreads();
    }

#pragma unroll
    for (int i = 0; i < 2; i++) {
        int rbase = row0 + wm * 32 + i * 16 + g;
#pragma unroll
        for (int j = 0; j < 5; j++) {
            int cbase = col0 + wn * 40 + j * 8 + t * 2;
#pragma unroll
            for (int q = 0; q < 4; q++) {
                int gm = rbase + ((q >= 2) ? 8 : 0);
                int gn = cbase + (q & 1);
                if (gm < M && gn < Nc) {
                    float v = acc[i][j][q];
                    if (BIAS) v += bias[gn];
                    if (ACT == 1) v = fmaxf(v, 0.f);
                    if (OUTM == 1) ((__half*)outv)[(long)gm * Nc + gn] = __float2half_rn(v);
                    else ((float*)outv)[(long)gm * Nc + gn] = v;
                }
            }
        }
    }
}

// ---------------- fused dense chain ----------------
__global__ void __launch_bounds__(256)
k_chain(const float* __restrict__ in, float* __restrict__ out,
        const float* __restrict__ w1, const float* __restrict__ b1,
        const float* __restrict__ w2, const float* __restrict__ b2,
        const float* __restrict__ w3, const float* __restrict__ b3,
        const float* __restrict__ w4, const float* __restrict__ b4) {
    __shared__ float sw1[200], sb1[10], sw2[30], sb2[3], sw3[30], sb3[10], sw4[200], sb4[20];
    int tid = threadIdx.x;
    for (int i = tid; i < 200; i += 256) sw1[i] = w1[i];
    for (int i = tid; i < 10; i += 256) sb1[i] = b1[i];
    for (int i = tid; i < 30; i += 256) sw2[i] = w2[i];
    for (int i = tid; i < 3; i += 256) sb2[i] = b2[i];
    for (int i = tid; i < 30; i += 256) sw3[i] = w3[i];
    for (int i = tid; i < 10; i += 256) sb3[i] = b3[i];
    for (int i = tid; i < 200; i += 256) sw4[i] = w4[i];
    for (int i = tid; i < 20; i += 256) sb4[i] = b4[i];
    __syncthreads();

    int n = blockIdx.x * blockDim.x + tid;
    if (n >= NN) return;
    float h0[20];
    const float4* ip = (const float4*)(in + (long)n * 20);
#pragma unroll
    for (int i = 0; i < 5; i++) {
        float4 v = __ldg(ip + i);
        h0[i * 4 + 0] = v.x; h0[i * 4 + 1] = v.y; h0[i * 4 + 2] = v.z; h0[i * 4 + 3] = v.w;
    }
    float h1[10];
#pragma unroll
    for (int j = 0; j < 10; j++) {
        float s = sb1[j];
#pragma unroll
        for (int i = 0; i < 20; i++) s = fmaf(h0[i], sw1[i * 10 + j], s);
        h1[j] = fmaxf(s, 0.f);
    }
    float z[3];
#pragma unroll
    for (int j = 0; j < 3; j++) {
        float s = sb2[j];
#pragma unroll
        for (int i = 0; i < 10; i++) s = fmaf(h1[i], sw2[i * 3 + j], s);
        z[j] = s;
    }
    float h2[10];
#pragma unroll
    for (int j = 0; j < 10; j++) {
        float s = sb3[j];
#pragma unroll
        for (int i = 0; i < 3; i++) s = fmaf(z[i], sw3[i * 10 + j], s);
        h2[j] = fmaxf(s, 0.f);
    }
    float* op = out + (long)n * 20;
#pragma unroll
    for (int j = 0; j < 20; j++) {
        float s = sb4[j];
#pragma unroll
        for (int i = 0; i < 10; i++) s = fmaf(h2[i], sw4[i * 20 + j], s);
        op[j] = fmaxf(s, 0.f);
    }
}

// ---------------- driver ----------------
template <int ACT, bool BIAS, int OUTM>
static void gemm_h(const __half* Ah, const __half* Bth, const float* b, void* o,
                   int K, int Nc) {
    dim3 g(cdiv(Nc, HBN_T), cdiv(NN, HBM_T));
    k_gemm_h<ACT, BIAS, OUTM><<<g, 256>>>(Ah, Bth, b, o, NN, K, Nc);
}

extern "C" void kernel_launch(void* const* d_in, const int* in_sizes, int n_in,
                              void* d_out, int out_size) {
    const float* x = (const float*)d_in[0];
    const int* ei = (const int*)d_in[1];
    const int* src = ei;
    const int* dst = ei + NE;
    const float* W[12];
    const float* B[12];
    for (int i = 0; i < 12; i++) {
        W[i] = (const float*)d_in[2 + 2 * i];
        B[i] = (const float*)d_in[3 + 2 * i];
    }
    float* bufA; cudaGetSymbolAddress((void**)&bufA, g_bufA);
    float* bufB; cudaGetSymbolAddress((void**)&bufB, g_bufB);
    __half* bufH; cudaGetSymbolAddress((void**)&bufH, g_bufH);
    __half* ah; cudaGetSymbolAddress((void**)&ah, g_ah);
    __half* ah2; cudaGetSymbolAddress((void**)&ah2, g_ah2);
    __half* wth; cudaGetSymbolAddress((void**)&wth, g_wth);
    float* outp = (float*)d_out;

    const int NB = cdiv(NN, 1024);
    k_wconv_init<<<cdiv(NN, 256), 256>>>(W[1], W[2], W[9], W[10]);
    k_count<<<cdiv(NE, 256), 256>>>(dst);
    k_scan1<<<NB, 1024>>>();
    k_scan3_self<<<NB, 1024>>>();
    k_edges<<<cdiv(NE, 256), 256>>>(src, dst);

    const int TPB = 256;
    int blocks80 = cdiv(cdiv(NN, 3) * 32, TPB);   // SUB=10, 3 nodes/warp
    int blocks40 = cdiv(cdiv(NN, 6) * 32, TPB);   // SUB=5, 6 nodes/warp
    int blocks4  = cdiv(cdiv(NN, 8) * 32, TPB);   // C=3, 8 nodes/warp
    int blocksN  = cdiv(NN, TPB);

    // encoder
    k_eg1<<<blocks4, TPB>>>(x, W[0], B[0], ah);                                     // agg+eg1 -> fp16
    gemm_h<0, false, 1>(ah, wth + WOFF_EG2, nullptr, bufH, 160, 80);                // eg2 matmul
    k_aggvh<80, 10, 1, true, 1><<<blocks80, TPB>>>(bufH, B[1], nullptr, ah);        // eg2 agg -> fp16
    gemm_h<0, false, 1>(ah, wth + WOFF_EG3, nullptr, bufH, 80, 40);                 // eg3 matmul
    k_eg3mm<<<blocks40, TPB>>>(bufH, B[2], W[3], bufA);                             // eg3 agg + eg4 matmul
    k_aggv<20, 5, 1, true><<<blocks40, TPB>>>(bufA, B[3], bufB);                    // eg4 agg
    // latent dense chain
    k_chain<<<blocksN, TPB>>>(bufB, bufA, W[4], B[4], W[5], B[5], W[6], B[6], W[7], B[7]);
    // decoder
    k_dg1mm<<<blocks40, TPB>>>(bufA, W[8], B[8], bufH);                             // dg1 agg + dense -> fp16
    k_aggvh<40, 5, 0, false, 1><<<blocks40, TPB>>>(bufH, nullptr, nullptr, ah);     // dg2 agg -> fp16
    gemm_h<1, true, 1>(ah, wth + WOFF_DG2, B[9], bufH, 40, 80);                     // dg2
    k_aggvh<80, 10, 0, false, 1><<<blocks80, TPB>>>(bufH, nullptr, nullptr, ah);    // dg3 agg -> fp16
    gemm_h<1, true, 1>(ah, wth + WOFF_DG3, B[10], ah2, 80, 160);                    // dg3 -> fp16
    k_dense_h<160, 3, 0, false><<<blocksN, TPB>>>(ah2, W[11], nullptr, bufB);       // dg4 matmul
    k_agg3<2, true, float><<<blocks4, TPB>>>(bufB, B[11], outp);                    // dg4 agg+tanh
}

// round 15
// speedup vs baseline: 1.1231x; 1.0206x over previous
#include <cuda_runtime.h>
#include <cuda_fp16.h>
#include <cuda_bf16.h>
#include <cstdint>

#define NN 100000
#define NE 1600000
#define NTOT (NE + NN)

// ---------------- scratch (device globals: allocation-free) ----------------
__device__ float  g_bufA[NN * 160];
__device__ float  g_bufB[NN * 160];
__device__ __align__(16) __half g_bufH[NN * 80];
__device__ __align__(16) __half g_ah[NN * 160];    // GEMM A operand (fp16)
__device__ __align__(16) __half g_ah2[NN * 160];   // dg3 fp16 output
__device__ __align__(16) __half g_wth[32000];      // transposed weights [n*K+k] fp16
__device__ int    g_cnt[NN];        // edge counts only; zero at load & after each run
__device__ float  g_dis[NN];
__device__ int    g_rowptr[NN + 1];
__device__ int    g_fill[NN];
__device__ int2   g_entries[NTOT];
__device__ int    g_bsums[128];

static inline int cdiv(int a, int b) { return (a + b - 1) / b; }

#define WOFF_EG2 0
#define WOFF_EG3 12800
#define WOFF_DG2 16000
#define WOFF_DG3 19200

#define CP_ASYNC16(saddr, gptr) \
    asm volatile("cp.async.cg.shared.global [%0], [%1], 16;\n" :: "r"(saddr), "l"(gptr))
#define CP_COMMIT() asm volatile("cp.async.commit_group;\n" ::: "memory")
#define CP_WAIT(n)  asm volatile("cp.async.wait_group %0;\n" :: "n"(n) : "memory")

// ---------------- fused: weight convert+transpose AND edge count ----------------
__global__ void k_wconv_count(const float* __restrict__ W1, const float* __restrict__ W2,
                              const float* __restrict__ W9, const float* __restrict__ W10,
                              const int* __restrict__ dst) {
    int idx = blockIdx.x * blockDim.x + threadIdx.x;
    if (idx < 32000) {
        const float* W; int K, Nc, off, li;
        if (idx < 12800)      { W = W1;  K = 160; Nc = 80;  off = WOFF_EG2; li = idx; }
        else if (idx < 16000) { W = W2;  K = 80;  Nc = 40;  off = WOFF_EG3; li = idx - 12800; }
        else if (idx < 19200) { W = W9;  K = 40;  Nc = 80;  off = WOFF_DG2; li = idx - 16000; }
        else                  { W = W10; K = 80;  Nc = 160; off = WOFF_DG3; li = idx - 19200; }
        int k = li / Nc, n = li - k * Nc;
        g_wth[off + n * K + k] = __float2half_rn(W[li]);
    }
    if (idx < NE) atomicAdd(&g_cnt[dst[idx]], 1);
}

// ---------------- CSR build ----------------
__global__ void k_scan1() {
    __shared__ int s[1024];
    int i = blockIdx.x * 1024 + threadIdx.x;
    int v = (i < NN) ? (g_cnt[i] + 1) : 0;   // +1 = self-loop
    if (i < NN) g_dis[i] = rsqrtf((float)v);
    s[threadIdx.x] = v;
    __syncthreads();
    for (int d = 1; d < 1024; d <<= 1) {
        int t = (threadIdx.x >= d) ? s[threadIdx.x - d] : 0;
        __syncthreads();
        s[threadIdx.x] += t;
        __syncthreads();
    }
    if (i < NN) g_rowptr[i + 1] = s[threadIdx.x];
    if (threadIdx.x == 1023) g_bsums[blockIdx.x] = s[1023];
}
// scan3 fused with: own bsums-prefix reduction, self-loop placement, fill init
__global__ void k_scan3_self() {
    __shared__ int swarp[32];
    int t = threadIdx.x;
    int v = (t < blockIdx.x) ? g_bsums[t] : 0;
#pragma unroll
    for (int o = 16; o > 0; o >>= 1) v += __shfl_down_sync(0xffffffffu, v, o);
    if ((t & 31) == 0) swarp[t >> 5] = v;
    __syncthreads();
    if (t < 32) {
        int w = swarp[t];
#pragma unroll
        for (int o = 16; o > 0; o >>= 1) w += __shfl_down_sync(0xffffffffu, w, o);
        if (t == 0) swarp[0] = w;
    }
    __syncthreads();
    int offset = swarp[0];

    int i = blockIdx.x * 1024 + t;
    if (i >= NN) return;
    int rp1 = g_rowptr[i + 1] + offset;
    g_rowptr[i + 1] = rp1;
    if (i == 0) g_rowptr[0] = 0;
    int p = rp1 - (g_cnt[i] + 1);
    float d = g_dis[i];
    g_entries[p] = make_int2(i, __float_as_int(d * d));
    g_fill[i] = p + 1;
}
__global__ void k_edges(const int* __restrict__ src, const int* __restrict__ dst) {
    int e = blockIdx.x * blockDim.x + threadIdx.x;
    if (e < NE) {
        int s = src[e], d = dst[e];
        int p = atomicAdd(&g_fill[d], 1);
        g_entries[p] = make_int2(s, __float_as_int(g_dis[s] * g_dis[d]));
    }
}

// ---------------- scalar aggregation (C=3); also re-zeros g_cnt for next replay ----------------
template <int ACT, bool BIAS, typename TIN>
__global__ void k_agg3(const TIN* __restrict__ in, const float* __restrict__ bias,
                       float* __restrict__ out) {
    int gtid = blockIdx.x * blockDim.x + threadIdx.x;
    if (gtid < NN) g_cnt[gtid] = 0;   // reset for next graph replay
    int gwarp = gtid >> 5;
    int lane = threadIdx.x & 31;
    int node = gwarp * 8 + lane / 4;
    int cl = lane & 3;
    if (node >= NN) return;
    int p0 = g_rowptr[node], p1 = g_rowptr[node + 1];
    float acc = 0.f;
    bool act3 = (cl < 3);
    int p = p0;
    for (; p + 4 <= p1; p += 4) {
        int2 e0 = __ldg(&g_entries[p]);
        int2 e1 = __ldg(&g_entries[p + 1]);
        int2 e2 = __ldg(&g_entries[p + 2]);
        int2 e3 = __ldg(&g_entries[p + 3]);
        if (act3) {
            float v0 = (float)__ldg(in + (long)e0.x * 3 + cl);
            float v1 = (float)__ldg(in + (long)e1.x * 3 + cl);
            float v2 = (float)__ldg(in + (long)e2.x * 3 + cl);
            float v3 = (float)__ldg(in + (long)e3.x * 3 + cl);
            acc = fmaf(__int_as_float(e0.y), v0, acc);
            acc = fmaf(__int_as_float(e1.y), v1, acc);
            acc = fmaf(__int_as_float(e2.y), v2, acc);
            acc = fmaf(__int_as_float(e3.y), v3, acc);
        }
    }
    for (; p < p1; p++) {
        int2 e = __ldg(&g_entries[p]);
        if (act3) {
            float v = (float)__ldg(in + (long)e.x * 3 + cl);
            acc = fmaf(__int_as_float(e.y), v, acc);
        }
    }
    if (act3) {
        float v = acc;
        if (BIAS) v += bias[cl];
        if (ACT == 1) v = fmaxf(v, 0.f);
        if (ACT == 2) v = tanhf(v);
        out[(long)node * 3 + cl] = v;
    }
}

// ---------------- fp16-input aggregation helpers ----------------
__device__ __forceinline__ void accum8h(float* acc, int4 h, float w) {
    const __half2* hp = (const __half2*)&h;
#pragma unroll
    for (int i = 0; i < 4; i++) {
        float2 f = __half22float2(hp[i]);
        acc[2 * i]     = fmaf(w, f.x, acc[2 * i]);
        acc[2 * i + 1] = fmaf(w, f.y, acc[2 * i + 1]);
    }
}

template <int C, int SUB, int ACT, bool BIAS, int OM>
__global__ void k_aggvh(const __half* __restrict__ in, const float* __restrict__ bias,
                        float* __restrict__ out, __half* __restrict__ oh) {
    constexpr int NV = C / 8;
    static_assert(NV <= SUB, "SUB too small");
    constexpr int NPW = 32 / SUB;
    int gwarp = (blockIdx.x * blockDim.x + threadIdx.x) >> 5;
    int lane = threadIdx.x & 31;
    int sg = lane / SUB;
    if (sg >= NPW) return;
    int node = gwarp * NPW + sg;
    int vl = lane % SUB;
    if (node >= NN) return;
    int p0 = g_rowptr[node], p1 = g_rowptr[node + 1];
    float acc[8] = {};
    bool active = (vl < NV);
    int p = p0;
    for (; p + 4 <= p1; p += 4) {
        int2 e0 = __ldg(&g_entries[p]);
        int2 e1 = __ldg(&g_entries[p + 1]);
        int2 e2 = __ldg(&g_entries[p + 2]);
        int2 e3 = __ldg(&g_entries[p + 3]);
        if (active) {
            int4 h0 = __ldg((const int4*)(in + (long)e0.x * C) + vl);
            int4 h1 = __ldg((const int4*)(in + (long)e1.x * C) + vl);
            int4 h2 = __ldg((const int4*)(in + (long)e2.x * C) + vl);
            int4 h3 = __ldg((const int4*)(in + (long)e3.x * C) + vl);
            accum8h(acc, h0, __int_as_float(e0.y));
            accum8h(acc, h1, __int_as_float(e1.y));
            accum8h(acc, h2, __int_as_float(e2.y));
            accum8h(acc, h3, __int_as_float(e3.y));
        }
    }
    for (; p < p1; p++) {
        int2 e = __ldg(&g_entries[p]);
        if (active) {
            int4 h = __ldg((const int4*)(in + (long)e.x * C) + vl);
            accum8h(acc, h, __int_as_float(e.y));
        }
    }
    if (active) {
        if (BIAS) {
            const float4* bp = (const float4*)bias + vl * 2;
            float4 b0 = __ldg(bp), b1 = __ldg(bp + 1);
            acc[0] += b0.x; acc[1] += b0.y; acc[2] += b0.z; acc[3] += b0.w;
            acc[4] += b1.x; acc[5] += b1.y; acc[6] += b1.z; acc[7] += b1.w;
        }
        if (ACT == 1) {
#pragma unroll
            for (int i = 0; i < 8; i++) acc[i] = fmaxf(acc[i], 0.f);
        }
        if (OM == 0) {
            float4* op = (float4*)(out + (long)node * C) + vl * 2;
            op[0] = make_float4(acc[0], acc[1], acc[2], acc[3]);
            op[1] = make_float4(acc[4], acc[5], acc[6], acc[7]);
        } else {
            __half hh[8];
#pragma unroll
            for (int i = 0; i < 8; i++) hh[i] = __float2half_rn(acc[i]);
            *((int4*)(oh + (long)node * C) + vl) = *(const int4*)hh;
        }
    }
}

// ---- FUSED: eg3 agg (C=40 fp16-in, bias+relu) + eg4 matmul 40->20 (f32 out) ----
__global__ void __launch_bounds__(256)
k_eg3mm(const __half* __restrict__ in, const float* __restrict__ bias,
        const float* __restrict__ W3, float* __restrict__ out) {
    __shared__ float sW[800];
    __shared__ float sB[40];
    for (int i = threadIdx.x; i < 800; i += 256) sW[i] = W3[i];
    for (int i = threadIdx.x; i < 40; i += 256) sB[i] = bias[i];
    __syncthreads();

    constexpr int C = 40, SUB = 5, NPW = 6;
    int gwarp = (blockIdx.x * blockDim.x + threadIdx.x) >> 5;
    int lane = threadIdx.x & 31;
    int sg = lane / SUB;
    if (sg >= NPW) return;
    int node = gwarp * NPW + sg;
    int vl = lane % SUB;
    bool valid = (node < NN);
    int p0 = 0, p1 = 0;
    if (valid) { p0 = g_rowptr[node]; p1 = g_rowptr[node + 1]; }
    float acc[8] = {};
    int p = p0;
    for (; p + 4 <= p1; p += 4) {
        int2 e0 = __ldg(&g_entries[p]);
        int2 e1 = __ldg(&g_entries[p + 1]);
        int2 e2 = __ldg(&g_entries[p + 2]);
        int2 e3 = __ldg(&g_entries[p + 3]);
        int4 h0 = __ldg((const int4*)(in + (long)e0.x * C) + vl);
        int4 h1 = __ldg((const int4*)(in + (long)e1.x * C) + vl);
        int4 h2 = __ldg((const int4*)(in + (long)e2.x * C) + vl);
        int4 h3 = __ldg((const int4*)(in + (long)e3.x * C) + vl);
        accum8h(acc, h0, __int_as_float(e0.y));
        accum8h(acc, h1, __int_as_float(e1.y));
        accum8h(acc, h2, __int_as_float(e2.y));
        accum8h(acc, h3, __int_as_float(e3.y));
    }
    for (; p < p1; p++) {
        int2 e = __ldg(&g_entries[p]);
        int4 h = __ldg((const int4*)(in + (long)e.x * C) + vl);
        accum8h(acc, h, __int_as_float(e.y));
    }
#pragma unroll
    for (int i = 0; i < 8; i++) acc[i] = fmaxf(acc[i] + sB[vl * 8 + i], 0.f);

    float o[4] = {0.f, 0.f, 0.f, 0.f};
    int base = sg * SUB;
#pragma unroll
    for (int k = 0; k < 40; k++) {
        float val = __shfl_sync(0x3fffffffu, acc[k & 7], base + (k >> 3));
#pragma unroll
        for (int j = 0; j < 4; j++)
            o[j] = fmaf(val, sW[k * 20 + vl * 4 + j], o[j]);
    }
    if (valid)
        *(float4*)(out + (long)node * 20 + vl * 4) = make_float4(o[0], o[1], o[2], o[3]);
}

// ---- FUSED: eg4 agg (C=20 f32-in, bias+relu) + full latent chain (f32 out, 20/node) ----
__global__ void __launch_bounds__(256)
k_eg4chain(const float* __restrict__ in, const float* __restrict__ B3,
           const float* __restrict__ w1, const float* __restrict__ b1,
           const float* __restrict__ w2, const float* __restrict__ b2,
           const float* __restrict__ w3, const float* __restrict__ b3,
           const float* __restrict__ w4, const float* __restrict__ b4,
           float* __restrict__ out) {
    __shared__ float sB3[20];
    __shared__ float sw1[200], sb1[10], sw2[30], sb2[3], sw3[30], sb3[10], sw4[200], sb4[20];
    int tid = threadIdx.x;
    for (int i = tid; i < 20; i += 256) sB3[i] = B3[i];
    for (int i = tid; i < 200; i += 256) sw1[i] = w1[i];
    for (int i = tid; i < 10; i += 256) sb1[i] = b1[i];
    for (int i = tid; i < 30; i += 256) sw2[i] = w2[i];
    for (int i = tid; i < 3; i += 256) sb2[i] = b2[i];
    for (int i = tid; i < 30; i += 256) sw3[i] = w3[i];
    for (int i = tid; i < 10; i += 256) sb3[i] = b3[i];
    for (int i = tid; i < 200; i += 256) sw4[i] = w4[i];
    for (int i = tid; i < 20; i += 256) sb4[i] = b4[i];
    __syncthreads();

    constexpr int C = 20, SUB = 5, NPW = 6;
    const unsigned MASK = 0x3fffffffu;
    int gwarp = (blockIdx.x * blockDim.x + tid) >> 5;
    int lane = tid & 31;
    int sg = lane / SUB;
    if (sg >= NPW) return;
    int node = gwarp * NPW + sg;
    int vl = lane % SUB;
    bool valid = (node < NN);
    int p0 = 0, p1 = 0;
    if (valid) { p0 = g_rowptr[node]; p1 = g_rowptr[node + 1]; }
    float4 acc = make_float4(0.f, 0.f, 0.f, 0.f);
    int p = p0;
    for (; p + 4 <= p1; p += 4) {
        int2 e0 = __ldg(&g_entries[p]);
        int2 e1 = __ldg(&g_entries[p + 1]);
        int2 e2 = __ldg(&g_entries[p + 2]);
        int2 e3 = __ldg(&g_entries[p + 3]);
        float4 v0 = __ldg((const float4*)(in + (long)e0.x * C) + vl);
        float4 v1 = __ldg((const float4*)(in + (long)e1.x * C) + vl);
        float4 v2 = __ldg((const float4*)(in + (long)e2.x * C) + vl);
        float4 v3 = __ldg((const float4*)(in + (long)e3.x * C) + vl);
        float w0 = __int_as_float(e0.y), w1f = __int_as_float(e1.y);
        float w2f = __int_as_float(e2.y), w3f = __int_as_float(e3.y);
        acc.x = fmaf(w0, v0.x, acc.x); acc.y = fmaf(w0, v0.y, acc.y);
        acc.z = fmaf(w0, v0.z, acc.z); acc.w = fmaf(w0, v0.w, acc.w);
        acc.x = fmaf(w1f, v1.x, acc.x); acc.y = fmaf(w1f, v1.y, acc.y);
        acc.z = fmaf(w1f, v1.z, acc.z); acc.w = fmaf(w1f, v1.w, acc.w);
        acc.x = fmaf(w2f, v2.x, acc.x); acc.y = fmaf(w2f, v2.y, acc.y);
        acc.z = fmaf(w2f, v2.z, acc.z); acc.w = fmaf(w2f, v2.w, acc.w);
        acc.x = fmaf(w3f, v3.x, acc.x); acc.y = fmaf(w3f, v3.y, acc.y);
        acc.z = fmaf(w3f, v3.z, acc.z); acc.w = fmaf(w3f, v3.w, acc.w);
    }
    for (; p < p1; p++) {
        int2 e = __ldg(&g_entries[p]);
        float w = __int_as_float(e.y);
        float4 v = __ldg((const float4*)(in + (long)e.x * C) + vl);
        acc.x = fmaf(w, v.x, acc.x); acc.y = fmaf(w, v.y, acc.y);
        acc.z = fmaf(w, v.z, acc.z); acc.w = fmaf(w, v.w, acc.w);
    }
    // eg4 epilogue: bias + relu -> h0 (lane vl holds channels vl*4 .. vl*4+3)
    float h0l[4];
    h0l[0] = fmaxf(acc.x + sB3[vl * 4 + 0], 0.f);
    h0l[1] = fmaxf(acc.y + sB3[vl * 4 + 1], 0.f);
    h0l[2] = fmaxf(acc.z + sB3[vl * 4 + 2], 0.f);
    h0l[3] = fmaxf(acc.w + sB3[vl * 4 + 3], 0.f);

    int base = sg * SUB;
    // h1[10]: lane computes c = vl*2, vl*2+1
    float h1a = sb1[vl * 2 + 0], h1b = sb1[vl * 2 + 1];
#pragma unroll
    for (int k = 0; k < 20; k++) {
        float v = __shfl_sync(MASK, h0l[k & 3], base + (k >> 2));
        h1a = fmaf(v, sw1[k * 10 + vl * 2 + 0], h1a);
        h1b = fmaf(v, sw1[k * 10 + vl * 2 + 1], h1b);
    }
    h1a = fmaxf(h1a, 0.f); h1b = fmaxf(h1b, 0.f);
    // z[3]: every lane computes all three
    float z0 = sb2[0], z1 = sb2[1], z2 = sb2[2];
#pragma unroll
    for (int k = 0; k < 10; k++) {
        float v = __shfl_sync(MASK, (k & 1) ? h1b : h1a, base + (k >> 1));
        z0 = fmaf(v, sw2[k * 3 + 0], z0);
        z1 = fmaf(v, sw2[k * 3 + 1], z1);
        z2 = fmaf(v, sw2[k * 3 + 2], z2);
    }
    // h2[10]: lane computes c = vl*2, vl*2+1 (order i = 0,1,2)
    float h2a = sb3[vl * 2 + 0], h2b = sb3[vl * 2 + 1];
    h2a = fmaf(z0, sw3[0 * 10 + vl * 2 + 0], h2a);
    h2b = fmaf(z0, sw3[0 * 10 + vl * 2 + 1], h2b);
    h2a = fmaf(z1, sw3[1 * 10 + vl * 2 + 0], h2a);
    h2b = fmaf(z1, sw3[1 * 10 + vl * 2 + 1], h2b);
    h2a = fmaf(z2, sw3[2 * 10 + vl * 2 + 0], h2a);
    h2b = fmaf(z2, sw3[2 * 10 + vl * 2 + 1], h2b);
    h2a = fmaxf(h2a, 0.f); h2b = fmaxf(h2b, 0.f);
    // out[20]: lane computes cols vl*4 .. vl*4+3
    float o[4];
#pragma unroll
    for (int j = 0; j < 4; j++) o[j] = sb4[vl * 4 + j];
#pragma unroll
    for (int k = 0; k < 10; k++) {
        float v = __shfl_sync(MASK, (k & 1) ? h2b : h2a, base + (k >> 1));
#pragma unroll
        for (int j = 0; j < 4; j++)
            o[j] = fmaf(v, sw4[k * 20 + vl * 4 + j], o[j]);
    }
    if (valid) {
#pragma unroll
        for (int j = 0; j < 4; j++) o[j] = fmaxf(o[j], 0.f);
        *(float4*)(out + (long)node * 20 + vl * 4) = make_float4(o[0], o[1], o[2], o[3]);
    }
}

// ---- FUSED: dg1 agg (C=20 f32-in) + dg1 dense 20->40 (+bias, relu, fp16 out) ----
__global__ void __launch_bounds__(256)
k_dg1mm(const float* __restrict__ in, const float* __restrict__ W8,
        const float* __restrict__ B8, __half* __restrict__ out) {
    __shared__ float sW[800];
    __shared__ float sB[40];
    for (int i = threadIdx.x; i < 800; i += 256) sW[i] = W8[i];
    for (int i = threadIdx.x; i < 40; i += 256) sB[i] = B8[i];
    __syncthreads();

    constexpr int C = 20, SUB = 5, NPW = 6;
    int gwarp = (blockIdx.x * blockDim.x + threadIdx.x) >> 5;
    int lane = threadIdx.x & 31;
    int sg = lane / SUB;
    if (sg >= NPW) return;
    int node = gwarp * NPW + sg;
    int vl = lane % SUB;
    bool valid = (node < NN);
    int p0 = 0, p1 = 0;
    if (valid) { p0 = g_rowptr[node]; p1 = g_rowptr[node + 1]; }
    float4 acc = make_float4(0.f, 0.f, 0.f, 0.f);
    int p = p0;
    for (; p + 4 <= p1; p += 4) {
        int2 e0 = __ldg(&g_entries[p]);
        int2 e1 = __ldg(&g_entries[p + 1]);
        int2 e2 = __ldg(&g_entries[p + 2]);
        int2 e3 = __ldg(&g_entries[p + 3]);
        float4 v0 = __ldg((const float4*)(in + (long)e0.x * C) + vl);
        float4 v1 = __ldg((const float4*)(in + (long)e1.x * C) + vl);
        float4 v2 = __ldg((const float4*)(in + (long)e2.x * C) + vl);
        float4 v3 = __ldg((const float4*)(in + (long)e3.x * C) + vl);
        float w0 = __int_as_float(e0.y), w1 = __int_as_float(e1.y);
        float w2 = __int_as_float(e2.y), w3 = __int_as_float(e3.y);
        acc.x = fmaf(w0, v0.x, acc.x); acc.y = fmaf(w0, v0.y, acc.y);
        acc.z = fmaf(w0, v0.z, acc.z); acc.w = fmaf(w0, v0.w, acc.w);
        acc.x = fmaf(w1, v1.x, acc.x); acc.y = fmaf(w1, v1.y, acc.y);
        acc.z = fmaf(w1, v1.z, acc.z); acc.w = fmaf(w1, v1.w, acc.w);
        acc.x = fmaf(w2, v2.x, acc.x); acc.y = fmaf(w2, v2.y, acc.y);
        acc.z = fmaf(w2, v2.z, acc.z); acc.w = fmaf(w2, v2.w, acc.w);
        acc.x = fmaf(w3, v3.x, acc.x); acc.y = fmaf(w3, v3.y, acc.y);
        acc.z = fmaf(w3, v3.z, acc.z); acc.w = fmaf(w3, v3.w, acc.w);
    }
    for (; p < p1; p++) {
        int2 e = __ldg(&g_entries[p]);
        float w = __int_as_float(e.y);
        float4 v = __ldg((const float4*)(in + (long)e.x * C) + vl);
        acc.x = fmaf(w, v.x, acc.x); acc.y = fmaf(w, v.y, acc.y);
        acc.z = fmaf(w, v.z, acc.z); acc.w = fmaf(w, v.w, acc.w);
    }
    float ar[4] = {acc.x, acc.y, acc.z, acc.w};

    float o[8];
#pragma unroll
    for (int j = 0; j < 8; j++) o[j] = sB[vl * 8 + j];
    int base = sg * SUB;
#pragma unroll
    for (int k = 0; k < 20; k++) {
        float val = __shfl_sync(0x3fffffffu, ar[k & 3], base + (k >> 2));
#pragma unroll
        for (int j = 0; j < 8; j++)
            o[j] = fmaf(val, sW[k * 40 + vl * 8 + j], o[j]);
    }
    if (valid) {
        __half hh[8];
#pragma unroll
        for (int j = 0; j < 8; j++) hh[j] = __float2half_rn(fmaxf(o[j], 0.f));
        *(int4*)(out + (long)node * 40 + vl * 8) = *(const int4*)hh;
    }
}

// ---------------- fused eg1 -> fp16 for eg2 GEMM ----------------
__global__ void __launch_bounds__(256)
k_eg1(const float* __restrict__ x, const float* __restrict__ W,
      const float* __restrict__ Bb, __half* __restrict__ oh) {
    __shared__ float sW[480];
    __shared__ float sB[160];
    for (int i = threadIdx.x; i < 480; i += 256) sW[i] = W[i];
    for (int i = threadIdx.x; i < 160; i += 256) sB[i] = Bb[i];
    __syncthreads();
    int gwarp = (blockIdx.x * blockDim.x + threadIdx.x) >> 5;
    int lane = threadIdx.x & 31;
    int nodeBase = gwarp * 8;
    int node = nodeBase + lane / 4;
    int cl = lane & 3;
    float acc = 0.f;
    if (node < NN) {
        int p0 = g_rowptr[node], p1 = g_rowptr[node + 1];
        bool act3 = (cl < 3);
        int p = p0;
        for (; p + 4 <= p1; p += 4) {
            int2 e0 = __ldg(&g_entries[p]);
            int2 e1 = __ldg(&g_entries[p + 1]);
            int2 e2 = __ldg(&g_entries[p + 2]);
            int2 e3 = __ldg(&g_entries[p + 3]);
            if (act3) {
                float v0 = __ldg(x + (long)e0.x * 3 + cl);
                float v1 = __ldg(x + (long)e1.x * 3 + cl);
                float v2 = __ldg(x + (long)e2.x * 3 + cl);
                float v3 = __ldg(x + (long)e3.x * 3 + cl);
                acc = fmaf(__int_as_float(e0.y), v0, acc);
                acc = fmaf(__int_as_float(e1.y), v1, acc);
                acc = fmaf(__int_as_float(e2.y), v2, acc);
                acc = fmaf(__int_as_float(e3.y), v3, acc);
            }
        }
        for (; p < p1; p++) {
            int2 e = __ldg(&g_entries[p]);
            if (act3) {
                float v = __ldg(x + (long)e.x * 3 + cl);
                acc = fmaf(__int_as_float(e.y), v, acc);
            }
        }
    }
#pragma unroll
    for (int j = 0; j < 8; j++) {
        int n2 = nodeBase + j;
        float a0 = __shfl_sync(0xffffffffu, acc, j * 4 + 0);
        float a1 = __shfl_sync(0xffffffffu, acc, j * 4 + 1);
        float a2 = __shfl_sync(0xffffffffu, acc, j * 4 + 2);
        if (n2 >= NN) break;
#pragma unroll
        for (int c0 = 0; c0 < 160; c0 += 32) {
            int c = c0 + lane;
            float v = sB[c];
            v = fmaf(a0, sW[c], v);
            v = fmaf(a1, sW[160 + c], v);
            v = fmaf(a2, sW[320 + c], v);
            v = fmaxf(v, 0.f);
            oh[(long)n2 * 160 + c] = __float2half_rn(v);
        }
    }
}

// ---------------- thread-per-node dense (fp16 input) ----------------
template <int K, int NC, int ACT, bool BIAS>
__global__ void __launch_bounds__(256)
k_dense_h(const __half* __restrict__ in, const float* __restrict__ W,
          const float* __restrict__ bias, float* __restrict__ out) {
    __shared__ float sW[K * NC];
    __shared__ float sB[NC];
    for (int i = threadIdx.x; i < K * NC; i += 256) sW[i] = W[i];
    if (BIAS) for (int i = threadIdx.x; i < NC; i += 256) sB[i] = bias[i];
    __syncthreads();
    int n = blockIdx.x * blockDim.x + threadIdx.x;
    if (n >= NN) return;
    float acc[NC];
#pragma unroll
    for (int c = 0; c < NC; c++) acc[c] = BIAS ? sB[c] : 0.f;
    const int4* ip = (const int4*)(in + (long)n * K);
#pragma unroll
    for (int k8 = 0; k8 < K / 8; k8++) {
        int4 hv = __ldg(ip + k8);
        const __half2* hp = (const __half2*)&hv;
#pragma unroll
        for (int q = 0; q < 4; q++) {
            float2 f = __half22float2(hp[q]);
            int kk = k8 * 8 + q * 2;
#pragma unroll
            for (int c = 0; c < NC; c++) {
                acc[c] = fmaf(f.x, sW[kk * NC + c], acc[c]);
                acc[c] = fmaf(f.y, sW[(kk + 1) * NC + c], acc[c]);
            }
        }
    }
#pragma unroll
    for (int c = 0; c < NC; c++) {
        float v = acc[c];
        if (ACT == 1) v = fmaxf(v, 0.f);
        out[(long)n * NC + c] = v;
    }
}

// ---------------- pure fp16 tensor GEMM, cp.async double-buffered ----------------
__device__ __forceinline__ void mma_f16(float* c, uint32_t a0, uint32_t a1,
                                        uint32_t a2, uint32_t a3,
                                        uint32_t b0, uint32_t b1) {
    asm volatile(
        "mma.sync.aligned.m16n8k16.row.col.f32.f16.f16.f32 "
        "{%0,%1,%2,%3}, {%4,%5,%6,%7}, {%8,%9}, {%0,%1,%2,%3};\n"
        : "+f"(c[0]), "+f"(c[1]), "+f"(c[2]), "+f"(c[3])
        : "r"(a0), "r"(a1), "r"(a2), "r"(a3), "r"(b0), "r"(b1));
}

#define HBM_T 128
#define HBN_T 80
#define HBK_T 32
#define HSA 40
#define HSB 40

template <int ACT, bool BIAS, int OUTM>
__global__ void __launch_bounds__(256, 2)
k_gemm_h(const __half* __restrict__ Ah, const __half* __restrict__ Bth,
         const float* __restrict__ bias, void* __restrict__ outv,
         int M, int K, int Nc) {
    __shared__ __half sAh[2][HBM_T * HSA];
    __shared__ __half sBh[2][HBN_T * HSB];

    int tid = threadIdx.x;
    int wid = tid >> 5;
    int lane = tid & 31;
    int g = lane >> 2;
    int t = lane & 3;
    int wm = wid & 3;
    int wn = wid >> 2;
    int row0 = blockIdx.y * HBM_T;
    int col0 = blockIdx.x * HBN_T;

    float acc[2][5][4];
#pragma unroll
    for (int i = 0; i < 2; i++)
#pragma unroll
        for (int j = 0; j < 5; j++)
#pragma unroll
            for (int q = 0; q < 4; q++) acc[i][j][q] = 0.f;

    const int4 z4 = make_int4(0, 0, 0, 0);

    auto load_tile = [&](int buf, int k0) {
#pragma unroll
        for (int it = 0; it < 2; it++) {
            int idx = tid + it * 256;
            int m = idx >> 2, kq = idx & 3;
            int gm = row0 + m;
            int gk = k0 + kq * 8;
            __half* sp = &sAh[buf][m * HSA + kq * 8];
            if ((gm < M) && (gk < K)) {
                uint32_t sa = (uint32_t)__cvta_generic_to_shared(sp);
                CP_ASYNC16(sa, &Ah[(long)gm * K + gk]);
            } else {
                *(int4*)sp = z4;
            }
        }
#pragma unroll
        for (int it = 0; it < 2; it++) {
            int idx = tid + it * 256;
            if (idx < 320) {
                int n = idx >> 2, kq = idx & 3;
                int gk = k0 + kq * 8;
                __half* sp = &sBh[buf][n * HSB + kq * 8];
                if (gk < K) {
                    uint32_t sa = (uint32_t)__cvta_generic_to_shared(sp);
                    CP_ASYNC16(sa, &Bth[(long)(col0 + n) * K + gk]);
                } else {
                    *(int4*)sp = z4;
                }
            }
        }
    };

    int nk = (K + HBK_T - 1) / HBK_T;
    load_tile(0, 0);
    CP_COMMIT();

    for (int kt = 0; kt < nk; kt++) {
        int buf = kt & 1;
        if (kt + 1 < nk) {
            load_tile(buf ^ 1, (kt + 1) * HBK_T);
            CP_COMMIT();
            CP_WAIT(1);
        } else {
            CP_WAIT(0);
        }
        __syncthreads();

#pragma unroll
        for (int ks = 0; ks < HBK_T; ks += 16) {
            uint32_t ah[2][4];
#pragma unroll
            for (int i = 0; i < 2; i++) {
                int r0 = wm * 32 + i * 16 + g;
                ah[i][0] = *(const uint32_t*)&sAh[buf][r0 * HSA + ks + 2 * t];
                ah[i][1] = *(const uint32_t*)&sAh[buf][(r0 + 8) * HSA + ks + 2 * t];
                ah[i][2] = *(const uint32_t*)&sAh[buf][r0 * HSA + ks + 2 * t + 8];
                ah[i][3] = *(const uint32_t*)&sAh[buf][(r0 + 8) * HSA + ks + 2 * t + 8];
            }
#pragma unroll
            for (int j = 0; j < 5; j++) {
                int c = wn * 40 + j * 8 + g;
                uint32_t bh0 = *(const uint32_t*)&sBh[buf][c * HSB + ks + 2 * t];
                uint32_t bh1 = *(const uint32_t*)&sBh[buf][c * HSB + ks + 2 * t + 8];
#pragma unroll
                for (int i = 0; i < 2; i++)
                    mma_f16(acc[i][j], ah[i][0], ah[i][1], ah[i][2], ah[i][3], bh0, bh1);
            }
        }
        __syncthreads();
    }

#pragma unroll
    for (int i = 0; i < 2; i++) {
        int rbase = row0 + wm * 32 + i * 16 + g;
#pragma unroll
        for (int j = 0; j < 5; j++) {
            int cbase = col0 + wn * 40 + j * 8 + t * 2;
#pragma unroll
            for (int q = 0; q < 4; q++) {
                int gm = rbase + ((q >= 2) ? 8 : 0);
                int gn = cbase + (q & 1);
                if (gm < M && gn < Nc) {
                    float v = acc[i][j][q];
                    if (BIAS) v += bias[gn];
                    if (ACT == 1) v = fmaxf(v, 0.f);
                    if (OUTM == 1) ((__half*)outv)[(long)gm * Nc + gn] = __float2half_rn(v);
                    else ((float*)outv)[(long)gm * Nc + gn] = v;
                }
            }
        }
    }
}

// ---------------- driver ----------------
template <int ACT, bool BIAS, int OUTM>
static void gemm_h(const __half* Ah, const __half* Bth, const float* b, void* o,
                   int K, int Nc) {
    dim3 g(cdiv(Nc, HBN_T), cdiv(NN, HBM_T));
    k_gemm_h<ACT, BIAS, OUTM><<<g, 256>>>(Ah, Bth, b, o, NN, K, Nc);
}

extern "C" void kernel_launch(void* const* d_in, const int* in_sizes, int n_in,
                              void* d_out, int out_size) {
    const float* x = (const float*)d_in[0];
    const int* ei = (const int*)d_in[1];
    const int* src = ei;
    const int* dst = ei + NE;
    const float* W[12];
    const float* B[12];
    for (int i = 0; i < 12; i++) {
        W[i] = (const float*)d_in[2 + 2 * i];
        B[i] = (const float*)d_in[3 + 2 * i];
    }
    float* bufA; cudaGetSymbolAddress((void**)&bufA, g_bufA);
    float* bufB; cudaGetSymbolAddress((void**)&bufB, g_bufB);
    __half* bufH; cudaGetSymbolAddress((void**)&bufH, g_bufH);
    __half* ah; cudaGetSymbolAddress((void**)&ah, g_ah);
    __half* ah2; cudaGetSymbolAddress((void**)&ah2, g_ah2);
    __half* wth; cudaGetSymbolAddress((void**)&wth, g_wth);
    float* outp = (float*)d_out;

    const int NB = cdiv(NN, 1024);
    // CSR build (4 launches): wconv+count, scan1, scan3_self, edges
    k_wconv_count<<<cdiv(NE, 256), 256>>>(W[1], W[2], W[9], W[10], dst);
    k_scan1<<<NB, 1024>>>();
    k_scan3_self<<<NB, 1024>>>();
    k_edges<<<cdiv(NE, 256), 256>>>(src, dst);

    const int TPB = 256;
    int blocks80 = cdiv(cdiv(NN, 3) * 32, TPB);   // SUB=10, 3 nodes/warp
    int blocks40 = cdiv(cdiv(NN, 6) * 32, TPB);   // SUB=5, 6 nodes/warp
    int blocks4  = cdiv(cdiv(NN, 8) * 32, TPB);   // C=3, 8 nodes/warp

    // encoder
    k_eg1<<<blocks4, TPB>>>(x, W[0], B[0], ah);                                     // agg+eg1 -> fp16
    gemm_h<0, false, 1>(ah, wth + WOFF_EG2, nullptr, bufH, 160, 80);                // eg2 matmul
    k_aggvh<80, 10, 1, true, 1><<<blocks80, TPB>>>(bufH, B[1], nullptr, ah);        // eg2 agg -> fp16
    gemm_h<0, false, 1>(ah, wth + WOFF_EG3, nullptr, bufH, 80, 40);                 // eg3 matmul
    k_eg3mm<<<blocks40, TPB>>>(bufH, B[2], W[3], bufA);                             // eg3 agg + eg4 matmul
    // eg4 agg + latent chain (fused)
    k_eg4chain<<<blocks40, TPB>>>(bufA, B[3], W[4], B[4], W[5], B[5], W[6], B[6],
                                  W[7], B[7], bufB);
    // decoder
    k_dg1mm<<<blocks40, TPB>>>(bufB, W[8], B[8], bufH);                             // dg1 agg + dense -> fp16
    k_aggvh<40, 5, 0, false, 1><<<blocks40, TPB>>>(bufH, nullptr, nullptr, ah);     // dg2 agg -> fp16
    gemm_h<1, true, 1>(ah, wth + WOFF_DG2, B[9], bufH, 40, 80);                     // dg2
    k_aggvh<80, 10, 0, false, 1><<<blocks80, TPB>>>(bufH, nullptr, nullptr, ah);    // dg3 agg -> fp16
    gemm_h<1, true, 1>(ah, wth + WOFF_DG3, B[10], ah2, 80, 160);                    // dg3 -> fp16
    k_dense_h<160, 3, 0, false><<<cdiv(NN, TPB), TPB>>>(ah2, W[11], nullptr, bufB); // dg4 matmul
    k_agg3<2, true, float><<<blocks4, TPB>>>(bufB, B[11], outp);                    // dg4 agg+tanh (+cnt reset)
}

// round 16
// speedup vs baseline: 1.2220x; 1.0880x over previous
#include <cuda_runtime.h>
#include <cuda_fp16.h>
#include <cuda_bf16.h>
#include <cstdint>

#define NN 100000
#define NE 1600000
#define NTOT (NE + NN)

// ---------------- scratch (device globals: allocation-free) ----------------
__device__ float  g_bufA[NN * 160];
__device__ float  g_bufB[NN * 160];
__device__ __align__(16) __half g_bufH[NN * 80];
__device__ __align__(16) __half g_ah[NN * 160];    // GEMM A operand (fp16)
__device__ __align__(16) __half g_ah2[NN * 160];   // dg3 fp16 output
__device__ __align__(16) __half g_wth[32000];      // transposed weights [n*K+k] fp16
__device__ float  g_xs[NN * 3];     // dis-prescaled input features
__device__ int    g_cnt[NN];        // edge counts only; zero at load & after each run
__device__ float  g_dis[NN];
__device__ int    g_rowptr[NN + 1];
__device__ int    g_fill[NN];
__device__ int    g_entries[NTOT];  // src index only (norm factored out)
__device__ int    g_bsums[128];

static inline int cdiv(int a, int b) { return (a + b - 1) / b; }

#define WOFF_EG2 0
#define WOFF_EG3 12800
#define WOFF_DG2 16000
#define WOFF_DG3 19200

#define CP_ASYNC16(saddr, gptr) \
    asm volatile("cp.async.cg.shared.global [%0], [%1], 16;\n" :: "r"(saddr), "l"(gptr))
#define CP_COMMIT() asm volatile("cp.async.commit_group;\n" ::: "memory")
#define CP_WAIT(n)  asm volatile("cp.async.wait_group %0;\n" :: "n"(n) : "memory")

// ---------------- fused: weight convert+transpose AND edge count ----------------
__global__ void k_wconv_count(const float* __restrict__ W1, const float* __restrict__ W2,
                              const float* __restrict__ W9, const float* __restrict__ W10,
                              const int* __restrict__ dst) {
    int idx = blockIdx.x * blockDim.x + threadIdx.x;
    if (idx < 32000) {
        const float* W; int K, Nc, off, li;
        if (idx < 12800)      { W = W1;  K = 160; Nc = 80;  off = WOFF_EG2; li = idx; }
        else if (idx < 16000) { W = W2;  K = 80;  Nc = 40;  off = WOFF_EG3; li = idx - 12800; }
        else if (idx < 19200) { W = W9;  K = 40;  Nc = 80;  off = WOFF_DG2; li = idx - 16000; }
        else                  { W = W10; K = 80;  Nc = 160; off = WOFF_DG3; li = idx - 19200; }
        int k = li / Nc, n = li - k * Nc;
        g_wth[off + n * K + k] = __float2half_rn(W[li]);
    }
    if (idx < NE) atomicAdd(&g_cnt[dst[idx]], 1);
}

// ---------------- CSR build ----------------
__global__ void k_scan1() {
    __shared__ int s[1024];
    int i = blockIdx.x * 1024 + threadIdx.x;
    int v = (i < NN) ? (g_cnt[i] + 1) : 0;   // +1 = self-loop
    if (i < NN) g_dis[i] = rsqrtf((float)v);
    s[threadIdx.x] = v;
    __syncthreads();
    for (int d = 1; d < 1024; d <<= 1) {
        int t = (threadIdx.x >= d) ? s[threadIdx.x - d] : 0;
        __syncthreads();
        s[threadIdx.x] += t;
        __syncthreads();
    }
    if (i < NN) g_rowptr[i + 1] = s[threadIdx.x];
    if (threadIdx.x == 1023) g_bsums[blockIdx.x] = s[1023];
}
// scan3: bsums prefix, self-loop placement, fill init, x-prescale
__global__ void k_scan3_self(const float* __restrict__ x) {
    __shared__ int swarp[32];
    int t = threadIdx.x;
    int v = (t < blockIdx.x) ? g_bsums[t] : 0;
#pragma unroll
    for (int o = 16; o > 0; o >>= 1) v += __shfl_down_sync(0xffffffffu, v, o);
    if ((t & 31) == 0) swarp[t >> 5] = v;
    __syncthreads();
    if (t < 32) {
        int w = swarp[t];
#pragma unroll
        for (int o = 16; o > 0; o >>= 1) w += __shfl_down_sync(0xffffffffu, w, o);
        if (t == 0) swarp[0] = w;
    }
    __syncthreads();
    int offset = swarp[0];

    int i = blockIdx.x * 1024 + t;
    if (i >= NN) return;
    int rp1 = g_rowptr[i + 1] + offset;
    g_rowptr[i + 1] = rp1;
    if (i == 0) g_rowptr[0] = 0;
    int p = rp1 - (g_cnt[i] + 1);
    float d = g_dis[i];
    g_entries[p] = i;           // self-loop entry (src only)
    g_fill[i] = p + 1;
    g_xs[i * 3 + 0] = d * x[i * 3 + 0];
    g_xs[i * 3 + 1] = d * x[i * 3 + 1];
    g_xs[i * 3 + 2] = d * x[i * 3 + 2];
}
__global__ void k_edges(const int* __restrict__ src, const int* __restrict__ dst) {
    int e = blockIdx.x * blockDim.x + threadIdx.x;
    if (e < NE) {
        int d = dst[e];
        int p = atomicAdd(&g_fill[d], 1);
        g_entries[p] = src[e];
    }
}

// ---------------- scalar aggregation (C=3, dg4, tanh); re-zeros g_cnt ----------------
__global__ void k_agg3t(const float* __restrict__ in, const float* __restrict__ bias,
                        float* __restrict__ out) {
    int gtid = blockIdx.x * blockDim.x + threadIdx.x;
    if (gtid < NN) g_cnt[gtid] = 0;   // reset for next graph replay
    int gwarp = gtid >> 5;
    int lane = threadIdx.x & 31;
    int node = gwarp * 8 + lane / 4;
    int cl = lane & 3;
    if (node >= NN) return;
    int p0 = g_rowptr[node], p1 = g_rowptr[node + 1];
    float acc = 0.f;
    bool act3 = (cl < 3);
    int p = p0;
    for (; p + 4 <= p1; p += 4) {
        int s0 = __ldg(&g_entries[p]);
        int s1 = __ldg(&g_entries[p + 1]);
        int s2 = __ldg(&g_entries[p + 2]);
        int s3 = __ldg(&g_entries[p + 3]);
        if (act3) {
            acc += __ldg(in + (long)s0 * 3 + cl);
            acc += __ldg(in + (long)s1 * 3 + cl);
            acc += __ldg(in + (long)s2 * 3 + cl);
            acc += __ldg(in + (long)s3 * 3 + cl);
        }
    }
    for (; p < p1; p++) {
        int s = __ldg(&g_entries[p]);
        if (act3) acc += __ldg(in + (long)s * 3 + cl);
    }
    if (act3) {
        float v = tanhf(g_dis[node] * acc + bias[cl]);
        out[(long)node * 3 + cl] = v;
    }
}

// ---------------- fp16-input aggregation helpers (plain sum) ----------------
__device__ __forceinline__ void add8h(float* acc, int4 h) {
    const __half2* hp = (const __half2*)&h;
#pragma unroll
    for (int i = 0; i < 4; i++) {
        float2 f = __half22float2(hp[i]);
        acc[2 * i]     += f.x;
        acc[2 * i + 1] += f.y;
    }
}

// dis-scaled sum, optional bias+relu, fp16 out (all uses OM=1 here)
template <int C, int SUB, int ACT, bool BIAS>
__global__ void k_aggvh(const __half* __restrict__ in, const float* __restrict__ bias,
                        __half* __restrict__ oh) {
    constexpr int NV = C / 8;
    static_assert(NV <= SUB, "SUB too small");
    constexpr int NPW = 32 / SUB;
    int gwarp = (blockIdx.x * blockDim.x + threadIdx.x) >> 5;
    int lane = threadIdx.x & 31;
    int sg = lane / SUB;
    if (sg >= NPW) return;
    int node = gwarp * NPW + sg;
    int vl = lane % SUB;
    if (node >= NN) return;
    int p0 = g_rowptr[node], p1 = g_rowptr[node + 1];
    float acc[8] = {};
    bool active = (vl < NV);
    int p = p0;
    for (; p + 4 <= p1; p += 4) {
        int s0 = __ldg(&g_entries[p]);
        int s1 = __ldg(&g_entries[p + 1]);
        int s2 = __ldg(&g_entries[p + 2]);
        int s3 = __ldg(&g_entries[p + 3]);
        if (active) {
            int4 h0 = __ldg((const int4*)(in + (long)s0 * C) + vl);
            int4 h1 = __ldg((const int4*)(in + (long)s1 * C) + vl);
            int4 h2 = __ldg((const int4*)(in + (long)s2 * C) + vl);
            int4 h3 = __ldg((const int4*)(in + (long)s3 * C) + vl);
            add8h(acc, h0); add8h(acc, h1); add8h(acc, h2); add8h(acc, h3);
        }
    }
    for (; p < p1; p++) {
        int s = __ldg(&g_entries[p]);
        if (active) add8h(acc, __ldg((const int4*)(in + (long)s * C) + vl));
    }
    if (active) {
        float dn = g_dis[node];
#pragma unroll
        for (int i = 0; i < 8; i++) acc[i] *= dn;
        if (BIAS) {
            const float4* bp = (const float4*)bias + vl * 2;
            float4 b0 = __ldg(bp), b1 = __ldg(bp + 1);
            acc[0] += b0.x; acc[1] += b0.y; acc[2] += b0.z; acc[3] += b0.w;
            acc[4] += b1.x; acc[5] += b1.y; acc[6] += b1.z; acc[7] += b1.w;
        }
        if (ACT == 1) {
#pragma unroll
            for (int i = 0; i < 8; i++) acc[i] = fmaxf(acc[i], 0.f);
        }
        __half hh[8];
#pragma unroll
        for (int i = 0; i < 8; i++) hh[i] = __float2half_rn(acc[i]);
        *((int4*)(oh + (long)node * C) + vl) = *(const int4*)hh;
    }
}

// ---- FUSED: eg3 agg (C=40 fp16, dis+bias+relu) + eg4 matmul 40->20, out prescaled ----
__global__ void __launch_bounds__(256)
k_eg3mm(const __half* __restrict__ in, const float* __restrict__ bias,
        const float* __restrict__ W3, float* __restrict__ out) {
    __shared__ float sW[800];
    __shared__ float sB[40];
    for (int i = threadIdx.x; i < 800; i += 256) sW[i] = W3[i];
    for (int i = threadIdx.x; i < 40; i += 256) sB[i] = bias[i];
    __syncthreads();

    constexpr int C = 40, SUB = 5, NPW = 6;
    int gwarp = (blockIdx.x * blockDim.x + threadIdx.x) >> 5;
    int lane = threadIdx.x & 31;
    int sg = lane / SUB;
    if (sg >= NPW) return;
    int node = gwarp * NPW + sg;
    int vl = lane % SUB;
    bool valid = (node < NN);
    int p0 = 0, p1 = 0;
    if (valid) { p0 = g_rowptr[node]; p1 = g_rowptr[node + 1]; }
    float acc[8] = {};
    int p = p0;
    for (; p + 4 <= p1; p += 4) {
        int s0 = __ldg(&g_entries[p]);
        int s1 = __ldg(&g_entries[p + 1]);
        int s2 = __ldg(&g_entries[p + 2]);
        int s3 = __ldg(&g_entries[p + 3]);
        add8h(acc, __ldg((const int4*)(in + (long)s0 * C) + vl));
        add8h(acc, __ldg((const int4*)(in + (long)s1 * C) + vl));
        add8h(acc, __ldg((const int4*)(in + (long)s2 * C) + vl));
        add8h(acc, __ldg((const int4*)(in + (long)s3 * C) + vl));
    }
    for (; p < p1; p++) {
        int s = __ldg(&g_entries[p]);
        add8h(acc, __ldg((const int4*)(in + (long)s * C) + vl));
    }
    float dn = valid ? g_dis[node] : 0.f;
#pragma unroll
    for (int i = 0; i < 8; i++) acc[i] = fmaxf(dn * acc[i] + sB[vl * 8 + i], 0.f);

    float o[4] = {0.f, 0.f, 0.f, 0.f};
    int base = sg * SUB;
#pragma unroll
    for (int k = 0; k < 40; k++) {
        float val = __shfl_sync(0x3fffffffu, acc[k & 7], base + (k >> 3));
#pragma unroll
        for (int j = 0; j < 4; j++)
            o[j] = fmaf(val, sW[k * 20 + vl * 4 + j], o[j]);
    }
    if (valid) {
#pragma unroll
        for (int j = 0; j < 4; j++) o[j] *= dn;   // prescale for eg4 agg
        *(float4*)(out + (long)node * 20 + vl * 4) = make_float4(o[0], o[1], o[2], o[3]);
    }
}

// ---- FUSED: eg4 agg (dis+bias+relu) + latent chain, out prescaled for dg1 agg ----
__global__ void __launch_bounds__(256)
k_eg4chain(const float* __restrict__ in, const float* __restrict__ B3,
           const float* __restrict__ w1, const float* __restrict__ b1,
           const float* __restrict__ w2, const float* __restrict__ b2,
           const float* __restrict__ w3, const float* __restrict__ b3,
           const float* __restrict__ w4, const float* __restrict__ b4,
           float* __restrict__ out) {
    __shared__ float sB3[20];
    __shared__ float sw1[200], sb1[10], sw2[30], sb2[3], sw3[30], sb3[10], sw4[200], sb4[20];
    int tid = threadIdx.x;
    for (int i = tid; i < 20; i += 256) sB3[i] = B3[i];
    for (int i = tid; i < 200; i += 256) sw1[i] = w1[i];
    for (int i = tid; i < 10; i += 256) sb1[i] = b1[i];
    for (int i = tid; i < 30; i += 256) sw2[i] = w2[i];
    for (int i = tid; i < 3; i += 256) sb2[i] = b2[i];
    for (int i = tid; i < 30; i += 256) sw3[i] = w3[i];
    for (int i = tid; i < 10; i += 256) sb3[i] = b3[i];
    for (int i = tid; i < 200; i += 256) sw4[i] = w4[i];
    for (int i = tid; i < 20; i += 256) sb4[i] = b4[i];
    __syncthreads();

    constexpr int C = 20, SUB = 5, NPW = 6;
    const unsigned MASK = 0x3fffffffu;
    int gwarp = (blockIdx.x * blockDim.x + tid) >> 5;
    int lane = tid & 31;
    int sg = lane / SUB;
    if (sg >= NPW) return;
    int node = gwarp * NPW + sg;
    int vl = lane % SUB;
    bool valid = (node < NN);
    int p0 = 0, p1 = 0;
    if (valid) { p0 = g_rowptr[node]; p1 = g_rowptr[node + 1]; }
    float4 acc = make_float4(0.f, 0.f, 0.f, 0.f);
    int p = p0;
    for (; p + 4 <= p1; p += 4) {
        int s0 = __ldg(&g_entries[p]);
        int s1 = __ldg(&g_entries[p + 1]);
        int s2 = __ldg(&g_entries[p + 2]);
        int s3 = __ldg(&g_entries[p + 3]);
        float4 v0 = __ldg((const float4*)(in + (long)s0 * C) + vl);
        float4 v1 = __ldg((const float4*)(in + (long)s1 * C) + vl);
        float4 v2 = __ldg((const float4*)(in + (long)s2 * C) + vl);
        float4 v3 = __ldg((const float4*)(in + (long)s3 * C) + vl);
        acc.x += v0.x + v1.x + v2.x + v3.x;
        acc.y += v0.y + v1.y + v2.y + v3.y;
        acc.z += v0.z + v1.z + v2.z + v3.z;
        acc.w += v0.w + v1.w + v2.w + v3.w;
    }
    for (; p < p1; p++) {
        int s = __ldg(&g_entries[p]);
        float4 v = __ldg((const float4*)(in + (long)s * C) + vl);
        acc.x += v.x; acc.y += v.y; acc.z += v.z; acc.w += v.w;
    }
    float dn = valid ? g_dis[node] : 0.f;
    float h0l[4];
    h0l[0] = fmaxf(dn * acc.x + sB3[vl * 4 + 0], 0.f);
    h0l[1] = fmaxf(dn * acc.y + sB3[vl * 4 + 1], 0.f);
    h0l[2] = fmaxf(dn * acc.z + sB3[vl * 4 + 2], 0.f);
    h0l[3] = fmaxf(dn * acc.w + sB3[vl * 4 + 3], 0.f);

    int base = sg * SUB;
    float h1a = sb1[vl * 2 + 0], h1b = sb1[vl * 2 + 1];
#pragma unroll
    for (int k = 0; k < 20; k++) {
        float v = __shfl_sync(MASK, h0l[k & 3], base + (k >> 2));
        h1a = fmaf(v, sw1[k * 10 + vl * 2 + 0], h1a);
        h1b = fmaf(v, sw1[k * 10 + vl * 2 + 1], h1b);
    }
    h1a = fmaxf(h1a, 0.f); h1b = fmaxf(h1b, 0.f);
    float z0 = sb2[0], z1 = sb2[1], z2 = sb2[2];
#pragma unroll
    for (int k = 0; k < 10; k++) {
        float v = __shfl_sync(MASK, (k & 1) ? h1b : h1a, base + (k >> 1));
        z0 = fmaf(v, sw2[k * 3 + 0], z0);
        z1 = fmaf(v, sw2[k * 3 + 1], z1);
        z2 = fmaf(v, sw2[k * 3 + 2], z2);
    }
    float h2a = sb3[vl * 2 + 0], h2b = sb3[vl * 2 + 1];
    h2a = fmaf(z0, sw3[0 * 10 + vl * 2 + 0], h2a);
    h2b = fmaf(z0, sw3[0 * 10 + vl * 2 + 1], h2b);
    h2a = fmaf(z1, sw3[1 * 10 + vl * 2 + 0], h2a);
    h2b = fmaf(z1, sw3[1 * 10 + vl * 2 + 1], h2b);
    h2a = fmaf(z2, sw3[2 * 10 + vl * 2 + 0], h2a);
    h2b = fmaf(z2, sw3[2 * 10 + vl * 2 + 1], h2b);
    h2a = fmaxf(h2a, 0.f); h2b = fmaxf(h2b, 0.f);
    float o[4];
#pragma unroll
    for (int j = 0; j < 4; j++) o[j] = sb4[vl * 4 + j];
#pragma unroll
    for (int k = 0; k < 10; k++) {
        float v = __shfl_sync(MASK, (k & 1) ? h2b : h2a, base + (k >> 1));
#pragma unroll
        for (int j = 0; j < 4; j++)
            o[j] = fmaf(v, sw4[k * 20 + vl * 4 + j], o[j]);
    }
    if (valid) {
#pragma unroll
        for (int j = 0; j < 4; j++) o[j] = dn * fmaxf(o[j], 0.f);  // prescale for dg1 agg
        *(float4*)(out + (long)node * 20 + vl * 4) = make_float4(o[0], o[1], o[2], o[3]);
    }
}

// ---- FUSED: dg1 agg (dis) + dense 20->40 (+bias, relu), out prescaled fp16 ----
__global__ void __launch_bounds__(256)
k_dg1mm(const float* __restrict__ in, const float* __restrict__ W8,
        const float* __restrict__ B8, __half* __restrict__ out) {
    __shared__ float sW[800];
    __shared__ float sB[40];
    for (int i = threadIdx.x; i < 800; i += 256) sW[i] = W8[i];
    for (int i = threadIdx.x; i < 40; i += 256) sB[i] = B8[i];
    __syncthreads();

    constexpr int C = 20, SUB = 5, NPW = 6;
    int gwarp = (blockIdx.x * blockDim.x + threadIdx.x) >> 5;
    int lane = threadIdx.x & 31;
    int sg = lane / SUB;
    if (sg >= NPW) return;
    int node = gwarp * NPW + sg;
    int vl = lane % SUB;
    bool valid = (node < NN);
    int p0 = 0, p1 = 0;
    if (valid) { p0 = g_rowptr[node]; p1 = g_rowptr[node + 1]; }
    float4 acc = make_float4(0.f, 0.f, 0.f, 0.f);
    int p = p0;
    for (; p + 4 <= p1; p += 4) {
        int s0 = __ldg(&g_entries[p]);
        int s1 = __ldg(&g_entries[p + 1]);
        int s2 = __ldg(&g_entries[p + 2]);
        int s3 = __ldg(&g_entries[p + 3]);
        float4 v0 = __ldg((const float4*)(in + (long)s0 * C) + vl);
        float4 v1 = __ldg((const float4*)(in + (long)s1 * C) + vl);
        float4 v2 = __ldg((const float4*)(in + (long)s2 * C) + vl);
        float4 v3 = __ldg((const float4*)(in + (long)s3 * C) + vl);
        acc.x += v0.x + v1.x + v2.x + v3.x;
        acc.y += v0.y + v1.y + v2.y + v3.y;
        acc.z += v0.z + v1.z + v2.z + v3.z;
        acc.w += v0.w + v1.w + v2.w + v3.w;
    }
    for (; p < p1; p++) {
        int s = __ldg(&g_entries[p]);
        float4 v = __ldg((const float4*)(in + (long)s * C) + vl);
        acc.x += v.x; acc.y += v.y; acc.z += v.z; acc.w += v.w;
    }
    float dn = valid ? g_dis[node] : 0.f;
    float ar[4] = {dn * acc.x, dn * acc.y, dn * acc.z, dn * acc.w};

    float o[8];
#pragma unroll
    for (int j = 0; j < 8; j++) o[j] = sB[vl * 8 + j];
    int base = sg * SUB;
#pragma unroll
    for (int k = 0; k < 20; k++) {
        float val = __shfl_sync(0x3fffffffu, ar[k & 3], base + (k >> 2));
#pragma unroll
        for (int j = 0; j < 8; j++)
            o[j] = fmaf(val, sW[k * 40 + vl * 8 + j], o[j]);
    }
    if (valid) {
        __half hh[8];
#pragma unroll
        for (int j = 0; j < 8; j++) hh[j] = __float2half_rn(dn * fmaxf(o[j], 0.f));
        *(int4*)(out + (long)node * 40 + vl * 8) = *(const int4*)hh;
    }
}

// ---------------- fused eg1: agg(x̃)·dis -> relu(a@W0+b) -> fp16 ----------------
__global__ void __launch_bounds__(256)
k_eg1(const float* __restrict__ W, const float* __restrict__ Bb, __half* __restrict__ oh) {
    __shared__ float sW[480];
    __shared__ float sB[160];
    for (int i = threadIdx.x; i < 480; i += 256) sW[i] = W[i];
    for (int i = threadIdx.x; i < 160; i += 256) sB[i] = Bb[i];
    __syncthreads();
    int gwarp = (blockIdx.x * blockDim.x + threadIdx.x) >> 5;
    int lane = threadIdx.x & 31;
    int nodeBase = gwarp * 8;
    int node = nodeBase + lane / 4;
    int cl = lane & 3;
    float acc = 0.f;
    if (node < NN) {
        int p0 = g_rowptr[node], p1 = g_rowptr[node + 1];
        bool act3 = (cl < 3);
        int p = p0;
        for (; p + 4 <= p1; p += 4) {
            int s0 = __ldg(&g_entries[p]);
            int s1 = __ldg(&g_entries[p + 1]);
            int s2 = __ldg(&g_entries[p + 2]);
            int s3 = __ldg(&g_entries[p + 3]);
            if (act3) {
                acc += __ldg(g_xs + (long)s0 * 3 + cl);
                acc += __ldg(g_xs + (long)s1 * 3 + cl);
                acc += __ldg(g_xs + (long)s2 * 3 + cl);
                acc += __ldg(g_xs + (long)s3 * 3 + cl);
            }
        }
        for (; p < p1; p++) {
            int s = __ldg(&g_entries[p]);
            if (act3) acc += __ldg(g_xs + (long)s * 3 + cl);
        }
        acc *= g_dis[node];
    }
#pragma unroll
    for (int j = 0; j < 8; j++) {
        int n2 = nodeBase + j;
        float a0 = __shfl_sync(0xffffffffu, acc, j * 4 + 0);
        float a1 = __shfl_sync(0xffffffffu, acc, j * 4 + 1);
        float a2 = __shfl_sync(0xffffffffu, acc, j * 4 + 2);
        if (n2 >= NN) break;
#pragma unroll
        for (int c0 = 0; c0 < 160; c0 += 32) {
            int c = c0 + lane;
            float v = sB[c];
            v = fmaf(a0, sW[c], v);
            v = fmaf(a1, sW[160 + c], v);
            v = fmaf(a2, sW[320 + c], v);
            v = fmaxf(v, 0.f);
            oh[(long)n2 * 160 + c] = __float2half_rn(v);
        }
    }
}

// ---------------- thread-per-node dense (fp16 in), out prescaled for dg4 agg ----------------
template <int K, int NC>
__global__ void __launch_bounds__(256)
k_dense_hs(const __half* __restrict__ in, const float* __restrict__ W,
           float* __restrict__ out) {
    __shared__ float sW[K * NC];
    for (int i = threadIdx.x; i < K * NC; i += 256) sW[i] = W[i];
    __syncthreads();
    int n = blockIdx.x * blockDim.x + threadIdx.x;
    if (n >= NN) return;
    float acc[NC] = {};
    const int4* ip = (const int4*)(in + (long)n * K);
#pragma unroll
    for (int k8 = 0; k8 < K / 8; k8++) {
        int4 hv = __ldg(ip + k8);
        const __half2* hp = (const __half2*)&hv;
#pragma unroll
        for (int q = 0; q < 4; q++) {
            float2 f = __half22float2(hp[q]);
            int kk = k8 * 8 + q * 2;
#pragma unroll
            for (int c = 0; c < NC; c++) {
                acc[c] = fmaf(f.x, sW[kk * NC + c], acc[c]);
                acc[c] = fmaf(f.y, sW[(kk + 1) * NC + c], acc[c]);
            }
        }
    }
    float dn = g_dis[n];
#pragma unroll
    for (int c = 0; c < NC; c++) out[(long)n * NC + c] = dn * acc[c];
}

// ---------------- pure fp16 tensor GEMM, cp.async double-buffered ----------------
__device__ __forceinline__ void mma_f16(float* c, uint32_t a0, uint32_t a1,
                                        uint32_t a2, uint32_t a3,
                                        uint32_t b0, uint32_t b1) {
    asm volatile(
        "mma.sync.aligned.m16n8k16.row.col.f32.f16.f16.f32 "
        "{%0,%1,%2,%3}, {%4,%5,%6,%7}, {%8,%9}, {%0,%1,%2,%3};\n"
        : "+f"(c[0]), "+f"(c[1]), "+f"(c[2]), "+f"(c[3])
        : "r"(a0), "r"(a1), "r"(a2), "r"(a3), "r"(b0), "r"(b1));
}

#define HBM_T 128
#define HBN_T 80
#define HBK_T 32
#define HSA 40
#define HSB 40

template <int ACT, bool BIAS, int OUTM, bool SCALE>
__global__ void __launch_bounds__(256, 2)
k_gemm_h(const __half* __restrict__ Ah, const __half* __restrict__ Bth,
         const float* __restrict__ bias, void* __restrict__ outv,
         int M, int K, int Nc) {
    __shared__ __half sAh[2][HBM_T * HSA];
    __shared__ __half sBh[2][HBN_T * HSB];

    int tid = threadIdx.x;
    int wid = tid >> 5;
    int lane = tid & 31;
    int g = lane >> 2;
    int t = lane & 3;
    int wm = wid & 3;
    int wn = wid >> 2;
    int row0 = blockIdx.y * HBM_T;
    int col0 = blockIdx.x * HBN_T;

    float acc[2][5][4];
#pragma unroll
    for (int i = 0; i < 2; i++)
#pragma unroll
        for (int j = 0; j < 5; j++)
#pragma unroll
            for (int q = 0; q < 4; q++) acc[i][j][q] = 0.f;

    const int4 z4 = make_int4(0, 0, 0, 0);

    auto load_tile = [&](int buf, int k0) {
#pragma unroll
        for (int it = 0; it < 2; it++) {
            int idx = tid + it * 256;
            int m = idx >> 2, kq = idx & 3;
            int gm = row0 + m;
            int gk = k0 + kq * 8;
            __half* sp = &sAh[buf][m * HSA + kq * 8];
            if ((gm < M) && (gk < K)) {
                uint32_t sa = (uint32_t)__cvta_generic_to_shared(sp);
                CP_ASYNC16(sa, &Ah[(long)gm * K + gk]);
            } else {
                *(int4*)sp = z4;
            }
        }
#pragma unroll
        for (int it = 0; it < 2; it++) {
            int idx = tid + it * 256;
            if (idx < 320) {
                int n = idx >> 2, kq = idx & 3;
                int gk = k0 + kq * 8;
                __half* sp = &sBh[buf][n * HSB + kq * 8];
                if (gk < K) {
                    uint32_t sa = (uint32_t)__cvta_generic_to_shared(sp);
                    CP_ASYNC16(sa, &Bth[(long)(col0 + n) * K + gk]);
                } else {
                    *(int4*)sp = z4;
                }
            }
        }
    };

    int nk = (K + HBK_T - 1) / HBK_T;
    load_tile(0, 0);
    CP_COMMIT();

    for (int kt = 0; kt < nk; kt++) {
        int buf = kt & 1;
        if (kt + 1 < nk) {
            load_tile(buf ^ 1, (kt + 1) * HBK_T);
            CP_COMMIT();
            CP_WAIT(1);
        } else {
            CP_WAIT(0);
        }
        __syncthreads();

#pragma unroll
        for (int ks = 0; ks < HBK_T; ks += 16) {
            uint32_t ah[2][4];
#pragma unroll
            for (int i = 0; i < 2; i++) {
                int r0 = wm * 32 + i * 16 + g;
                ah[i][0] = *(const uint32_t*)&sAh[buf][r0 * HSA + ks + 2 * t];
                ah[i][1] = *(const uint32_t*)&sAh[buf][(r0 + 8) * HSA + ks + 2 * t];
                ah[i][2] = *(const uint32_t*)&sAh[buf][r0 * HSA + ks + 2 * t + 8];
                ah[i][3] = *(const uint32_t*)&sAh[buf][(r0 + 8) * HSA + ks + 2 * t + 8];
            }
#pragma unroll
            for (int j = 0; j < 5; j++) {
                int c = wn * 40 + j * 8 + g;
                uint32_t bh0 = *(const uint32_t*)&sBh[buf][c * HSB + ks + 2 * t];
                uint32_t bh1 = *(const uint32_t*)&sBh[buf][c * HSB + ks + 2 * t + 8];
#pragma unroll
                for (int i = 0; i < 2; i++)
                    mma_f16(acc[i][j], ah[i][0], ah[i][1], ah[i][2], ah[i][3], bh0, bh1);
            }
        }
        __syncthreads();
    }

#pragma unroll
    for (int i = 0; i < 2; i++) {
        int rbase = row0 + wm * 32 + i * 16 + g;
#pragma unroll
        for (int j = 0; j < 5; j++) {
            int cbase = col0 + wn * 40 + j * 8 + t * 2;
#pragma unroll
            for (int q = 0; q < 4; q++) {
                int gm = rbase + ((q >= 2) ? 8 : 0);
                int gn = cbase + (q & 1);
                if (gm < M && gn < Nc) {
                    float v = acc[i][j][q];
                    if (BIAS) v += bias[gn];
                    if (ACT == 1) v = fmaxf(v, 0.f);
                    if (SCALE) v *= __ldg(&g_dis[gm]);
                    if (OUTM == 1) ((__half*)outv)[(long)gm * Nc + gn] = __float2half_rn(v);
                    else ((float*)outv)[(long)gm * Nc + gn] = v;
                }
            }
        }
    }
}

// ---------------- driver ----------------
template <int ACT, bool BIAS, int OUTM, bool SCALE>
static void gemm_h(const __half* Ah, const __half* Bth, const float* b, void* o,
                   int K, int Nc) {
    dim3 g(cdiv(Nc, HBN_T), cdiv(NN, HBM_T));
    k_gemm_h<ACT, BIAS, OUTM, SCALE><<<g, 256>>>(Ah, Bth, b, o, NN, K, Nc);
}

extern "C" void kernel_launch(void* const* d_in, const int* in_sizes, int n_in,
                              void* d_out, int out_size) {
    const float* x = (const float*)d_in[0];
    const int* ei = (const int*)d_in[1];
    const int* src = ei;
    const int* dst = ei + NE;
    const float* W[12];
    const float* B[12];
    for (int i = 0; i < 12; i++) {
        W[i] = (const float*)d_in[2 + 2 * i];
        B[i] = (const float*)d_in[3 + 2 * i];
    }
    float* bufA; cudaGetSymbolAddress((void**)&bufA, g_bufA);
    float* bufB; cudaGetSymbolAddress((void**)&bufB, g_bufB);
    __half* bufH; cudaGetSymbolAddress((void**)&bufH, g_bufH);
    __half* ah; cudaGetSymbolAddress((void**)&ah, g_ah);
    __half* ah2; cudaGetSymbolAddress((void**)&ah2, g_ah2);
    __half* wth; cudaGetSymbolAddress((void**)&wth, g_wth);
    float* outp = (float*)d_out;

    const int NB = cdiv(NN, 1024);
    // CSR build (4 launches)
    k_wconv_count<<<cdiv(NE, 256), 256>>>(W[1], W[2], W[9], W[10], dst);
    k_scan1<<<NB, 1024>>>();
    k_scan3_self<<<NB, 1024>>>(x);
    k_edges<<<cdiv(NE, 256), 256>>>(src, dst);

    const int TPB = 256;
    int blocks80 = cdiv(cdiv(NN, 3) * 32, TPB);   // SUB=10, 3 nodes/warp
    int blocks40 = cdiv(cdiv(NN, 6) * 32, TPB);   // SUB=5, 6 nodes/warp
    int blocks4  = cdiv(cdiv(NN, 8) * 32, TPB);   // C=3, 8 nodes/warp

    // encoder
    k_eg1<<<blocks4, TPB>>>(W[0], B[0], ah);                                        // agg(x̃)+eg1 -> fp16
    gemm_h<0, false, 1, true>(ah, wth + WOFF_EG2, nullptr, bufH, 160, 80);          // eg2 mm (prescaled out)
    k_aggvh<80, 10, 1, true><<<blocks80, TPB>>>(bufH, B[1], ah);                    // eg2 agg -> fp16
    gemm_h<0, false, 1, true>(ah, wth + WOFF_EG3, nullptr, bufH, 80, 40);           // eg3 mm (prescaled out)
    k_eg3mm<<<blocks40, TPB>>>(bufH, B[2], W[3], bufA);                             // eg3 agg + eg4 mm (prescaled)
    k_eg4chain<<<blocks40, TPB>>>(bufA, B[3], W[4], B[4], W[5], B[5], W[6], B[6],
                                  W[7], B[7], bufB);                                // eg4 agg + chain (prescaled)
    // decoder
    k_dg1mm<<<blocks40, TPB>>>(bufB, W[8], B[8], bufH);                             // dg1 agg+dense (prescaled fp16)
    k_aggvh<40, 5, 0, false><<<blocks40, TPB>>>(bufH, nullptr, ah);                 // dg2 agg -> fp16
    gemm_h<1, true, 1, true>(ah, wth + WOFF_DG2, B[9], bufH, 40, 80);               // dg2 (prescaled out)
    k_aggvh<80, 10, 0, false><<<blocks80, TPB>>>(bufH, nullptr, ah);                // dg3 agg -> fp16
    gemm_h<1, true, 1, false>(ah, wth + WOFF_DG3, B[10], ah2, 80, 160);             // dg3 -> fp16 (unscaled)
    k_dense_hs<160, 3><<<cdiv(NN, TPB), TPB>>>(ah2, W[11], bufB);                   // dg4 mm (prescaled out)
    k_agg3t<<<blocks4, TPB>>>(bufB, B[11], outp);                                   // dg4 agg+tanh (+cnt reset)
}